// round 7
// baseline (speedup 1.0000x reference)
#include <cuda_runtime.h>
#include <cstdint>

#define Bq 1024
#define Lq 100
#define NBLK 128
#define NTHR 512

typedef unsigned long long u64;

// ---------------- static scratch ----------------
__device__ float g_Wp0t[768 * 1024];     // [k][n] gate-interleaved n
__device__ float g_Wp1t[512 * 1024];
__device__ float g_b0p[1024], g_b1p[1024];
__device__ float g_Wcc[512 * 256];       // [k][n] for concat
__device__ float g_Wsk[256 * 512];       // [k][n] stacked: n<256 Wout, n>=256 Wco
__device__ float g_h0a[Bq * 256], g_h0b[Bq * 256];
__device__ float g_h1a[Bq * 256], g_h1b[Bq * 256];
__device__ float g_c0[Bq * 256], g_c1[Bq * 256];
__device__ float g_ctx[Bq * 256];
__device__ unsigned g_count;

// ---------------- f32x2 helpers ----------------
__device__ __forceinline__ u64 pk2(float lo, float hi) {
    u64 r; asm("mov.b64 %0, {%1, %2};" : "=l"(r) : "f"(lo), "f"(hi)); return r;
}
__device__ __forceinline__ float2 up2(u64 v) {
    float2 r; asm("mov.b64 {%0, %1}, %2;" : "=f"(r.x), "=f"(r.y) : "l"(v)); return r;
}
__device__ __forceinline__ void fma2(u64& d, u64 a, u64 b) {
    asm("fma.rn.f32x2 %0, %1, %2, %0;" : "+l"(d) : "l"(a), "l"(b));
}
__device__ __forceinline__ float sigm(float x) { return 1.f / (1.f + __expf(-x)); }

// ---------------- grid barrier ----------------
__device__ __forceinline__ void gsync(unsigned target) {
    __syncthreads();
    if (threadIdx.x == 0) {
        unsigned o;
        asm volatile("atom.add.release.gpu.u32 %0, [%1], 1;"
                     : "=r"(o) : "l"(&g_count) : "memory");
        unsigned cur;
        do {
            asm volatile("ld.acquire.gpu.u32 %0, [%1];"
                         : "=r"(cur) : "l"(&g_count) : "memory");
        } while ((int)(cur - target) < 0);
    }
    __syncthreads();
}

// ---------------- shared pool ----------------
struct SPool {
    union {
        struct { float A[2][32][68]; float W[2][32][144]; } l;
        struct {
            u64 h1p[256][4];          // h1 row-pairs [k][pair]
            u64 cap[256][4];          // ctx_att pairs
            u64 cxp[256][4];          // new ctx pairs
            float qs[8][256];
            float ca8[8][256];
            float lq8[8][512];        // [logit|Q]
            float accp[8][256];       // attention partial
            float m1[8], e1[8];
        } p3;
    };
};

// =============== LSTM GEMM: tile 64x128, all 16 warps compute ================
// W global layout [Kt][1024] gate-interleaved cols. Smem W col-permuted:
// col n -> (n&7)<4 ? (n>>3)*4+(n&3) : 80+(n>>3)*4+(n&3)  (conflict-free LDS.128)
__device__ void lstm_gemm(SPool* sp, const int* gidx, int bm, int bn,
                          const float* A0, const float* A1, const float* A2, int Kt,
                          bool gather, const float* __restrict__ Wt,
                          const float* __restrict__ bias,
                          float* __restrict__ cst, float* __restrict__ hout) {
    const int tid = threadIdx.x;
    const int rg = tid >> 4, cg = tid & 15;
    const int rowA = tid & 63, kqA = (tid >> 6) << 2;   // A loader: 64 rows x 8 kq
    const int kkW = tid >> 4, c0W = (tid & 15) << 3;    // W loader: 32 kk x 16 col8

    u64 acc[2][4];
#pragma unroll
    for (int r = 0; r < 2; r++)
#pragma unroll
        for (int j = 0; j < 4; j++) acc[r][j] = 0ull;

    float4 pa, pw0, pw1;
    {   // prefetch chunk 0
        int seg = kqA >> 8, kc = kqA & 255;
        const float* Ab = (seg == 0) ? A0 : (seg == 1 ? A1 : A2);
        const float* p = (gather && seg == 0) ? (Ab + (size_t)gidx[rowA] * 256 + kc)
                                              : (Ab + (size_t)(bm + rowA) * 256 + kc);
        pa = *(const float4*)p;
        const float* wp = Wt + (size_t)kkW * 1024 + bn + c0W;
        pw0 = *(const float4*)wp; pw1 = *(const float4*)(wp + 4);
    }
    // store chunk 0 -> buf 0
    {
        sp->l.A[0][kqA + 0][rowA] = pa.x; sp->l.A[0][kqA + 1][rowA] = pa.y;
        sp->l.A[0][kqA + 2][rowA] = pa.z; sp->l.A[0][kqA + 3][rowA] = pa.w;
        float v[8] = {pw0.x, pw0.y, pw0.z, pw0.w, pw1.x, pw1.y, pw1.z, pw1.w};
#pragma unroll
        for (int i = 0; i < 8; i++) {
            int col = c0W + i, sub = col & 7, grp = col >> 3;
            int colp = (sub < 4) ? (grp * 4 + sub) : (80 + grp * 4 + sub - 4);
            sp->l.W[0][kkW][colp] = v[i];
        }
    }
    const int nc = Kt >> 5;
    for (int c = 0; c < nc; c++) {
        const int buf = c & 1;
        __syncthreads();
        const bool more = (c + 1) < nc;
        if (more) {
            const int kb = (c + 1) << 5;
            int k = kb + kqA, seg = k >> 8, kc = k & 255;
            const float* Ab = (seg == 0) ? A0 : (seg == 1 ? A1 : A2);
            const float* p = (gather && seg == 0) ? (Ab + (size_t)gidx[rowA] * 256 + kc)
                                                  : (Ab + (size_t)(bm + rowA) * 256 + kc);
            pa = *(const float4*)p;
            const float* wp = Wt + (size_t)(kb + kkW) * 1024 + bn + c0W;
            pw0 = *(const float4*)wp; pw1 = *(const float4*)(wp + 4);
        }
#pragma unroll
        for (int kk = 0; kk < 32; kk++) {
            float2 av = *(const float2*)&sp->l.A[buf][kk][rg * 2];
            u64 a0 = pk2(av.x, av.x), a1 = pk2(av.y, av.y);
            ulonglong2 w0 = *(const ulonglong2*)&sp->l.W[buf][kk][cg * 4];
            ulonglong2 w1 = *(const ulonglong2*)&sp->l.W[buf][kk][80 + cg * 4];
            fma2(acc[0][0], a0, w0.x); fma2(acc[0][1], a0, w0.y);
            fma2(acc[0][2], a0, w1.x); fma2(acc[0][3], a0, w1.y);
            fma2(acc[1][0], a1, w0.x); fma2(acc[1][1], a1, w0.y);
            fma2(acc[1][2], a1, w1.x); fma2(acc[1][3], a1, w1.y);
        }
        if (more) {
            const int nb = buf ^ 1;
            sp->l.A[nb][kqA + 0][rowA] = pa.x; sp->l.A[nb][kqA + 1][rowA] = pa.y;
            sp->l.A[nb][kqA + 2][rowA] = pa.z; sp->l.A[nb][kqA + 3][rowA] = pa.w;
            float v[8] = {pw0.x, pw0.y, pw0.z, pw0.w, pw1.x, pw1.y, pw1.z, pw1.w};
#pragma unroll
            for (int i = 0; i < 8; i++) {
                int col = c0W + i, sub = col & 7, grp = col >> 3;
                int colp = (sub < 4) ? (grp * 4 + sub) : (80 + grp * 4 + sub - 4);
                sp->l.W[nb][kkW][colp] = v[i];
            }
        }
    }
    // epilogue: cols 8cg..8cg+7 = gates (i,f,g,o) of hiddens 2cg, 2cg+1
    const int nb0 = bn + cg * 8;
    const float bi0 = bias[nb0 + 0], bf0 = bias[nb0 + 1];
    const float bg0 = bias[nb0 + 2], bo0 = bias[nb0 + 3];
    const float bi1 = bias[nb0 + 4], bf1 = bias[nb0 + 5];
    const float bg1 = bias[nb0 + 6], bo1 = bias[nb0 + 7];
    const int hb = (bn >> 2) + cg * 2;
#pragma unroll
    for (int r = 0; r < 2; r++) {
        const int row = bm + rg * 2 + r;
        {
            float2 gif = up2(acc[r][0]);
            float2 ggo = up2(acc[r][1]);
            float I = sigm(gif.x + bi0), F = sigm(gif.y + bf0);
            float G = tanhf(ggo.x + bg0), Og = sigm(ggo.y + bo0);
            int idx = row * 256 + hb;
            float cn = F * cst[idx] + I * G;
            cst[idx] = cn; hout[idx] = Og * tanhf(cn);
        }
        {
            float2 gif = up2(acc[r][2]);
            float2 ggo = up2(acc[r][3]);
            float I = sigm(gif.x + bi1), F = sigm(gif.y + bf1);
            float G = tanhf(ggo.x + bg1), Og = sigm(ggo.y + bo1);
            int idx = row * 256 + hb + 1;
            float cn = F * cst[idx] + I * G;
            cst[idx] = cn; hout[idx] = Og * tanhf(cn);
        }
    }
}

// =============== fused tail phase: block owns rows r0..r0+7 ==================
__device__ void fused_tail(SPool* sp, int bid, int t,
                           const float* __restrict__ h1n,
                           const float* __restrict__ eo,
                           const float* __restrict__ Wa,
                           const float* __restrict__ bcrit,
                           const int* __restrict__ actions,
                           float* __restrict__ out) {
    const int tid = threadIdx.x;
    const int r0 = bid * 8;
    const int col = tid & 255, pp = (tid >> 8) * 2;   // pairs pp, pp+1

    // ---- build h1 pairs [k][pair] ----
    {
        int k = col;
        float a = h1n[(r0 + 2 * pp + 0) * 256 + k];
        float b = h1n[(r0 + 2 * pp + 1) * 256 + k];
        float c = h1n[(r0 + 2 * pp + 2) * 256 + k];
        float d = h1n[(r0 + 2 * pp + 3) * 256 + k];
        sp->p3.h1p[k][pp] = pk2(a, b);
        sp->p3.h1p[k][pp + 1] = pk2(c, d);
    }
    __syncthreads();

    // ---- q = h1 @ Wa  (Wa already [k][n]) ----
    {
        u64 a0 = 0ull, a1 = 0ull;
#pragma unroll 4
        for (int k = 0; k < 256; k++) {
            float w = Wa[k * 256 + col];
            u64 wd = pk2(w, w);
            ulonglong2 hp = *(const ulonglong2*)&sp->p3.h1p[k][pp];
            fma2(a0, hp.x, wd); fma2(a1, hp.y, wd);
        }
        float2 v0 = up2(a0), v1 = up2(a1);
        sp->p3.qs[2 * pp + 0][col] = v0.x; sp->p3.qs[2 * pp + 1][col] = v0.y;
        sp->p3.qs[2 * pp + 2][col] = v1.x; sp->p3.qs[2 * pp + 3][col] = v1.y;
    }
    __syncthreads();

    // ---- attention: 2 warps per row, online softmax ----
    {
        const int w = tid >> 5, lane = tid & 31;
        const int r8 = w >> 1, half = w & 1, b = r0 + r8;
        float4 q0 = *(const float4*)&sp->p3.qs[r8][lane * 4];
        float4 q1 = *(const float4*)&sp->p3.qs[r8][128 + lane * 4];
        const float* eb = eo + (size_t)b * Lq * 256;
        float m = -1e30f, esum = 0.f;
        float4 a0 = make_float4(0, 0, 0, 0), a1 = make_float4(0, 0, 0, 0);
        const int l0 = half * 50;
#pragma unroll 2
        for (int l = l0; l < l0 + 50; l++) {
            const float* p = eb + (size_t)l * 256;
            float4 v0 = *(const float4*)(p + lane * 4);
            float4 v1 = *(const float4*)(p + 128 + lane * 4);
            float s = v0.x * q0.x + v0.y * q0.y + v0.z * q0.z + v0.w * q0.w
                    + v1.x * q1.x + v1.y * q1.y + v1.z * q1.z + v1.w * q1.w;
#pragma unroll
            for (int o = 16; o; o >>= 1) s += __shfl_xor_sync(0xFFFFFFFFu, s, o);
            if (s <= m) {
                float wg = __expf(s - m);
                esum += wg;
                a0.x += wg * v0.x; a0.y += wg * v0.y; a0.z += wg * v0.z; a0.w += wg * v0.w;
                a1.x += wg * v1.x; a1.y += wg * v1.y; a1.z += wg * v1.z; a1.w += wg * v1.w;
            } else {
                float r = __expf(m - s);
                esum = esum * r + 1.f;
                a0.x = a0.x * r + v0.x; a0.y = a0.y * r + v0.y;
                a0.z = a0.z * r + v0.z; a0.w = a0.w * r + v0.w;
                a1.x = a1.x * r + v1.x; a1.y = a1.y * r + v1.y;
                a1.z = a1.z * r + v1.z; a1.w = a1.w * r + v1.w;
                m = s;
            }
        }
        if (half) {
            sp->p3.m1[r8] = m; sp->p3.e1[r8] = esum;
            *(float4*)&sp->p3.accp[r8][lane * 4] = a0;
            *(float4*)&sp->p3.accp[r8][128 + lane * 4] = a1;
        }
        __syncthreads();
        if (!half) {
            float m1 = sp->p3.m1[r8], e1 = sp->p3.e1[r8];
            float M = fmaxf(m, m1);
            float s0 = __expf(m - M), s1 = __expf(m1 - M);
            float inv = 1.f / (esum * s0 + e1 * s1);
            float4 p0 = *(const float4*)&sp->p3.accp[r8][lane * 4];
            float4 p1 = *(const float4*)&sp->p3.accp[r8][128 + lane * 4];
            float4 o0, o1;
            o0.x = (a0.x * s0 + p0.x * s1) * inv; o0.y = (a0.y * s0 + p0.y * s1) * inv;
            o0.z = (a0.z * s0 + p0.z * s1) * inv; o0.w = (a0.w * s0 + p0.w * s1) * inv;
            o1.x = (a1.x * s0 + p1.x * s1) * inv; o1.y = (a1.y * s0 + p1.y * s1) * inv;
            o1.z = (a1.z * s0 + p1.z * s1) * inv; o1.w = (a1.w * s0 + p1.w * s1) * inv;
            *(float4*)&sp->p3.ca8[r8][lane * 4] = o0;
            *(float4*)&sp->p3.ca8[r8][128 + lane * 4] = o1;
        }
    }
    __syncthreads();

    // ---- pack ctx_att pairs ----
    {
        int k = col;
        sp->p3.cap[k][pp] = pk2(sp->p3.ca8[2 * pp + 0][k], sp->p3.ca8[2 * pp + 1][k]);
        sp->p3.cap[k][pp + 1] = pk2(sp->p3.ca8[2 * pp + 2][k], sp->p3.ca8[2 * pp + 3][k]);
    }
    __syncthreads();

    // ---- ctx = tanh([h1 | ctx_att] @ Wconcat^T), K=512 ----
    {
        u64 a0 = 0ull, a1 = 0ull;
#pragma unroll 4
        for (int k = 0; k < 256; k++) {
            float w = g_Wcc[k * 256 + col];
            u64 wd = pk2(w, w);
            ulonglong2 hp = *(const ulonglong2*)&sp->p3.h1p[k][pp];
            fma2(a0, hp.x, wd); fma2(a1, hp.y, wd);
        }
#pragma unroll 4
        for (int k = 0; k < 256; k++) {
            float w = g_Wcc[(256 + k) * 256 + col];
            u64 wd = pk2(w, w);
            ulonglong2 hp = *(const ulonglong2*)&sp->p3.cap[k][pp];
            fma2(a0, hp.x, wd); fma2(a1, hp.y, wd);
        }
        float2 v0 = up2(a0), v1 = up2(a1);
        float t0 = tanhf(v0.x), t1 = tanhf(v0.y);
        float t2 = tanhf(v1.x), t3 = tanhf(v1.y);
        g_ctx[(r0 + 2 * pp + 0) * 256 + col] = t0;
        g_ctx[(r0 + 2 * pp + 1) * 256 + col] = t1;
        g_ctx[(r0 + 2 * pp + 2) * 256 + col] = t2;
        g_ctx[(r0 + 2 * pp + 3) * 256 + col] = t3;
        sp->p3.cxp[col][pp] = pk2(t0, t1);
        sp->p3.cxp[col][pp + 1] = pk2(t2, t3);
    }
    __syncthreads();

    // ---- stacked [logit|Q] = ctx @ Wsk, col = tid (0..511) ----
    {
        u64 b0 = 0ull, b1 = 0ull, b2 = 0ull, b3 = 0ull;
#pragma unroll 4
        for (int k = 0; k < 256; k++) {
            float w = g_Wsk[k * 512 + tid];
            u64 wd = pk2(w, w);
            ulonglong2 c01 = *(const ulonglong2*)&sp->p3.cxp[k][0];
            ulonglong2 c23 = *(const ulonglong2*)&sp->p3.cxp[k][2];
            fma2(b0, c01.x, wd); fma2(b1, c01.y, wd);
            fma2(b2, c23.x, wd); fma2(b3, c23.y, wd);
        }
        float bias = (tid >= 256) ? bcrit[tid - 256] : 0.f;
        float2 v0 = up2(b0), v1 = up2(b1), v2 = up2(b2), v3 = up2(b3);
        sp->p3.lq8[0][tid] = v0.x + bias; sp->p3.lq8[1][tid] = v0.y + bias;
        sp->p3.lq8[2][tid] = v1.x + bias; sp->p3.lq8[3][tid] = v1.y + bias;
        sp->p3.lq8[4][tid] = v2.x + bias; sp->p3.lq8[5][tid] = v2.y + bias;
        sp->p3.lq8[6][tid] = v3.x + bias; sp->p3.lq8[7][tid] = v3.y + bias;
    }
    __syncthreads();

    // ---- finalize: warp-per-row ----
    {
        const int w = tid >> 5, lane = tid & 31;
        if (w < 8) {
            const int b = r0 + w;
            float4 l0 = *(const float4*)&sp->p3.lq8[w][lane * 4];
            float4 l1 = *(const float4*)&sp->p3.lq8[w][128 + lane * 4];
            float m = fmaxf(fmaxf(fmaxf(l0.x, l0.y), fmaxf(l0.z, l0.w)),
                            fmaxf(fmaxf(l1.x, l1.y), fmaxf(l1.z, l1.w)));
#pragma unroll
            for (int o = 16; o; o >>= 1) m = fmaxf(m, __shfl_xor_sync(0xFFFFFFFFu, m, o));
            float4 e0 = make_float4(__expf(l0.x - m), __expf(l0.y - m),
                                    __expf(l0.z - m), __expf(l0.w - m));
            float4 e1 = make_float4(__expf(l1.x - m), __expf(l1.y - m),
                                    __expf(l1.z - m), __expf(l1.w - m));
            float s = e0.x + e0.y + e0.z + e0.w + e1.x + e1.y + e1.z + e1.w;
#pragma unroll
            for (int o = 16; o; o >>= 1) s += __shfl_xor_sync(0xFFFFFFFFu, s, o);
            float inv = 1.f / s;
            e0.x *= inv; e0.y *= inv; e0.z *= inv; e0.w *= inv;
            e1.x *= inv; e1.y *= inv; e1.z *= inv; e1.w *= inv;
            float* outl = out + (size_t)Bq * Lq + ((size_t)b * Lq + t) * 256;
            *(float4*)(outl + lane * 4) = e0;
            *(float4*)(outl + 128 + lane * 4) = e1;
            float4 Q0 = *(const float4*)&sp->p3.lq8[w][256 + lane * 4];
            float4 Q1 = *(const float4*)&sp->p3.lq8[w][384 + lane * 4];
            float v = e0.x * Q0.x + e0.y * Q0.y + e0.z * Q0.z + e0.w * Q0.w
                    + e1.x * Q1.x + e1.y * Q1.y + e1.z * Q1.z + e1.w * Q1.w;
#pragma unroll
            for (int o = 16; o; o >>= 1) v += __shfl_xor_sync(0xFFFFFFFFu, v, o);
            if (!lane) {
                out[(size_t)Bq * Lq + (size_t)Bq * Lq * 256 + b * Lq + t] = v;
                out[b * Lq + t] = (float)actions[b * Lq + t];
            }
        }
    }
}

// =============== persistent mega-kernel ======================================
__global__ void __launch_bounds__(NTHR, 1)
mega(const float* __restrict__ enc_out, const float* __restrict__ enc_h,
     const float* __restrict__ enc_c, const float* __restrict__ emb,
     const float* __restrict__ Wih0, const float* __restrict__ Whh0,
     const float* __restrict__ bih0, const float* __restrict__ bhh0,
     const float* __restrict__ Wih1, const float* __restrict__ Whh1,
     const float* __restrict__ bih1, const float* __restrict__ bhh1,
     const float* __restrict__ Wa, const float* __restrict__ Wconcat,
     const float* __restrict__ Wout, const float* __restrict__ Wcrit,
     const float* __restrict__ bcrit, const int* __restrict__ actions,
     float* __restrict__ out) {
    extern __shared__ float dynsm[];
    SPool* sp = (SPool*)dynsm;
    __shared__ int gidx[64];
    const int bid = blockIdx.x, tid = threadIdx.x;
    unsigned bt = 0;

    // ---- init ----
    for (int idx = bid * NTHR + tid; idx < 768 * 1024; idx += NBLK * NTHR) {
        int k = idx >> 10, n = idx & 1023;
        int h = n >> 2, g = n & 3, orow = g * 256 + h;
        g_Wp0t[idx] = (k < 512) ? Wih0[orow * 512 + k] : Whh0[orow * 256 + (k - 512)];
    }
    for (int idx = bid * NTHR + tid; idx < 512 * 1024; idx += NBLK * NTHR) {
        int k = idx >> 10, n = idx & 1023;
        int h = n >> 2, g = n & 3, orow = g * 256 + h;
        g_Wp1t[idx] = (k < 256) ? Wih1[orow * 256 + k] : Whh1[orow * 256 + (k - 256)];
    }
    for (int idx = bid * NTHR + tid; idx < 512 * 256; idx += NBLK * NTHR) {
        int k = idx >> 8, n = idx & 255;
        g_Wcc[idx] = Wconcat[n * 512 + k];
    }
    for (int idx = bid * NTHR + tid; idx < 65536; idx += NBLK * NTHR) {
        int k = idx >> 8, n = idx & 255;
        g_Wsk[k * 512 + n] = Wout[n * 256 + k];
    }
    {   // Wco = Wcrit @ Wout -> g_Wsk[j*512 + 256 + i] = Wco[i][j]
        int g = bid * NTHR + tid;          // exactly 65536 threads
        int i = g >> 8, j = g & 255;
        float acc = 0.f;
        const float* wc = Wcrit + i * 256;
#pragma unroll 4
        for (int k = 0; k < 256; k++) acc += wc[k] * Wout[k * 256 + j];
        g_Wsk[j * 512 + 256 + i] = acc;
    }
    for (int idx = bid * NTHR + tid; idx < 1024; idx += NBLK * NTHR) {
        int h = idx >> 2, g = idx & 3, orow = g * 256 + h;
        g_b0p[idx] = bih0[orow] + bhh0[orow];
        g_b1p[idx] = bih1[orow] + bhh1[orow];
    }
    for (int idx = bid * NTHR + tid; idx < Bq * 256; idx += NBLK * NTHR) {
        g_h0a[idx] = enc_h[idx]; g_h1a[idx] = enc_h[Bq * 256 + idx];
        g_c0[idx] = enc_c[idx];  g_c1[idx] = enc_c[Bq * 256 + idx];
        int b = idx >> 8, hh = idx & 255;
        const float* p = enc_out + (size_t)b * Lq * 256 + hh;
        float s = 0.f;
        for (int l = 0; l < Lq; l++) s += p[(size_t)l * 256];
        g_ctx[idx] = s * (1.0f / Lq);
    }
    bt += NBLK; gsync(bt);

    float *h0c = g_h0a, *h0n = g_h0b, *h1c = g_h1a, *h1n = g_h1b;
    const int bmL = (bid >> 3) * 64, bnL = (bid & 7) * 128;

    for (int t = 0; t < Lq; t++) {
        // P1: LSTM0 [emb(gather) | ctx | h0] K=768
        if (tid < 64)
            gidx[tid] = (t == 0) ? 0 : actions[(bmL + tid) * Lq + (t - 1)];
        __syncthreads();
        lstm_gemm(sp, gidx, bmL, bnL, emb, g_ctx, h0c, 768, true,
                  g_Wp0t, g_b0p, g_c0, h0n);
        bt += NBLK; gsync(bt);
        // P2: LSTM1 [h0n | h1c] K=512
        lstm_gemm(sp, gidx, bmL, bnL, h0n, h1c, nullptr, 512, false,
                  g_Wp1t, g_b1p, g_c1, h1n);
        bt += NBLK; gsync(bt);
        // P3: fused q + attention + concat + stacked + finalize (block-local)
        fused_tail(sp, bid, t, h1n, enc_out, Wa, bcrit, actions, out);
        bt += NBLK; gsync(bt);
        float* tmp = h0c; h0c = h0n; h0n = tmp;
        tmp = h1c; h1c = h1n; h1n = tmp;
    }
}

__global__ void reset_k() { g_count = 0; }

// ---------------- host ----------------
extern "C" void kernel_launch(void* const* d_in, const int* in_sizes, int n_in,
                              void* d_out, int out_size) {
    const float* enc_out = (const float*)d_in[0];
    const float* enc_h   = (const float*)d_in[1];
    const float* enc_c   = (const float*)d_in[2];
    const float* emb     = (const float*)d_in[3];
    const float* Wih0    = (const float*)d_in[4];
    const float* Whh0    = (const float*)d_in[5];
    const float* bih0    = (const float*)d_in[6];
    const float* bhh0    = (const float*)d_in[7];
    const float* Wih1    = (const float*)d_in[8];
    const float* Whh1    = (const float*)d_in[9];
    const float* bih1    = (const float*)d_in[10];
    const float* bhh1    = (const float*)d_in[11];
    const float* Wa      = (const float*)d_in[12];
    const float* Wconcat = (const float*)d_in[13];
    const float* Wout    = (const float*)d_in[14];
    const float* Wcrit   = (const float*)d_in[15];
    const float* bcrit   = (const float*)d_in[16];
    const int*   actions = (const int*)d_in[17];
    float* out = (float*)d_out;

    const int smem = (int)sizeof(SPool);
    cudaFuncSetAttribute(mega, cudaFuncAttributeMaxDynamicSharedMemorySize, smem);
    reset_k<<<1, 1>>>();
    mega<<<NBLK, NTHR, smem>>>(enc_out, enc_h, enc_c, emb,
                               Wih0, Whh0, bih0, bhh0,
                               Wih1, Whh1, bih1, bhh1,
                               Wa, Wconcat, Wout, Wcrit, bcrit, actions, out);
}

// round 9
// speedup vs baseline: 1.5519x; 1.5519x over previous
#include <cuda_runtime.h>
#include <cuda_bf16.h>
#include <cstdint>

#define Bq 1024
#define Lq 100
#define NBLK 128
#define NTHR 512

typedef unsigned long long u64;

// ---------------- static scratch ----------------
// pre-split/pre-swizzled bf16 weight images, k-major [k][n] per 64x64 tile:
// [ct][chunk][hi 8192B | lo 8192B]
__device__ __align__(16) unsigned char g_W0sw[16 * 12 * 16384];  // 3 MB
__device__ __align__(16) unsigned char g_W1sw[16 * 8 * 16384];   // 2 MB
__device__ float g_b0p[1024], g_b1p[1024];
__device__ float g_WaT[256 * 256];
__device__ float g_h0a[Bq * 256], g_h0b[Bq * 256];
__device__ float g_h1a[Bq * 256], g_h1b[Bq * 256];
__device__ float g_c0[Bq * 256], g_c1[Bq * 256];
__device__ float g_ctx[Bq * 256], g_ctx_att[Bq * 256];
__device__ float g_q[Bq * 256];
__device__ float g_logit[Bq * 256], g_Q[Bq * 256];
__device__ unsigned g_count;

// ---------------- smem layout (dynamic, offsets in bytes) ----------------
// LSTM: A bufs [0,65536) (per buf: hi 16K + lo 16K), W bufs [65536, 98304)
// Dsm epilogue reuses [0, 32768) (buf0 A region; final mma reads buf1 only)
#define AHI_OFF(b) ((b) * 32768)
#define ALO_OFF(b) (AHI_OFF(b) + 16384)
#define WHI_OFF(b) (65536 + (b) * 16384)
#define WLO_OFF(b) (WHI_OFF(b) + 8192)
#define SMEM_TOTAL 106496

#define SWZ(x) ((x) ^ (((x) >> 3) & 0x70))

// ---------------- f32x2 helpers (tail SIMT GEMMs) ----------------
__device__ __forceinline__ u64 pk2(float lo, float hi) {
    u64 r; asm("mov.b64 %0, {%1, %2};" : "=l"(r) : "f"(lo), "f"(hi)); return r;
}
__device__ __forceinline__ float2 up2(u64 v) {
    float2 r; asm("mov.b64 {%0, %1}, %2;" : "=f"(r.x), "=f"(r.y) : "l"(v)); return r;
}
__device__ __forceinline__ void fma2(u64& d, u64 a, u64 b) {
    asm("fma.rn.f32x2 %0, %1, %2, %0;" : "+l"(d) : "l"(a), "l"(b));
}
__device__ __forceinline__ float sigm(float x) { return 1.f / (1.f + __expf(-x)); }

// ---------------- tensor-core primitives (sm_80-class, no arch suffix) ------
__device__ __forceinline__ uint32_t smem_u32(const void* p) {
    uint32_t a;
    asm("{ .reg .u64 t; cvta.to.shared.u64 t, %1; cvt.u32.u64 %0, t; }"
        : "=r"(a) : "l"(p));
    return a;
}
#define LDSM4(r, a) asm volatile( \
    "ldmatrix.sync.aligned.m8n8.x4.shared.b16 {%0,%1,%2,%3}, [%4];" \
    : "=r"((r)[0]), "=r"((r)[1]), "=r"((r)[2]), "=r"((r)[3]) : "r"(a))
#define LDSM4T(r, a) asm volatile( \
    "ldmatrix.sync.aligned.m8n8.x4.trans.shared.b16 {%0,%1,%2,%3}, [%4];" \
    : "=r"((r)[0]), "=r"((r)[1]), "=r"((r)[2]), "=r"((r)[3]) : "r"(a))
__device__ __forceinline__ void mma16816(float* d, const uint32_t* a,
                                         uint32_t b0, uint32_t b1) {
    asm volatile("mma.sync.aligned.m16n8k16.row.col.f32.bf16.bf16.f32 "
                 "{%0,%1,%2,%3}, {%4,%5,%6,%7}, {%8,%9}, {%0,%1,%2,%3};"
                 : "+f"(d[0]), "+f"(d[1]), "+f"(d[2]), "+f"(d[3])
                 : "r"(a[0]), "r"(a[1]), "r"(a[2]), "r"(a[3]), "r"(b0), "r"(b1));
}
__device__ __forceinline__ uint32_t pkbf(float a, float b) {
    uint16_t ua = __bfloat16_as_ushort(__float2bfloat16(a));
    uint16_t ub = __bfloat16_as_ushort(__float2bfloat16(b));
    return (uint32_t)ua | ((uint32_t)ub << 16);
}

// ---------------- grid barrier ----------------
__device__ __forceinline__ void gsync(unsigned target) {
    __syncthreads();
    if (threadIdx.x == 0) {
        unsigned o;
        asm volatile("atom.add.release.gpu.u32 %0, [%1], 1;"
                     : "=r"(o) : "l"(&g_count) : "memory");
        unsigned cur;
        do {
            asm volatile("ld.acquire.gpu.u32 %0, [%1];"
                         : "=r"(cur) : "l"(&g_count) : "memory");
        } while ((int)(cur - target) < 0);
    }
    __syncthreads();
}

// ---------------- tail pool (verbatim R3 layout) ----------------
struct TailPool {
    union {
        struct { float As[16][136]; float Ws[16][72]; } g;
        struct { float q[256]; float sc[128]; float part[512]; float tile[100 * 256]; } a;
        struct { float part[512]; } f;
    };
};

// =============== LSTM via mma.sync bf16-split ================================
// Block tile M=128 x N=64 (gate-interleaved). 16 warps = 4(M) x 4(N).
__device__ void lstm_mma(char* sm, uint32_t smb, const int* gidx, int bm, int ct,
                         const float* A0, const float* A1, const float* A2, int nch,
                         bool gather, const unsigned char* __restrict__ Wsw,
                         const float* __restrict__ bias,
                         float* __restrict__ cst, float* __restrict__ hout) {
    const int tid = threadIdx.x;
    const int warp = tid >> 5, lane = tid & 31;
    const int mw = warp & 3, nw = warp >> 2;
    const int row = tid >> 2, q = tid & 3;

    float d[2][2][4];
#pragma unroll
    for (int mt = 0; mt < 2; mt++)
#pragma unroll
        for (int nt = 0; nt < 2; nt++)
#pragma unroll
            for (int e = 0; e < 4; e++) d[mt][nt][e] = 0.f;

    // ldmatrix lane address components (constant over chunks)
    const int lrowA = mw * 32 + (lane & 15);            // + mt*16
    const int lkselA = (lane >> 4);                      // 16B chunk bit
    const int lrowB = (lane & 15);                       // + ks*16
    const int ljB = nw * 2 + (lane >> 4);

    float f[16];
    uint4 w0, w1;
    {   // prefetch chunk 0
        int kc = q * 16;
        const float* p = gather ? (A0 + (size_t)gidx[row] * 256 + kc)
                                : (A0 + (size_t)(bm + row) * 256 + kc);
        const float4* p4 = (const float4*)p;
        *(float4*)(f + 0) = p4[0]; *(float4*)(f + 4) = p4[1];
        *(float4*)(f + 8) = p4[2]; *(float4*)(f + 12) = p4[3];
        const uint4* wsrc = (const uint4*)Wsw;
        w0 = wsrc[tid]; w1 = wsrc[512 + tid];
    }

    for (int c = 0; c < nch; c++) {
        const int buf = c & 1;
        // ---- store staged chunk ----
        {
            uint32_t hw[8], lw[8];
#pragma unroll
            for (int i = 0; i < 8; i++) {
                float a = f[2 * i], b = f[2 * i + 1];
                __nv_bfloat16 ha = __float2bfloat16(a), hb = __float2bfloat16(b);
                hw[i] = (uint32_t)__bfloat16_as_ushort(ha)
                      | ((uint32_t)__bfloat16_as_ushort(hb) << 16);
                lw[i] = pkbf(a - __bfloat162float(ha), b - __bfloat162float(hb));
            }
            uint32_t b0 = row * 128 + q * 32;
            uint32_t s0 = SWZ(b0), s1 = SWZ(b0 + 16);
            *(uint4*)(sm + AHI_OFF(buf) + s0) = make_uint4(hw[0], hw[1], hw[2], hw[3]);
            *(uint4*)(sm + AHI_OFF(buf) + s1) = make_uint4(hw[4], hw[5], hw[6], hw[7]);
            *(uint4*)(sm + ALO_OFF(buf) + s0) = make_uint4(lw[0], lw[1], lw[2], lw[3]);
            *(uint4*)(sm + ALO_OFF(buf) + s1) = make_uint4(lw[4], lw[5], lw[6], lw[7]);
            *(uint4*)(sm + WHI_OFF(buf) + tid * 16) = w0;
            *(uint4*)(sm + WLO_OFF(buf) + tid * 16) = w1;
        }
        __syncthreads();
        // ---- prefetch next chunk ----
        if (c + 1 < nch) {
            int cn = c + 1;
            int seg = cn >> 2;
            int kc = ((cn & 3) * 64) + q * 16;
            const float* Ab = (seg == 0) ? A0 : (seg == 1 ? A1 : A2);
            const float* p = (gather && seg == 0)
                             ? (Ab + (size_t)gidx[row] * 256 + kc)
                             : (Ab + (size_t)(bm + row) * 256 + kc);
            const float4* p4 = (const float4*)p;
            *(float4*)(f + 0) = p4[0]; *(float4*)(f + 4) = p4[1];
            *(float4*)(f + 8) = p4[2]; *(float4*)(f + 12) = p4[3];
            const uint4* wsrc = (const uint4*)(Wsw + (size_t)cn * 16384);
            w0 = wsrc[tid]; w1 = wsrc[512 + tid];
        }
        // ---- tensor math: 4 k16-steps ----
        const uint32_t ah_base = smb + AHI_OFF(buf);
        const uint32_t al_base = smb + ALO_OFF(buf);
        const uint32_t wh_base = smb + WHI_OFF(buf);
        const uint32_t wl_base = smb + WLO_OFF(buf);
#pragma unroll
        for (int ks = 0; ks < 4; ks++) {
            uint32_t ah[2][4], al[2][4], bh[4], bl[4];
#pragma unroll
            for (int mt = 0; mt < 2; mt++) {
                uint32_t off = SWZ((uint32_t)((lrowA + mt * 16) * 128
                                              + (ks * 2 + lkselA) * 16));
                LDSM4(ah[mt], ah_base + off);
                LDSM4(al[mt], al_base + off);
            }
            {
                uint32_t off = SWZ((uint32_t)((ks * 16 + lrowB) * 128 + ljB * 16));
                LDSM4T(bh, wh_base + off);
                LDSM4T(bl, wl_base + off);
            }
#pragma unroll
            for (int mt = 0; mt < 2; mt++)
#pragma unroll
                for (int nt = 0; nt < 2; nt++) {
                    mma16816(d[mt][nt], ah[mt], bh[2 * nt], bh[2 * nt + 1]);
                    mma16816(d[mt][nt], ah[mt], bl[2 * nt], bl[2 * nt + 1]);
                    mma16816(d[mt][nt], al[mt], bh[2 * nt], bh[2 * nt + 1]);
                }
        }
    }
    // ---- epilogue: D frags -> Dsm [128][64] f32 at smem offset 0 ----
    {
        float* Dsm = (float*)sm;
#pragma unroll
        for (int mt = 0; mt < 2; mt++) {
            int r = mw * 32 + mt * 16 + (lane >> 2);
#pragma unroll
            for (int nt = 0; nt < 2; nt++) {
                int cc = nw * 16 + nt * 8 + 2 * (lane & 3);
                *(float2*)(Dsm + r * 64 + cc) = make_float2(d[mt][nt][0], d[mt][nt][1]);
                *(float2*)(Dsm + (r + 8) * 64 + cc) = make_float2(d[mt][nt][2], d[mt][nt][3]);
            }
        }
    }
    __syncthreads();
    // ---- LSTM cell: 2048 cells, 4 per thread ----
    {
        const float* Dsm = (const float*)sm;
#pragma unroll
        for (int i = 0; i < 4; i++) {
            int e = tid + i * 512;
            int r = e >> 4, hl = e & 15;
            float4 g4 = *(const float4*)(Dsm + r * 64 + hl * 4);
            int nb = ct * 64 + hl * 4;
            float gi = g4.x + bias[nb + 0];
            float gf = g4.y + bias[nb + 1];
            float gg = g4.z + bias[nb + 2];
            float go = g4.w + bias[nb + 3];
            float I = sigm(gi), F = sigm(gf);
            float G = tanhf(gg), Og = sigm(go);
            int idx = (bm + r) * 256 + ct * 16 + hl;
            float cn = F * cst[idx] + I * G;
            cst[idx] = cn;
            hout[idx] = Og * tanhf(cn);
        }
    }
    __syncthreads();
}

// =============== small GEMM 64x32 (verbatim R3) ==============================
__device__ void gemm_small(TailPool* sp, int bm, int bn,
                           const float* A0, const float* A1, int Kt,
                           const float* __restrict__ W, const float* __restrict__ bias,
                           int mode, float* __restrict__ C) {
    const int tid = threadIdx.x;
    const int tx = tid & 15, ty = tid >> 4;
    u64 acc0 = 0ull, acc1 = 0ull;
    float4 pa, pw;
    const int rA = tid >> 2, kq = (tid & 3) * 4;
    if (tid < 256) pa = *(const float4*)(A0 + (size_t)(bm + rA) * 256 + kq);
    if (tid < 128) pw = *(const float4*)(W + (size_t)(bn + rA) * Kt + kq);
    for (int k0 = 0; k0 < Kt; k0 += 16) {
        if (tid < 256) {
            sp->g.As[kq + 0][rA] = pa.x; sp->g.As[kq + 1][rA] = pa.y;
            sp->g.As[kq + 2][rA] = pa.z; sp->g.As[kq + 3][rA] = pa.w;
        }
        if (tid < 128) {
            sp->g.Ws[kq + 0][rA] = pw.x; sp->g.Ws[kq + 1][rA] = pw.y;
            sp->g.Ws[kq + 2][rA] = pw.z; sp->g.Ws[kq + 3][rA] = pw.w;
        }
        __syncthreads();
        int kn = k0 + 16;
        if (kn < Kt) {
            if (tid < 256) {
                int k = kn + kq, seg = k >> 8, kc = k & 255;
                const float* Ab = seg ? A1 : A0;
                pa = *(const float4*)(Ab + (size_t)(bm + rA) * 256 + kc);
            }
            if (tid < 128) pw = *(const float4*)(W + (size_t)(bn + rA) * Kt + kn + kq);
        }
#pragma unroll
        for (int kk = 0; kk < 16; kk++) {
            float2 a = *(const float2*)&sp->g.As[kk][ty * 2];
            u64 wv = *(const u64*)&sp->g.Ws[kk][tx * 2];
            fma2(acc0, pk2(a.x, a.x), wv);
            fma2(acc1, pk2(a.y, a.y), wv);
        }
        __syncthreads();
    }
#pragma unroll
    for (int j = 0; j < 2; j++) {
        float2 v = up2(j ? acc1 : acc0);
        int rw = bm + ty * 2 + j;
        int c0 = bn + tx * 2;
        float v0 = v.x, v1 = v.y;
        if (bias) { v0 += bias[c0]; v1 += bias[c0 + 1]; }
        if (mode == 1) { v0 = tanhf(v0); v1 = tanhf(v1); }
        C[(size_t)rw * 256 + c0] = v0;
        C[(size_t)rw * 256 + c0 + 1] = v1;
    }
}

// =============== attention (verbatim R3) =====================================
__device__ void attention_row(TailPool* sp, int b, const float* __restrict__ q,
                              const float* __restrict__ eo, float* __restrict__ ctx_att) {
    const int tid = threadIdx.x, w = tid >> 5, lane = tid & 31;
    if (tid < 256) sp->a.q[tid] = q[b * 256 + tid];
    if (tid >= 100 && tid < 128) sp->a.sc[tid] = -1e30f;
    __syncthreads();
    float4 q0 = *(const float4*)&sp->a.q[lane * 4];
    float4 q1 = *(const float4*)&sp->a.q[128 + lane * 4];
    const float* rowbase = eo + (size_t)b * Lq * 256;
    int l = w;
    float4 v0, v1;
    {
        const float* p = rowbase + (size_t)l * 256;
        v0 = *(const float4*)(p + lane * 4);
        v1 = *(const float4*)(p + 128 + lane * 4);
    }
    while (l < Lq) {
        int ln = l + 16;
        float4 n0, n1;
        if (ln < Lq) {
            const float* p = rowbase + (size_t)ln * 256;
            n0 = *(const float4*)(p + lane * 4);
            n1 = *(const float4*)(p + 128 + lane * 4);
        }
        *(float4*)&sp->a.tile[l * 256 + lane * 4] = v0;
        *(float4*)&sp->a.tile[l * 256 + 128 + lane * 4] = v1;
        float s = v0.x * q0.x + v0.y * q0.y + v0.z * q0.z + v0.w * q0.w
                + v1.x * q1.x + v1.y * q1.y + v1.z * q1.z + v1.w * q1.w;
#pragma unroll
        for (int o = 16; o; o >>= 1) s += __shfl_xor_sync(0xFFFFFFFFu, s, o);
        if (!lane) sp->a.sc[l] = s;
        v0 = n0; v1 = n1; l = ln;
    }
    __syncthreads();
    if (tid < 128) sp->a.part[tid] = sp->a.sc[tid];
    __syncthreads();
    for (int s = 64; s; s >>= 1) {
        if (tid < s) sp->a.part[tid] = fmaxf(sp->a.part[tid], sp->a.part[tid + s]);
        __syncthreads();
    }
    float mx = sp->a.part[0];
    __syncthreads();
    if (tid < 128) {
        float e = (tid < Lq) ? __expf(sp->a.sc[tid] - mx) : 0.f;
        sp->a.sc[tid] = e; sp->a.part[tid] = e;
    }
    __syncthreads();
    for (int s = 64; s; s >>= 1) {
        if (tid < s) sp->a.part[tid] += sp->a.part[tid + s];
        __syncthreads();
    }
    float inv = 1.f / sp->a.part[0];
    __syncthreads();
    int col = tid & 255, half = tid >> 8;
    float acc = 0.f;
    int l0 = half * 50;
#pragma unroll 5
    for (int l2 = l0; l2 < l0 + 50; l2++) acc += sp->a.sc[l2] * sp->a.tile[l2 * 256 + col];
    sp->a.part[tid] = acc;
    __syncthreads();
    if (tid < 256) ctx_att[b * 256 + tid] = (sp->a.part[tid] + sp->a.part[tid + 256]) * inv;
    __syncthreads();
}

// =============== finalize pair (verbatim R3) =================================
__device__ void finalize_pair(TailPool* sp, int pr, int t, const float* __restrict__ logit,
                              const float* __restrict__ Q, const int* __restrict__ actions,
                              float* __restrict__ out) {
    const int tid = threadIdx.x;
    const int col = tid & 255, half = tid >> 8;
    const int b = pr * 2 + half;
    float x = logit[b * 256 + col];
    sp->f.part[tid] = x; __syncthreads();
    for (int s = 128; s; s >>= 1) {
        if (col < s) sp->f.part[tid] = fmaxf(sp->f.part[tid], sp->f.part[tid + s]);
        __syncthreads();
    }
    float mx = sp->f.part[half * 256];
    __syncthreads();
    float e = __expf(x - mx);
    sp->f.part[tid] = e; __syncthreads();
    for (int s = 128; s; s >>= 1) {
        if (col < s) sp->f.part[tid] += sp->f.part[tid + s];
        __syncthreads();
    }
    float pi = e / sp->f.part[half * 256];
    __syncthreads();
    out[(size_t)Bq * Lq + ((size_t)b * Lq + t) * 256 + col] = pi;
    sp->f.part[tid] = pi * Q[b * 256 + col];
    __syncthreads();
    for (int s = 128; s; s >>= 1) {
        if (col < s) sp->f.part[tid] += sp->f.part[tid + s];
        __syncthreads();
    }
    if (col == 0) {
        out[(size_t)Bq * Lq + (size_t)Bq * Lq * 256 + b * Lq + t] = sp->f.part[half * 256];
        out[b * Lq + t] = (float)actions[b * Lq + t];
    }
    __syncthreads();
}

// =============== persistent mega-kernel ======================================
__global__ void __launch_bounds__(NTHR, 1)
mega(const float* __restrict__ enc_out, const float* __restrict__ enc_h,
     const float* __restrict__ enc_c, const float* __restrict__ emb,
     const float* __restrict__ Wih0, const float* __restrict__ Whh0,
     const float* __restrict__ bih0, const float* __restrict__ bhh0,
     const float* __restrict__ Wih1, const float* __restrict__ Whh1,
     const float* __restrict__ bih1, const float* __restrict__ bhh1,
     const float* __restrict__ Wa, const float* __restrict__ Wconcat,
     const float* __restrict__ Wout, const float* __restrict__ Wcrit,
     const float* __restrict__ bcrit, const int* __restrict__ actions,
     float* __restrict__ out) {
    extern __shared__ char dynsm[];
    TailPool* sp = (TailPool*)dynsm;
    __shared__ int gidx[128];
    const int bid = blockIdx.x, tid = threadIdx.x;
    const uint32_t smb = smem_u32(dynsm);
    unsigned bt = 0;

    // ---- init: pre-split/pre-swizzled weights (k-major), biases, WaT, state --
    for (int idx = bid * NTHR + tid; idx < 16 * 12 * 4096; idx += NBLK * NTHR) {
        int ct = idx / 49152, rem = idx - ct * 49152;
        int ch = rem >> 12, rr = rem & 4095;
        int k = rr >> 6, n = rr & 63;
        int np = ct * 64 + n, h = np >> 2, g = np & 3, orow = g * 256 + h;
        int kk = ch * 64 + k;
        float w = (kk < 512) ? Wih0[orow * 512 + kk] : Whh0[orow * 256 + (kk - 512)];
        __nv_bfloat16 hi = __float2bfloat16(w);
        __nv_bfloat16 lo = __float2bfloat16(w - __bfloat162float(hi));
        unsigned char* base = g_W0sw + (size_t)(ct * 12 + ch) * 16384;
        uint32_t off = SWZ((uint32_t)(k * 128 + n * 2));
        *(__nv_bfloat16*)(base + off) = hi;
        *(__nv_bfloat16*)(base + 8192 + off) = lo;
    }
    for (int idx = bid * NTHR + tid; idx < 16 * 8 * 4096; idx += NBLK * NTHR) {
        int ct = idx / 32768, rem = idx - ct * 32768;
        int ch = rem >> 12, rr = rem & 4095;
        int k = rr >> 6, n = rr & 63;
        int np = ct * 64 + n, h = np >> 2, g = np & 3, orow = g * 256 + h;
        int kk = ch * 64 + k;
        float w = (kk < 256) ? Wih1[orow * 256 + kk] : Whh1[orow * 256 + (kk - 256)];
        __nv_bfloat16 hi = __float2bfloat16(w);
        __nv_bfloat16 lo = __float2bfloat16(w - __bfloat162float(hi));
        unsigned char* base = g_W1sw + (size_t)(ct * 8 + ch) * 16384;
        uint32_t off = SWZ((uint32_t)(k * 128 + n * 2));
        *(__nv_bfloat16*)(base + off) = hi;
        *(__nv_bfloat16*)(base + 8192 + off) = lo;
    }
    for (int idx = bid * NTHR + tid; idx < 65536; idx += NBLK * NTHR) {
        int k = idx >> 8, h = idx & 255;
        g_WaT[idx] = Wa[h * 256 + k];
    }
    for (int idx = bid * NTHR + tid; idx < 1024; idx += NBLK * NTHR) {
        int h = idx >> 2, g = idx & 3, orow = g * 256 + h;
        g_b0p[idx] = bih0[orow] + bhh0[orow];
        g_b1p[idx] = bih1[orow] + bhh1[orow];
    }
    for (int idx = bid * NTHR + tid; idx < Bq * 256; idx += NBLK * NTHR) {
        g_h0a[idx] = enc_h[idx]; g_h1a[idx] = enc_h[Bq * 256 + idx];
        g_c0[idx] = enc_c[idx];  g_c1[idx] = enc_c[Bq * 256 + idx];
        int b = idx >> 8, hh = idx & 255;
        const float* p = enc_out + (size_t)b * Lq * 256 + hh;
        float s = 0.f;
        for (int l = 0; l < Lq; l++) s += p[(size_t)l * 256];
        g_ctx[idx] = s * (1.0f / Lq);
    }
    bt += NBLK; gsync(bt);

    float *h0c = g_h0a, *h0n = g_h0b, *h1c = g_h1a, *h1n = g_h1b;
    const int bmL = (bid >> 4) * 128, ctL = bid & 15;
    const int bmS = (bid >> 3) * 64,  bnS = (bid & 7) * 32;

    for (int t = 0; t < Lq; t++) {
        // P1: LSTM0 [emb(gather) | ctx | h0] K=768, tensor cores
        if (tid < 128)
            gidx[tid] = (t == 0) ? 0 : actions[(bmL + tid) * Lq + (t - 1)];
        __syncthreads();
        lstm_mma(dynsm, smb, gidx, bmL, ctL, emb, g_ctx, h0c, 12, true,
                 g_W0sw + (size_t)ctL * (12 * 16384), g_b0p, g_c0, h0n);
        bt += NBLK; gsync(bt);
        // P2: LSTM1 [h0n | h1c] K=512, tensor cores
        lstm_mma(dynsm, smb, gidx, bmL, ctL, h0n, h1c, nullptr, 8, false,
                 g_W1sw + (size_t)ctL * (8 * 16384), g_b1p, g_c1, h1n);
        bt += NBLK; gsync(bt);
        // P3: q = h1 @ Wa
        gemm_small(sp, bmS, bnS, h1n, nullptr, 256, g_WaT, nullptr, 0, g_q);
        bt += NBLK; gsync(bt);
        // P4: attention (8 rows sequential per block)
        for (int b = bid; b < Bq; b += NBLK)
            attention_row(sp, b, g_q, enc_out, g_ctx_att);
        bt += NBLK; gsync(bt);
        // P5: ctx = tanh([h1|ctx_att] @ Wconcat^T)
        gemm_small(sp, bmS, bnS, h1n, g_ctx_att, 512, Wconcat, nullptr, 1, g_ctx);
        bt += NBLK; gsync(bt);
        // P6: logit = ctx @ Wout^T
        gemm_small(sp, bmS, bnS, g_ctx, nullptr, 256, Wout, nullptr, 0, g_logit);
        bt += NBLK; gsync(bt);
        // P7: Q = logit @ Wcrit^T + bcrit
        gemm_small(sp, bmS, bnS, g_logit, nullptr, 256, Wcrit, bcrit, 0, g_Q);
        bt += NBLK; gsync(bt);
        // P8: finalize (no trailing barrier)
        for (int pr = bid; pr < 512; pr += NBLK)
            finalize_pair(sp, pr, t, g_logit, g_Q, actions, out);
        float* tmp = h0c; h0c = h0n; h0n = tmp;
        tmp = h1c; h1c = h1n; h1n = tmp;
    }
}

__global__ void reset_k() { g_count = 0; }

// ---------------- host ----------------
extern "C" void kernel_launch(void* const* d_in, const int* in_sizes, int n_in,
                              void* d_out, int out_size) {
    const float* enc_out = (const float*)d_in[0];
    const float* enc_h   = (const float*)d_in[1];
    const float* enc_c   = (const float*)d_in[2];
    const float* emb     = (const float*)d_in[3];
    const float* Wih0    = (const float*)d_in[4];
    const float* Whh0    = (const float*)d_in[5];
    const float* bih0    = (const float*)d_in[6];
    const float* bhh0    = (const float*)d_in[7];
    const float* Wih1    = (const float*)d_in[8];
    const float* Whh1    = (const float*)d_in[9];
    const float* bih1    = (const float*)d_in[10];
    const float* bhh1    = (const float*)d_in[11];
    const float* Wa      = (const float*)d_in[12];
    const float* Wconcat = (const float*)d_in[13];
    const float* Wout    = (const float*)d_in[14];
    const float* Wcrit   = (const float*)d_in[15];
    const float* bcrit   = (const float*)d_in[16];
    const int*   actions = (const int*)d_in[17];
    float* out = (float*)d_out;

    cudaFuncSetAttribute(mega, cudaFuncAttributeMaxDynamicSharedMemorySize, SMEM_TOTAL);
    reset_k<<<1, 1>>>();
    mega<<<NBLK, NTHR, SMEM_TOTAL>>>(enc_out, enc_h, enc_c, emb,
                                     Wih0, Whh0, bih0, bhh0,
                                     Wih1, Whh1, bih1, bhh1,
                                     Wa, Wconcat, Wout, Wcrit, bcrit, actions, out);
}

// round 10
// speedup vs baseline: 1.7648x; 1.1372x over previous
#include <cuda_runtime.h>
#include <cuda_bf16.h>
#include <cstdint>

#define Bq 1024
#define Lq 100
#define NBLK 128
#define NTHR 512

typedef unsigned long long u64;

// ---------------- static scratch ----------------
// pre-split/pre-swizzled bf16 weight images, k-major [k][n] per 64x64 tile:
// layout [n-tile][chunk][hi 8192B | lo 8192B]
__device__ __align__(16) unsigned char g_W0sw[16 * 12 * 16384];  // 3 MB
__device__ __align__(16) unsigned char g_W1sw[16 * 8 * 16384];   // 2 MB
__device__ __align__(16) unsigned char g_Waw[4 * 4 * 16384];     // 256 KB
__device__ __align__(16) unsigned char g_Wccw[4 * 8 * 16384];    // 512 KB
__device__ __align__(16) unsigned char g_Wskw[8 * 4 * 16384];    // 512 KB
__device__ float g_Wco[256 * 256];
__device__ float g_b0p[1024], g_b1p[1024];
__device__ float g_h0a[Bq * 256], g_h0b[Bq * 256];
__device__ float g_h1a[Bq * 256], g_h1b[Bq * 256];
__device__ float g_c0[Bq * 256], g_c1[Bq * 256];
__device__ float g_ctx[Bq * 256], g_ctx_att[Bq * 256];
__device__ float g_q[Bq * 256];
__device__ float g_logit[Bq * 256], g_Q[Bq * 256];
__device__ unsigned g_count;

// ---------------- smem layout (dynamic, offsets in bytes) ----------------
#define AHI_OFF(b) ((b) * 32768)
#define ALO_OFF(b) (AHI_OFF(b) + 16384)
#define WHI_OFF(b) (65536 + (b) * 16384)
#define WLO_OFF(b) (WHI_OFF(b) + 8192)
#define SMEM_TOTAL 106496

#define SWZ(x) ((x) ^ (((x) >> 3) & 0x70))

__device__ __forceinline__ float sigm(float x) { return 1.f / (1.f + __expf(-x)); }

// ---------------- tensor-core primitives ----------------
__device__ __forceinline__ uint32_t smem_u32(const void* p) {
    uint32_t a;
    asm("{ .reg .u64 t; cvta.to.shared.u64 t, %1; cvt.u32.u64 %0, t; }"
        : "=r"(a) : "l"(p));
    return a;
}
#define LDSM4(r, a) asm volatile( \
    "ldmatrix.sync.aligned.m8n8.x4.shared.b16 {%0,%1,%2,%3}, [%4];" \
    : "=r"((r)[0]), "=r"((r)[1]), "=r"((r)[2]), "=r"((r)[3]) : "r"(a))
#define LDSM4T(r, a) asm volatile( \
    "ldmatrix.sync.aligned.m8n8.x4.trans.shared.b16 {%0,%1,%2,%3}, [%4];" \
    : "=r"((r)[0]), "=r"((r)[1]), "=r"((r)[2]), "=r"((r)[3]) : "r"(a))
__device__ __forceinline__ void mma16816(float* d, const uint32_t* a,
                                         uint32_t b0, uint32_t b1) {
    asm volatile("mma.sync.aligned.m16n8k16.row.col.f32.bf16.bf16.f32 "
                 "{%0,%1,%2,%3}, {%4,%5,%6,%7}, {%8,%9}, {%0,%1,%2,%3};"
                 : "+f"(d[0]), "+f"(d[1]), "+f"(d[2]), "+f"(d[3])
                 : "r"(a[0]), "r"(a[1]), "r"(a[2]), "r"(a[3]), "r"(b0), "r"(b1));
}
__device__ __forceinline__ uint32_t pkbf(float a, float b) {
    uint16_t ua = __bfloat16_as_ushort(__float2bfloat16(a));
    uint16_t ub = __bfloat16_as_ushort(__float2bfloat16(b));
    return (uint32_t)ua | ((uint32_t)ub << 16);
}

// ---------------- grid barrier ----------------
__device__ __forceinline__ void gsync(unsigned target) {
    __syncthreads();
    if (threadIdx.x == 0) {
        unsigned o;
        asm volatile("atom.add.release.gpu.u32 %0, [%1], 1;"
                     : "=r"(o) : "l"(&g_count) : "memory");
        unsigned cur;
        do {
            asm volatile("ld.acquire.gpu.u32 %0, [%1];"
                         : "=r"(cur) : "l"(&g_count) : "memory");
        } while ((int)(cur - target) < 0);
    }
    __syncthreads();
}

// ---------------- tail pool (attention/finalize only) ----------------
struct TailPool {
    union {
        struct { float q[256]; float sc[128]; float part[512]; float tile[100 * 256]; } a;
        struct { float part[512]; } f;
    };
};

// =============== staging helper: stage one K=64 A-chunk (hi/lo split) ========
__device__ __forceinline__ void stage_A(char* sm, int buf, int row, int q,
                                        const float* f) {
    uint32_t hw[8], lw[8];
#pragma unroll
    for (int i = 0; i < 8; i++) {
        float a = f[2 * i], b = f[2 * i + 1];
        __nv_bfloat16 ha = __float2bfloat16(a), hb = __float2bfloat16(b);
        hw[i] = (uint32_t)__bfloat16_as_ushort(ha)
              | ((uint32_t)__bfloat16_as_ushort(hb) << 16);
        lw[i] = pkbf(a - __bfloat162float(ha), b - __bfloat162float(hb));
    }
    uint32_t b0 = row * 128 + q * 32;
    uint32_t s0 = SWZ(b0), s1 = SWZ(b0 + 16);
    *(uint4*)(sm + AHI_OFF(buf) + s0) = make_uint4(hw[0], hw[1], hw[2], hw[3]);
    *(uint4*)(sm + AHI_OFF(buf) + s1) = make_uint4(hw[4], hw[5], hw[6], hw[7]);
    *(uint4*)(sm + ALO_OFF(buf) + s0) = make_uint4(lw[0], lw[1], lw[2], lw[3]);
    *(uint4*)(sm + ALO_OFF(buf) + s1) = make_uint4(lw[4], lw[5], lw[6], lw[7]);
}

// =============== LSTM via mma.sync bf16-split (verbatim R9) ==================
__device__ void lstm_mma(char* sm, uint32_t smb, const int* gidx, int bm, int ct,
                         const float* A0, const float* A1, const float* A2, int nch,
                         bool gather, const unsigned char* __restrict__ Wsw,
                         const float* __restrict__ bias,
                         float* __restrict__ cst, float* __restrict__ hout) {
    const int tid = threadIdx.x;
    const int warp = tid >> 5, lane = tid & 31;
    const int mw = warp & 3, nw = warp >> 2;
    const int row = tid >> 2, q = tid & 3;

    float d[2][2][4];
#pragma unroll
    for (int mt = 0; mt < 2; mt++)
#pragma unroll
        for (int nt = 0; nt < 2; nt++)
#pragma unroll
            for (int e = 0; e < 4; e++) d[mt][nt][e] = 0.f;

    const int lrowA = mw * 32 + (lane & 15);
    const int lkselA = (lane >> 4);
    const int lrowB = (lane & 15);
    const int ljB = nw * 2 + (lane >> 4);

    float f[16];
    uint4 w0, w1;
    {
        int kc = q * 16;
        const float* p = gather ? (A0 + (size_t)gidx[row] * 256 + kc)
                                : (A0 + (size_t)(bm + row) * 256 + kc);
        const float4* p4 = (const float4*)p;
        *(float4*)(f + 0) = p4[0]; *(float4*)(f + 4) = p4[1];
        *(float4*)(f + 8) = p4[2]; *(float4*)(f + 12) = p4[3];
        const uint4* wsrc = (const uint4*)Wsw;
        w0 = wsrc[tid]; w1 = wsrc[512 + tid];
    }

    for (int c = 0; c < nch; c++) {
        const int buf = c & 1;
        stage_A(sm, buf, row, q, f);
        *(uint4*)(sm + WHI_OFF(buf) + tid * 16) = w0;
        *(uint4*)(sm + WLO_OFF(buf) + tid * 16) = w1;
        __syncthreads();
        if (c + 1 < nch) {
            int cn = c + 1;
            int seg = cn >> 2;
            int kc = ((cn & 3) * 64) + q * 16;
            const float* Ab = (seg == 0) ? A0 : (seg == 1 ? A1 : A2);
            const float* p = (gather && seg == 0)
                             ? (Ab + (size_t)gidx[row] * 256 + kc)
                             : (Ab + (size_t)(bm + row) * 256 + kc);
            const float4* p4 = (const float4*)p;
            *(float4*)(f + 0) = p4[0]; *(float4*)(f + 4) = p4[1];
            *(float4*)(f + 8) = p4[2]; *(float4*)(f + 12) = p4[3];
            const uint4* wsrc = (const uint4*)(Wsw + (size_t)cn * 16384);
            w0 = wsrc[tid]; w1 = wsrc[512 + tid];
        }
        const uint32_t ah_base = smb + AHI_OFF(buf);
        const uint32_t al_base = smb + ALO_OFF(buf);
        const uint32_t wh_base = smb + WHI_OFF(buf);
        const uint32_t wl_base = smb + WLO_OFF(buf);
#pragma unroll
        for (int ks = 0; ks < 4; ks++) {
            uint32_t ah[2][4], al[2][4], bh[4], bl[4];
#pragma unroll
            for (int mt = 0; mt < 2; mt++) {
                uint32_t off = SWZ((uint32_t)((lrowA + mt * 16) * 128
                                              + (ks * 2 + lkselA) * 16));
                LDSM4(ah[mt], ah_base + off);
                LDSM4(al[mt], al_base + off);
            }
            {
                uint32_t off = SWZ((uint32_t)((ks * 16 + lrowB) * 128 + ljB * 16));
                LDSM4T(bh, wh_base + off);
                LDSM4T(bl, wl_base + off);
            }
#pragma unroll
            for (int mt = 0; mt < 2; mt++)
#pragma unroll
                for (int nt = 0; nt < 2; nt++) {
                    mma16816(d[mt][nt], ah[mt], bh[2 * nt], bh[2 * nt + 1]);
                    mma16816(d[mt][nt], ah[mt], bl[2 * nt], bl[2 * nt + 1]);
                    mma16816(d[mt][nt], al[mt], bh[2 * nt], bh[2 * nt + 1]);
                }
        }
    }
    // epilogue: D -> Dsm -> LSTM cell
    {
        float* Dsm = (float*)sm;
#pragma unroll
        for (int mt = 0; mt < 2; mt++) {
            int r = mw * 32 + mt * 16 + (lane >> 2);
#pragma unroll
            for (int nt = 0; nt < 2; nt++) {
                int cc = nw * 16 + nt * 8 + 2 * (lane & 3);
                *(float2*)(Dsm + r * 64 + cc) = make_float2(d[mt][nt][0], d[mt][nt][1]);
                *(float2*)(Dsm + (r + 8) * 64 + cc) = make_float2(d[mt][nt][2], d[mt][nt][3]);
            }
        }
    }
    __syncthreads();
    {
        const float* Dsm = (const float*)sm;
#pragma unroll
        for (int i = 0; i < 4; i++) {
            int e = tid + i * 512;
            int r = e >> 4, hl = e & 15;
            float4 g4 = *(const float4*)(Dsm + r * 64 + hl * 4);
            int nb = ct * 64 + hl * 4;
            float gi = g4.x + bias[nb + 0];
            float gf = g4.y + bias[nb + 1];
            float gg = g4.z + bias[nb + 2];
            float go = g4.w + bias[nb + 3];
            float I = sigm(gi), F = sigm(gf);
            float G = tanhf(gg), Og = sigm(go);
            int idx = (bm + r) * 256 + ct * 16 + hl;
            float cn = F * cst[idx] + I * G;
            cst[idx] = cn;
            hout[idx] = Og * tanhf(cn);
        }
    }
    __syncthreads();
}

// =============== generic mma GEMM tile 128x64, direct-frag epilogue ==========
// mode 0: store C0; 1: tanh store C0; 3: stacked (col<256 -> C0, else C1+bias)
__device__ void mma_out(char* sm, uint32_t smb, int bm, int ct,
                        const float* A0, const float* A1, int nch,
                        const unsigned char* __restrict__ Wsw,
                        const float* __restrict__ bias, int mode,
                        float* __restrict__ C0, float* __restrict__ C1) {
    const int tid = threadIdx.x;
    const int warp = tid >> 5, lane = tid & 31;
    const int mw = warp & 3, nw = warp >> 2;
    const int row = tid >> 2, q = tid & 3;

    float d[2][2][4];
#pragma unroll
    for (int mt = 0; mt < 2; mt++)
#pragma unroll
        for (int nt = 0; nt < 2; nt++)
#pragma unroll
            for (int e = 0; e < 4; e++) d[mt][nt][e] = 0.f;

    const int lrowA = mw * 32 + (lane & 15);
    const int lkselA = (lane >> 4);
    const int lrowB = (lane & 15);
    const int ljB = nw * 2 + (lane >> 4);

    float f[16];
    uint4 w0, w1;
    {
        const float4* p4 = (const float4*)(A0 + (size_t)(bm + row) * 256 + q * 16);
        *(float4*)(f + 0) = p4[0]; *(float4*)(f + 4) = p4[1];
        *(float4*)(f + 8) = p4[2]; *(float4*)(f + 12) = p4[3];
        const uint4* wsrc = (const uint4*)Wsw;
        w0 = wsrc[tid]; w1 = wsrc[512 + tid];
    }

    for (int c = 0; c < nch; c++) {
        const int buf = c & 1;
        stage_A(sm, buf, row, q, f);
        *(uint4*)(sm + WHI_OFF(buf) + tid * 16) = w0;
        *(uint4*)(sm + WLO_OFF(buf) + tid * 16) = w1;
        __syncthreads();
        if (c + 1 < nch) {
            int cn = c + 1;
            int seg = cn >> 2;
            int kc = ((cn & 3) * 64) + q * 16;
            const float* Ab = seg ? A1 : A0;
            const float4* p4 = (const float4*)(Ab + (size_t)(bm + row) * 256 + kc);
            *(float4*)(f + 0) = p4[0]; *(float4*)(f + 4) = p4[1];
            *(float4*)(f + 8) = p4[2]; *(float4*)(f + 12) = p4[3];
            const uint4* wsrc = (const uint4*)(Wsw + (size_t)cn * 16384);
            w0 = wsrc[tid]; w1 = wsrc[512 + tid];
        }
        const uint32_t ah_base = smb + AHI_OFF(buf);
        const uint32_t al_base = smb + ALO_OFF(buf);
        const uint32_t wh_base = smb + WHI_OFF(buf);
        const uint32_t wl_base = smb + WLO_OFF(buf);
#pragma unroll
        for (int ks = 0; ks < 4; ks++) {
            uint32_t ah[2][4], al[2][4], bh[4], bl[4];
#pragma unroll
            for (int mt = 0; mt < 2; mt++) {
                uint32_t off = SWZ((uint32_t)((lrowA + mt * 16) * 128
                                              + (ks * 2 + lkselA) * 16));
                LDSM4(ah[mt], ah_base + off);
                LDSM4(al[mt], al_base + off);
            }
            {
                uint32_t off = SWZ((uint32_t)((ks * 16 + lrowB) * 128 + ljB * 16));
                LDSM4T(bh, wh_base + off);
                LDSM4T(bl, wl_base + off);
            }
#pragma unroll
            for (int mt = 0; mt < 2; mt++)
#pragma unroll
                for (int nt = 0; nt < 2; nt++) {
                    mma16816(d[mt][nt], ah[mt], bh[2 * nt], bh[2 * nt + 1]);
                    mma16816(d[mt][nt], ah[mt], bl[2 * nt], bl[2 * nt + 1]);
                    mma16816(d[mt][nt], al[mt], bh[2 * nt], bh[2 * nt + 1]);
                }
        }
    }
    // direct fragment store
#pragma unroll
    for (int mt = 0; mt < 2; mt++) {
        int r = bm + mw * 32 + mt * 16 + (lane >> 2);
#pragma unroll
        for (int nt = 0; nt < 2; nt++) {
            int cc = nw * 16 + nt * 8 + 2 * (lane & 3);
            int colg = ct * 64 + cc;
            float2 v0 = make_float2(d[mt][nt][0], d[mt][nt][1]);
            float2 v1 = make_float2(d[mt][nt][2], d[mt][nt][3]);
            if (mode == 1) {
                v0.x = tanhf(v0.x); v0.y = tanhf(v0.y);
                v1.x = tanhf(v1.x); v1.y = tanhf(v1.y);
            }
            if (mode == 3 && colg >= 256) {
                float b0 = bias[colg - 256], b1 = bias[colg - 255];
                v0.x += b0; v0.y += b1; v1.x += b0; v1.y += b1;
                *(float2*)(C1 + (size_t)r * 256 + colg - 256) = v0;
                *(float2*)(C1 + (size_t)(r + 8) * 256 + colg - 256) = v1;
            } else {
                *(float2*)(C0 + (size_t)r * 256 + colg) = v0;
                *(float2*)(C0 + (size_t)(r + 8) * 256 + colg) = v1;
            }
        }
    }
    __syncthreads();
}

// =============== attention (verbatim R3/R9) ==================================
__device__ void attention_row(TailPool* sp, int b, const float* __restrict__ q,
                              const float* __restrict__ eo, float* __restrict__ ctx_att) {
    const int tid = threadIdx.x, w = tid >> 5, lane = tid & 31;
    if (tid < 256) sp->a.q[tid] = q[b * 256 + tid];
    if (tid >= 100 && tid < 128) sp->a.sc[tid] = -1e30f;
    __syncthreads();
    float4 q0 = *(const float4*)&sp->a.q[lane * 4];
    float4 q1 = *(const float4*)&sp->a.q[128 + lane * 4];
    const float* rowbase = eo + (size_t)b * Lq * 256;
    int l = w;
    float4 v0, v1;
    {
        const float* p = rowbase + (size_t)l * 256;
        v0 = *(const float4*)(p + lane * 4);
        v1 = *(const float4*)(p + 128 + lane * 4);
    }
    while (l < Lq) {
        int ln = l + 16;
        float4 n0, n1;
        if (ln < Lq) {
            const float* p = rowbase + (size_t)ln * 256;
            n0 = *(const float4*)(p + lane * 4);
            n1 = *(const float4*)(p + 128 + lane * 4);
        }
        *(float4*)&sp->a.tile[l * 256 + lane * 4] = v0;
        *(float4*)&sp->a.tile[l * 256 + 128 + lane * 4] = v1;
        float s = v0.x * q0.x + v0.y * q0.y + v0.z * q0.z + v0.w * q0.w
                + v1.x * q1.x + v1.y * q1.y + v1.z * q1.z + v1.w * q1.w;
#pragma unroll
        for (int o = 16; o; o >>= 1) s += __shfl_xor_sync(0xFFFFFFFFu, s, o);
        if (!lane) sp->a.sc[l] = s;
        v0 = n0; v1 = n1; l = ln;
    }
    __syncthreads();
    if (tid < 128) sp->a.part[tid] = sp->a.sc[tid];
    __syncthreads();
    for (int s = 64; s; s >>= 1) {
        if (tid < s) sp->a.part[tid] = fmaxf(sp->a.part[tid], sp->a.part[tid + s]);
        __syncthreads();
    }
    float mx = sp->a.part[0];
    __syncthreads();
    if (tid < 128) {
        float e = (tid < Lq) ? __expf(sp->a.sc[tid] - mx) : 0.f;
        sp->a.sc[tid] = e; sp->a.part[tid] = e;
    }
    __syncthreads();
    for (int s = 64; s; s >>= 1) {
        if (tid < s) sp->a.part[tid] += sp->a.part[tid + s];
        __syncthreads();
    }
    float inv = 1.f / sp->a.part[0];
    __syncthreads();
    int col = tid & 255, half = tid >> 8;
    float acc = 0.f;
    int l0 = half * 50;
#pragma unroll 5
    for (int l2 = l0; l2 < l0 + 50; l2++) acc += sp->a.sc[l2] * sp->a.tile[l2 * 256 + col];
    sp->a.part[tid] = acc;
    __syncthreads();
    if (tid < 256) ctx_att[b * 256 + tid] = (sp->a.part[tid] + sp->a.part[tid + 256]) * inv;
    __syncthreads();
}

// =============== finalize pair (verbatim R3/R9) ==============================
__device__ void finalize_pair(TailPool* sp, int pr, int t, const float* __restrict__ logit,
                              const float* __restrict__ Q, const int* __restrict__ actions,
                              float* __restrict__ out) {
    const int tid = threadIdx.x;
    const int col = tid & 255, half = tid >> 8;
    const int b = pr * 2 + half;
    float x = logit[b * 256 + col];
    sp->f.part[tid] = x; __syncthreads();
    for (int s = 128; s; s >>= 1) {
        if (col < s) sp->f.part[tid] = fmaxf(sp->f.part[tid], sp->f.part[tid + s]);
        __syncthreads();
    }
    float mx = sp->f.part[half * 256];
    __syncthreads();
    float e = __expf(x - mx);
    sp->f.part[tid] = e; __syncthreads();
    for (int s = 128; s; s >>= 1) {
        if (col < s) sp->f.part[tid] += sp->f.part[tid + s];
        __syncthreads();
    }
    float pi = e / sp->f.part[half * 256];
    __syncthreads();
    out[(size_t)Bq * Lq + ((size_t)b * Lq + t) * 256 + col] = pi;
    sp->f.part[tid] = pi * Q[b * 256 + col];
    __syncthreads();
    for (int s = 128; s; s >>= 1) {
        if (col < s) sp->f.part[tid] += sp->f.part[tid + s];
        __syncthreads();
    }
    if (col == 0) {
        out[(size_t)Bq * Lq + (size_t)Bq * Lq * 256 + b * Lq + t] = sp->f.part[half * 256];
        out[b * Lq + t] = (float)actions[b * Lq + t];
    }
    __syncthreads();
}

// =============== persistent mega-kernel ======================================
__global__ void __launch_bounds__(NTHR, 1)
mega(const float* __restrict__ enc_out, const float* __restrict__ enc_h,
     const float* __restrict__ enc_c, const float* __restrict__ emb,
     const float* __restrict__ Wih0, const float* __restrict__ Whh0,
     const float* __restrict__ bih0, const float* __restrict__ bhh0,
     const float* __restrict__ Wih1, const float* __restrict__ Whh1,
     const float* __restrict__ bih1, const float* __restrict__ bhh1,
     const float* __restrict__ Wa, const float* __restrict__ Wconcat,
     const float* __restrict__ Wout, const float* __restrict__ Wcrit,
     const float* __restrict__ bcrit, const int* __restrict__ actions,
     float* __restrict__ out) {
    extern __shared__ char dynsm[];
    TailPool* sp = (TailPool*)dynsm;
    __shared__ int gidx[128];
    const int bid = blockIdx.x, tid = threadIdx.x;
    const uint32_t smb = smem_u32(dynsm);
    unsigned bt = 0;

    // ---- init phase 0: LSTM weight images, Wa/Wcc images, Wco, biases, state
    for (int idx = bid * NTHR + tid; idx < 16 * 12 * 4096; idx += NBLK * NTHR) {
        int ct = idx / 49152, rem = idx - ct * 49152;
        int ch = rem >> 12, rr = rem & 4095;
        int k = rr >> 6, n = rr & 63;
        int np = ct * 64 + n, h = np >> 2, g = np & 3, orow = g * 256 + h;
        int kk = ch * 64 + k;
        float w = (kk < 512) ? Wih0[orow * 512 + kk] : Whh0[orow * 256 + (kk - 512)];
        __nv_bfloat16 hi = __float2bfloat16(w);
        __nv_bfloat16 lo = __float2bfloat16(w - __bfloat162float(hi));
        unsigned char* base = g_W0sw + (size_t)(ct * 12 + ch) * 16384;
        uint32_t off = SWZ((uint32_t)(k * 128 + n * 2));
        *(__nv_bfloat16*)(base + off) = hi;
        *(__nv_bfloat16*)(base + 8192 + off) = lo;
    }
    for (int idx = bid * NTHR + tid; idx < 16 * 8 * 4096; idx += NBLK * NTHR) {
        int ct = idx / 32768, rem = idx - ct * 32768;
        int ch = rem >> 12, rr = rem & 4095;
        int k = rr >> 6, n = rr & 63;
        int np = ct * 64 + n, h = np >> 2, g = np & 3, orow = g * 256 + h;
        int kk = ch * 64 + k;
        float w = (kk < 256) ? Wih1[orow * 256 + kk] : Whh1[orow * 256 + (kk - 256)];
        __nv_bfloat16 hi = __float2bfloat16(w);
        __nv_bfloat16 lo = __float2bfloat16(w - __bfloat162float(hi));
        unsigned char* base = g_W1sw + (size_t)(ct * 8 + ch) * 16384;
        uint32_t off = SWZ((uint32_t)(k * 128 + n * 2));
        *(__nv_bfloat16*)(base + off) = hi;
        *(__nv_bfloat16*)(base + 8192 + off) = lo;
    }
    // q weights: B[k][n] = Wa[k][n]
    for (int idx = bid * NTHR + tid; idx < 4 * 4 * 4096; idx += NBLK * NTHR) {
        int ct = idx / 16384, rem = idx - ct * 16384;
        int ch = rem >> 12, rr = rem & 4095;
        int k = rr >> 6, n = rr & 63;
        int np = ct * 64 + n, kk = ch * 64 + k;
        float w = Wa[kk * 256 + np];
        __nv_bfloat16 hi = __float2bfloat16(w);
        __nv_bfloat16 lo = __float2bfloat16(w - __bfloat162float(hi));
        unsigned char* base = g_Waw + (size_t)(ct * 4 + ch) * 16384;
        uint32_t off = SWZ((uint32_t)(k * 128 + n * 2));
        *(__nv_bfloat16*)(base + off) = hi;
        *(__nv_bfloat16*)(base + 8192 + off) = lo;
    }
    // concat weights: B[k][n] = Wconcat[n][k], K=512
    for (int idx = bid * NTHR + tid; idx < 4 * 8 * 4096; idx += NBLK * NTHR) {
        int ct = idx / 32768, rem = idx - ct * 32768;
        int ch = rem >> 12, rr = rem & 4095;
        int k = rr >> 6, n = rr & 63;
        int np = ct * 64 + n, kk = ch * 64 + k;
        float w = Wconcat[np * 512 + kk];
        __nv_bfloat16 hi = __float2bfloat16(w);
        __nv_bfloat16 lo = __float2bfloat16(w - __bfloat162float(hi));
        unsigned char* base = g_Wccw + (size_t)(ct * 8 + ch) * 16384;
        uint32_t off = SWZ((uint32_t)(k * 128 + n * 2));
        *(__nv_bfloat16*)(base + off) = hi;
        *(__nv_bfloat16*)(base + 8192 + off) = lo;
    }
    {   // Wco = Wcrit @ Wout (fp32, exact init)
        int g = bid * NTHR + tid;          // exactly 65536 threads
        int i = g >> 8, j = g & 255;
        float acc = 0.f;
        const float* wc = Wcrit + i * 256;
#pragma unroll 4
        for (int k = 0; k < 256; k++) acc += wc[k] * Wout[k * 256 + j];
        g_Wco[i * 256 + j] = acc;
    }
    for (int idx = bid * NTHR + tid; idx < 1024; idx += NBLK * NTHR) {
        int h = idx >> 2, g = idx & 3, orow = g * 256 + h;
        g_b0p[idx] = bih0[orow] + bhh0[orow];
        g_b1p[idx] = bih1[orow] + bhh1[orow];
    }
    for (int idx = bid * NTHR + tid; idx < Bq * 256; idx += NBLK * NTHR) {
        g_h0a[idx] = enc_h[idx]; g_h1a[idx] = enc_h[Bq * 256 + idx];
        g_c0[idx] = enc_c[idx];  g_c1[idx] = enc_c[Bq * 256 + idx];
        int b = idx >> 8, hh = idx & 255;
        const float* p = enc_out + (size_t)b * Lq * 256 + hh;
        float s = 0.f;
        for (int l = 0; l < Lq; l++) s += p[(size_t)l * 256];
        g_ctx[idx] = s * (1.0f / Lq);
    }
    bt += NBLK; gsync(bt);
    // ---- init phase 0b: stacked weight image (needs g_Wco) ----
    for (int idx = bid * NTHR + tid; idx < 8 * 4 * 4096; idx += NBLK * NTHR) {
        int ct = idx / 16384, rem = idx - ct * 16384;
        int ch = rem >> 12, rr = rem & 4095;
        int k = rr >> 6, n = rr & 63;
        int np = ct * 64 + n, kk = ch * 64 + k;
        float w = (np < 256) ? Wout[np * 256 + kk] : g_Wco[(np - 256) * 256 + kk];
        __nv_bfloat16 hi = __float2bfloat16(w);
        __nv_bfloat16 lo = __float2bfloat16(w - __bfloat162float(hi));
        unsigned char* base = g_Wskw + (size_t)(ct * 4 + ch) * 16384;
        uint32_t off = SWZ((uint32_t)(k * 128 + n * 2));
        *(__nv_bfloat16*)(base + off) = hi;
        *(__nv_bfloat16*)(base + 8192 + off) = lo;
    }
    bt += NBLK; gsync(bt);

    float *h0c = g_h0a, *h0n = g_h0b, *h1c = g_h1a, *h1n = g_h1b;
    const int bmL = (bid >> 4) * 128, ctL = bid & 15;

    for (int t = 0; t < Lq; t++) {
        // P1: LSTM0 [emb(gather) | ctx | h0] K=768, mma
        if (tid < 128)
            gidx[tid] = (t == 0) ? 0 : actions[(bmL + tid) * Lq + (t - 1)];
        __syncthreads();
        lstm_mma(dynsm, smb, gidx, bmL, ctL, emb, g_ctx, h0c, 12, true,
                 g_W0sw + (size_t)ctL * (12 * 16384), g_b0p, g_c0, h0n);
        bt += NBLK; gsync(bt);
        // P2: LSTM1 [h0n | h1c] K=512, mma
        lstm_mma(dynsm, smb, gidx, bmL, ctL, h0n, h1c, nullptr, 8, false,
                 g_W1sw + (size_t)ctL * (8 * 16384), g_b1p, g_c1, h1n);
        bt += NBLK; gsync(bt);
        // P3: q = h1 @ Wa, mma (32 tiles)
        if (bid < 32)
            mma_out(dynsm, smb, (bid >> 2) * 128, bid & 3, h1n, nullptr, 4,
                    g_Waw + (size_t)(bid & 3) * (4 * 16384), nullptr, 0, g_q, nullptr);
        bt += NBLK; gsync(bt);
        // P4: attention (8 rows sequential per block)
        for (int b = bid; b < Bq; b += NBLK)
            attention_row(sp, b, g_q, enc_out, g_ctx_att);
        bt += NBLK; gsync(bt);
        // P5: ctx = tanh([h1|ctx_att] @ Wconcat^T), mma (32 tiles, K=512)
        if (bid < 32)
            mma_out(dynsm, smb, (bid >> 2) * 128, bid & 3, h1n, g_ctx_att, 8,
                    g_Wccw + (size_t)(bid & 3) * (8 * 16384), nullptr, 1, g_ctx, nullptr);
        bt += NBLK; gsync(bt);
        // P6: [logit|Q] = ctx @ [Wout;Wco]^T + [0|bcrit], mma (64 tiles)
        if (bid < 64)
            mma_out(dynsm, smb, (bid >> 3) * 128, bid & 7, g_ctx, nullptr, 4,
                    g_Wskw + (size_t)(bid & 7) * (4 * 16384), bcrit, 3, g_logit, g_Q);
        bt += NBLK; gsync(bt);
        // P7: finalize (no trailing barrier)
        for (int pr = bid; pr < 512; pr += NBLK)
            finalize_pair(sp, pr, t, g_logit, g_Q, actions, out);
        float* tmp = h0c; h0c = h0n; h0n = tmp;
        tmp = h1c; h1c = h1n; h1n = tmp;
    }
}

__global__ void reset_k() { g_count = 0; }

// ---------------- host ----------------
extern "C" void kernel_launch(void* const* d_in, const int* in_sizes, int n_in,
                              void* d_out, int out_size) {
    const float* enc_out = (const float*)d_in[0];
    const float* enc_h   = (const float*)d_in[1];
    const float* enc_c   = (const float*)d_in[2];
    const float* emb     = (const float*)d_in[3];
    const float* Wih0    = (const float*)d_in[4];
    const float* Whh0    = (const float*)d_in[5];
    const float* bih0    = (const float*)d_in[6];
    const float* bhh0    = (const float*)d_in[7];
    const float* Wih1    = (const float*)d_in[8];
    const float* Whh1    = (const float*)d_in[9];
    const float* bih1    = (const float*)d_in[10];
    const float* bhh1    = (const float*)d_in[11];
    const float* Wa      = (const float*)d_in[12];
    const float* Wconcat = (const float*)d_in[13];
    const float* Wout    = (const float*)d_in[14];
    const float* Wcrit   = (const float*)d_in[15];
    const float* bcrit   = (const float*)d_in[16];
    const int*   actions = (const int*)d_in[17];
    float* out = (float*)d_out;

    cudaFuncSetAttribute(mega, cudaFuncAttributeMaxDynamicSharedMemorySize, SMEM_TOTAL);
    reset_k<<<1, 1>>>();
    mega<<<NBLK, NTHR, SMEM_TOTAL>>>(enc_out, enc_h, enc_c, emb,
                                     Wih0, Whh0, bih0, bhh0,
                                     Wih1, Whh1, bih1, bhh1,
                                     Wa, Wconcat, Wout, Wcrit, bcrit, actions, out);
}

// round 12
// speedup vs baseline: 2.0515x; 1.1624x over previous
#include <cuda_runtime.h>
#include <cuda_bf16.h>
#include <cstdint>

#define Bq 1024
#define Lq 100
#define NBLK 128
#define NTHR 512

typedef unsigned long long u64;

// ---------------- static scratch ----------------
__device__ __align__(16) unsigned char g_W0sw[16 * 12 * 16384];  // 3 MB
__device__ __align__(16) unsigned char g_W1sw[16 * 8 * 16384];   // 2 MB
__device__ __align__(16) unsigned char g_Waw[4 * 4 * 16384];     // 256 KB
__device__ __align__(16) unsigned char g_Wccw[4 * 8 * 16384];    // 512 KB
__device__ __align__(16) unsigned char g_Wskw[8 * 4 * 16384];    // 512 KB
__device__ float g_Wco[256 * 256];
__device__ float g_b0p[1024], g_b1p[1024];
__device__ float g_h0a[Bq * 256], g_h0b[Bq * 256];
__device__ float g_h1a[Bq * 256], g_h1b[Bq * 256];
__device__ float g_c0[Bq * 256], g_c1[Bq * 256];
__device__ float g_ctx[Bq * 256], g_ctx_att[Bq * 256];
__device__ float g_q[Bq * 256], g_pre[Bq * 256];
__device__ float g_logit[Bq * 256], g_Q[Bq * 256];
__device__ unsigned g_count;

// ---------------- smem layout (dynamic, offsets in bytes) ----------------
#define AHI_OFF(b) ((b) * 32768)
#define ALO_OFF(b) (AHI_OFF(b) + 16384)
#define WHI_OFF(b) (65536 + (b) * 16384)
#define WLO_OFF(b) (WHI_OFF(b) + 8192)
#define SMEM_TOTAL 106496

#define SWZ(x) ((x) ^ (((x) >> 3) & 0x70))

__device__ __forceinline__ float sigm(float x) { return 1.f / (1.f + __expf(-x)); }

// ---------------- tensor-core primitives ----------------
__device__ __forceinline__ uint32_t smem_u32(const void* p) {
    uint32_t a;
    asm("{ .reg .u64 t; cvta.to.shared.u64 t, %1; cvt.u32.u64 %0, t; }"
        : "=r"(a) : "l"(p));
    return a;
}
#define LDSM4(r, a) asm volatile( \
    "ldmatrix.sync.aligned.m8n8.x4.shared.b16 {%0,%1,%2,%3}, [%4];" \
    : "=r"((r)[0]), "=r"((r)[1]), "=r"((r)[2]), "=r"((r)[3]) : "r"(a))
#define LDSM4T(r, a) asm volatile( \
    "ldmatrix.sync.aligned.m8n8.x4.trans.shared.b16 {%0,%1,%2,%3}, [%4];" \
    : "=r"((r)[0]), "=r"((r)[1]), "=r"((r)[2]), "=r"((r)[3]) : "r"(a))
__device__ __forceinline__ void mma16816(float* d, const uint32_t* a,
                                         uint32_t b0, uint32_t b1) {
    asm volatile("mma.sync.aligned.m16n8k16.row.col.f32.bf16.bf16.f32 "
                 "{%0,%1,%2,%3}, {%4,%5,%6,%7}, {%8,%9}, {%0,%1,%2,%3};"
                 : "+f"(d[0]), "+f"(d[1]), "+f"(d[2]), "+f"(d[3])
                 : "r"(a[0]), "r"(a[1]), "r"(a[2]), "r"(a[3]), "r"(b0), "r"(b1));
}
__device__ __forceinline__ uint32_t pkbf(float a, float b) {
    uint16_t ua = __bfloat16_as_ushort(__float2bfloat16(a));
    uint16_t ub = __bfloat16_as_ushort(__float2bfloat16(b));
    return (uint32_t)ua | ((uint32_t)ub << 16);
}

// ---------------- grid barrier ----------------
__device__ __forceinline__ void gsync(unsigned target) {
    __syncthreads();
    if (threadIdx.x == 0) {
        unsigned o;
        asm volatile("atom.add.release.gpu.u32 %0, [%1], 1;"
                     : "=r"(o) : "l"(&g_count) : "memory");
        unsigned cur;
        do {
            asm volatile("ld.acquire.gpu.u32 %0, [%1];"
                         : "=r"(cur) : "l"(&g_count) : "memory");
        } while ((int)(cur - target) < 0);
    }
    __syncthreads();
}

// ---------------- tail pool (attention/finalize) ----------------
struct TailPool {
    union {
        struct { float acc[8][256]; float m1[8], e1[8]; } att;
        struct { float part[512]; } f;
    };
};

// =============== staging helper ==============================================
__device__ __forceinline__ void stage_A(char* sm, int buf, int row, int q,
                                        const float* f) {
    uint32_t hw[8], lw[8];
#pragma unroll
    for (int i = 0; i < 8; i++) {
        float a = f[2 * i], b = f[2 * i + 1];
        __nv_bfloat16 ha = __float2bfloat16(a), hb = __float2bfloat16(b);
        hw[i] = (uint32_t)__bfloat16_as_ushort(ha)
              | ((uint32_t)__bfloat16_as_ushort(hb) << 16);
        lw[i] = pkbf(a - __bfloat162float(ha), b - __bfloat162float(hb));
    }
    uint32_t b0 = row * 128 + q * 32;
    uint32_t s0 = SWZ(b0), s1 = SWZ(b0 + 16);
    *(uint4*)(sm + AHI_OFF(buf) + s0) = make_uint4(hw[0], hw[1], hw[2], hw[3]);
    *(uint4*)(sm + AHI_OFF(buf) + s1) = make_uint4(hw[4], hw[5], hw[6], hw[7]);
    *(uint4*)(sm + ALO_OFF(buf) + s0) = make_uint4(lw[0], lw[1], lw[2], lw[3]);
    *(uint4*)(sm + ALO_OFF(buf) + s1) = make_uint4(lw[4], lw[5], lw[6], lw[7]);
}

// =============== LSTM via mma.sync bf16-split (verbatim R9/R10) ==============
__device__ void lstm_mma(char* sm, uint32_t smb, const int* gidx, int bm, int ct,
                         const float* A0, const float* A1, const float* A2, int nch,
                         bool gather, const unsigned char* __restrict__ Wsw,
                         const float* __restrict__ bias,
                         float* __restrict__ cst, float* __restrict__ hout) {
    const int tid = threadIdx.x;
    const int warp = tid >> 5, lane = tid & 31;
    const int mw = warp & 3, nw = warp >> 2;
    const int row = tid >> 2, q = tid & 3;

    float d[2][2][4];
#pragma unroll
    for (int mt = 0; mt < 2; mt++)
#pragma unroll
        for (int nt = 0; nt < 2; nt++)
#pragma unroll
            for (int e = 0; e < 4; e++) d[mt][nt][e] = 0.f;

    const int lrowA = mw * 32 + (lane & 15);
    const int lkselA = (lane >> 4);
    const int lrowB = (lane & 15);
    const int ljB = nw * 2 + (lane >> 4);

    float f[16];
    uint4 w0, w1;
    {
        int kc = q * 16;
        const float* p = gather ? (A0 + (size_t)gidx[row] * 256 + kc)
                                : (A0 + (size_t)(bm + row) * 256 + kc);
        const float4* p4 = (const float4*)p;
        *(float4*)(f + 0) = p4[0]; *(float4*)(f + 4) = p4[1];
        *(float4*)(f + 8) = p4[2]; *(float4*)(f + 12) = p4[3];
        const uint4* wsrc = (const uint4*)Wsw;
        w0 = wsrc[tid]; w1 = wsrc[512 + tid];
    }

    for (int c = 0; c < nch; c++) {
        const int buf = c & 1;
        stage_A(sm, buf, row, q, f);
        *(uint4*)(sm + WHI_OFF(buf) + tid * 16) = w0;
        *(uint4*)(sm + WLO_OFF(buf) + tid * 16) = w1;
        __syncthreads();
        if (c + 1 < nch) {
            int cn = c + 1;
            int seg = cn >> 2;
            int kc = ((cn & 3) * 64) + q * 16;
            const float* Ab = (seg == 0) ? A0 : (seg == 1 ? A1 : A2);
            const float* p = (gather && seg == 0)
                             ? (Ab + (size_t)gidx[row] * 256 + kc)
                             : (Ab + (size_t)(bm + row) * 256 + kc);
            const float4* p4 = (const float4*)p;
            *(float4*)(f + 0) = p4[0]; *(float4*)(f + 4) = p4[1];
            *(float4*)(f + 8) = p4[2]; *(float4*)(f + 12) = p4[3];
            const uint4* wsrc = (const uint4*)(Wsw + (size_t)cn * 16384);
            w0 = wsrc[tid]; w1 = wsrc[512 + tid];
        }
        const uint32_t ah_base = smb + AHI_OFF(buf);
        const uint32_t al_base = smb + ALO_OFF(buf);
        const uint32_t wh_base = smb + WHI_OFF(buf);
        const uint32_t wl_base = smb + WLO_OFF(buf);
#pragma unroll
        for (int ks = 0; ks < 4; ks++) {
            uint32_t ah[2][4], al[2][4], bh[4], bl[4];
#pragma unroll
            for (int mt = 0; mt < 2; mt++) {
                uint32_t off = SWZ((uint32_t)((lrowA + mt * 16) * 128
                                              + (ks * 2 + lkselA) * 16));
                LDSM4(ah[mt], ah_base + off);
                LDSM4(al[mt], al_base + off);
            }
            {
                uint32_t off = SWZ((uint32_t)((ks * 16 + lrowB) * 128 + ljB * 16));
                LDSM4T(bh, wh_base + off);
                LDSM4T(bl, wl_base + off);
            }
#pragma unroll
            for (int mt = 0; mt < 2; mt++)
#pragma unroll
                for (int nt = 0; nt < 2; nt++) {
                    mma16816(d[mt][nt], ah[mt], bh[2 * nt], bh[2 * nt + 1]);
                    mma16816(d[mt][nt], ah[mt], bl[2 * nt], bl[2 * nt + 1]);
                    mma16816(d[mt][nt], al[mt], bh[2 * nt], bh[2 * nt + 1]);
                }
        }
    }
    {
        float* Dsm = (float*)sm;
#pragma unroll
        for (int mt = 0; mt < 2; mt++) {
            int r = mw * 32 + mt * 16 + (lane >> 2);
#pragma unroll
            for (int nt = 0; nt < 2; nt++) {
                int cc = nw * 16 + nt * 8 + 2 * (lane & 3);
                *(float2*)(Dsm + r * 64 + cc) = make_float2(d[mt][nt][0], d[mt][nt][1]);
                *(float2*)(Dsm + (r + 8) * 64 + cc) = make_float2(d[mt][nt][2], d[mt][nt][3]);
            }
        }
    }
    __syncthreads();
    {
        const float* Dsm = (const float*)sm;
#pragma unroll
        for (int i = 0; i < 4; i++) {
            int e = tid + i * 512;
            int r = e >> 4, hl = e & 15;
            float4 g4 = *(const float4*)(Dsm + r * 64 + hl * 4);
            int nb = ct * 64 + hl * 4;
            float gi = g4.x + bias[nb + 0];
            float gf = g4.y + bias[nb + 1];
            float gg = g4.z + bias[nb + 2];
            float go = g4.w + bias[nb + 3];
            float I = sigm(gi), F = sigm(gf);
            float G = tanhf(gg), Og = sigm(go);
            int idx = (bm + r) * 256 + ct * 16 + hl;
            float cn = F * cst[idx] + I * G;
            cst[idx] = cn;
            hout[idx] = Og * tanhf(cn);
        }
    }
    __syncthreads();
}

// =============== generic mma GEMM tile 128x64, direct-frag epilogue ==========
// mode 0: store C0; 1: tanh store C0; 3: stacked (col<256 -> C0, else C1+bias)
// mode 4: C0 = tanh(D + C1[pre])
__device__ void mma_out(char* sm, uint32_t smb, int bm, int ct,
                        const float* A0, const float* A1, int nch,
                        const unsigned char* __restrict__ Wsw,
                        const float* __restrict__ bias, int mode,
                        float* __restrict__ C0, float* __restrict__ C1) {
    const int tid = threadIdx.x;
    const int warp = tid >> 5, lane = tid & 31;
    const int mw = warp & 3, nw = warp >> 2;
    const int row = tid >> 2, q = tid & 3;

    float d[2][2][4];
#pragma unroll
    for (int mt = 0; mt < 2; mt++)
#pragma unroll
        for (int nt = 0; nt < 2; nt++)
#pragma unroll
            for (int e = 0; e < 4; e++) d[mt][nt][e] = 0.f;

    const int lrowA = mw * 32 + (lane & 15);
    const int lkselA = (lane >> 4);
    const int lrowB = (lane & 15);
    const int ljB = nw * 2 + (lane >> 4);

    float f[16];
    uint4 w0, w1;
    {
        const float4* p4 = (const float4*)(A0 + (size_t)(bm + row) * 256 + q * 16);
        *(float4*)(f + 0) = p4[0]; *(float4*)(f + 4) = p4[1];
        *(float4*)(f + 8) = p4[2]; *(float4*)(f + 12) = p4[3];
        const uint4* wsrc = (const uint4*)Wsw;
        w0 = wsrc[tid]; w1 = wsrc[512 + tid];
    }

    for (int c = 0; c < nch; c++) {
        const int buf = c & 1;
        stage_A(sm, buf, row, q, f);
        *(uint4*)(sm + WHI_OFF(buf) + tid * 16) = w0;
        *(uint4*)(sm + WLO_OFF(buf) + tid * 16) = w1;
        __syncthreads();
        if (c + 1 < nch) {
            int cn = c + 1;
            int seg = cn >> 2;
            int kc = ((cn & 3) * 64) + q * 16;
            const float* Ab = seg ? A1 : A0;
            const float4* p4 = (const float4*)(Ab + (size_t)(bm + row) * 256 + kc);
            *(float4*)(f + 0) = p4[0]; *(float4*)(f + 4) = p4[1];
            *(float4*)(f + 8) = p4[2]; *(float4*)(f + 12) = p4[3];
            const uint4* wsrc = (const uint4*)(Wsw + (size_t)cn * 16384);
            w0 = wsrc[tid]; w1 = wsrc[512 + tid];
        }
        const uint32_t ah_base = smb + AHI_OFF(buf);
        const uint32_t al_base = smb + ALO_OFF(buf);
        const uint32_t wh_base = smb + WHI_OFF(buf);
        const uint32_t wl_base = smb + WLO_OFF(buf);
#pragma unroll
        for (int ks = 0; ks < 4; ks++) {
            uint32_t ah[2][4], al[2][4], bh[4], bl[4];
#pragma unroll
            for (int mt = 0; mt < 2; mt++) {
                uint32_t off = SWZ((uint32_t)((lrowA + mt * 16) * 128
                                              + (ks * 2 + lkselA) * 16));
                LDSM4(ah[mt], ah_base + off);
                LDSM4(al[mt], al_base + off);
            }
            {
                uint32_t off = SWZ((uint32_t)((ks * 16 + lrowB) * 128 + ljB * 16));
                LDSM4T(bh, wh_base + off);
                LDSM4T(bl, wl_base + off);
            }
#pragma unroll
            for (int mt = 0; mt < 2; mt++)
#pragma unroll
                for (int nt = 0; nt < 2; nt++) {
                    mma16816(d[mt][nt], ah[mt], bh[2 * nt], bh[2 * nt + 1]);
                    mma16816(d[mt][nt], ah[mt], bl[2 * nt], bl[2 * nt + 1]);
                    mma16816(d[mt][nt], al[mt], bh[2 * nt], bh[2 * nt + 1]);
                }
        }
    }
#pragma unroll
    for (int mt = 0; mt < 2; mt++) {
        int r = bm + mw * 32 + mt * 16 + (lane >> 2);
#pragma unroll
        for (int nt = 0; nt < 2; nt++) {
            int cc = nw * 16 + nt * 8 + 2 * (lane & 3);
            int colg = ct * 64 + cc;
            float2 v0 = make_float2(d[mt][nt][0], d[mt][nt][1]);
            float2 v1 = make_float2(d[mt][nt][2], d[mt][nt][3]);
            if (mode == 1) {
                v0.x = tanhf(v0.x); v0.y = tanhf(v0.y);
                v1.x = tanhf(v1.x); v1.y = tanhf(v1.y);
            }
            if (mode == 4) {
                float2 p0 = *(const float2*)(C1 + (size_t)r * 256 + colg);
                float2 p1 = *(const float2*)(C1 + (size_t)(r + 8) * 256 + colg);
                v0.x = tanhf(v0.x + p0.x); v0.y = tanhf(v0.y + p0.y);
                v1.x = tanhf(v1.x + p1.x); v1.y = tanhf(v1.y + p1.y);
                *(float2*)(C0 + (size_t)r * 256 + colg) = v0;
                *(float2*)(C0 + (size_t)(r + 8) * 256 + colg) = v1;
            } else if (mode == 3 && colg >= 256) {
                float b0 = bias[colg - 256], b1 = bias[colg - 255];
                v0.x += b0; v0.y += b1; v1.x += b0; v1.y += b1;
                *(float2*)(C1 + (size_t)r * 256 + colg - 256) = v0;
                *(float2*)(C1 + (size_t)(r + 8) * 256 + colg - 256) = v1;
            } else {
                *(float2*)(C0 + (size_t)r * 256 + colg) = v0;
                *(float2*)(C0 + (size_t)(r + 8) * 256 + colg) = v1;
            }
        }
    }
    __syncthreads();
}

// =============== attention: single-pass online softmax, 8 rows/block =========
__device__ void attention8(TailPool* sp, int bid, const float* __restrict__ eo,
                           float* __restrict__ ctx_att) {
    const int tid = threadIdx.x, w = tid >> 5, lane = tid & 31;
    const int r8 = w >> 1, half = w & 1, b = bid * 8 + r8;
    const float* qb = g_q + b * 256;
    float4 q0 = *(const float4*)(qb + lane * 4);
    float4 q1 = *(const float4*)(qb + 128 + lane * 4);
    const float* eb = eo + (size_t)b * Lq * 256;
    float m = -1e30f, esum = 0.f;
    float4 a0 = make_float4(0, 0, 0, 0), a1 = make_float4(0, 0, 0, 0);
    const int l0 = half * 50;
#pragma unroll 2
    for (int l = l0; l < l0 + 50; l++) {
        const float* p = eb + (size_t)l * 256;
        float4 v0 = *(const float4*)(p + lane * 4);
        float4 v1 = *(const float4*)(p + 128 + lane * 4);
        float s = v0.x * q0.x + v0.y * q0.y + v0.z * q0.z + v0.w * q0.w
                + v1.x * q1.x + v1.y * q1.y + v1.z * q1.z + v1.w * q1.w;
#pragma unroll
        for (int o = 16; o; o >>= 1) s += __shfl_xor_sync(0xFFFFFFFFu, s, o);
        if (s <= m) {
            float wg = __expf(s - m);
            esum += wg;
            a0.x += wg * v0.x; a0.y += wg * v0.y; a0.z += wg * v0.z; a0.w += wg * v0.w;
            a1.x += wg * v1.x; a1.y += wg * v1.y; a1.z += wg * v1.z; a1.w += wg * v1.w;
        } else {
            float r = __expf(m - s);
            esum = esum * r + 1.f;
            a0.x = a0.x * r + v0.x; a0.y = a0.y * r + v0.y;
            a0.z = a0.z * r + v0.z; a0.w = a0.w * r + v0.w;
            a1.x = a1.x * r + v1.x; a1.y = a1.y * r + v1.y;
            a1.z = a1.z * r + v1.z; a1.w = a1.w * r + v1.w;
            m = s;
        }
    }
    if (half) {
        sp->att.m1[r8] = m; sp->att.e1[r8] = esum;
        *(float4*)&sp->att.acc[r8][lane * 4] = a0;
        *(float4*)&sp->att.acc[r8][128 + lane * 4] = a1;
    }
    __syncthreads();
    if (!half) {
        float m1 = sp->att.m1[r8], e1 = sp->att.e1[r8];
        float M = fmaxf(m, m1);
        float s0 = __expf(m - M), s1 = __expf(m1 - M);
        float inv = 1.f / (esum * s0 + e1 * s1);
        float4 p0 = *(const float4*)&sp->att.acc[r8][lane * 4];
        float4 p1 = *(const float4*)&sp->att.acc[r8][128 + lane * 4];
        float4 o0, o1;
        o0.x = (a0.x * s0 + p0.x * s1) * inv; o0.y = (a0.y * s0 + p0.y * s1) * inv;
        o0.z = (a0.z * s0 + p0.z * s1) * inv; o0.w = (a0.w * s0 + p0.w * s1) * inv;
        o1.x = (a1.x * s0 + p1.x * s1) * inv; o1.y = (a1.y * s0 + p1.y * s1) * inv;
        o1.z = (a1.z * s0 + p1.z * s1) * inv; o1.w = (a1.w * s0 + p1.w * s1) * inv;
        *(float4*)(ctx_att + b * 256 + lane * 4) = o0;
        *(float4*)(ctx_att + b * 256 + 128 + lane * 4) = o1;
    }
    __syncthreads();
}

// =============== finalize pair (verbatim R3/R10) =============================
__device__ void finalize_pair(TailPool* sp, int pr, int t, const float* __restrict__ logit,
                              const float* __restrict__ Q, const int* __restrict__ actions,
                              float* __restrict__ out) {
    const int tid = threadIdx.x;
    const int col = tid & 255, half = tid >> 8;
    const int b = pr * 2 + half;
    float x = logit[b * 256 + col];
    sp->f.part[tid] = x; __syncthreads();
    for (int s = 128; s; s >>= 1) {
        if (col < s) sp->f.part[tid] = fmaxf(sp->f.part[tid], sp->f.part[tid + s]);
        __syncthreads();
    }
    float mx = sp->f.part[half * 256];
    __syncthreads();
    float e = __expf(x - mx);
    sp->f.part[tid] = e; __syncthreads();
    for (int s = 128; s; s >>= 1) {
        if (col < s) sp->f.part[tid] += sp->f.part[tid + s];
        __syncthreads();
    }
    float pi = e / sp->f.part[half * 256];
    __syncthreads();
    out[(size_t)Bq * Lq + ((size_t)b * Lq + t) * 256 + col] = pi;
    sp->f.part[tid] = pi * Q[b * 256 + col];
    __syncthreads();
    for (int s = 128; s; s >>= 1) {
        if (col < s) sp->f.part[tid] += sp->f.part[tid + s];
        __syncthreads();
    }
    if (col == 0) {
        out[(size_t)Bq * Lq + (size_t)Bq * Lq * 256 + b * Lq + t] = sp->f.part[half * 256];
        out[b * Lq + t] = (float)actions[b * Lq + t];
    }
    __syncthreads();
}

// =============== persistent mega-kernel ======================================
__global__ void __launch_bounds__(NTHR, 1)
mega(const float* __restrict__ enc_out, const float* __restrict__ enc_h,
     const float* __restrict__ enc_c, const float* __restrict__ emb,
     const float* __restrict__ Wih0, const float* __restrict__ Whh0,
     const float* __restrict__ bih0, const float* __restrict__ bhh0,
     const float* __restrict__ Wih1, const float* __restrict__ Whh1,
     const float* __restrict__ bih1, const float* __restrict__ bhh1,
     const float* __restrict__ Wa, const float* __restrict__ Wconcat,
     const float* __restrict__ Wout, const float* __restrict__ Wcrit,
     const float* __restrict__ bcrit, const int* __restrict__ actions,
     float* __restrict__ out) {
    extern __shared__ char dynsm[];
    TailPool* sp = (TailPool*)dynsm;
    __shared__ int gidx[128];
    const int bid = blockIdx.x, tid = threadIdx.x;
    const uint32_t smb = smem_u32(dynsm);
    unsigned bt = 0;

    // ---- init phase 0 ----
    for (int idx = bid * NTHR + tid; idx < 16 * 12 * 4096; idx += NBLK * NTHR) {
        int ct = idx / 49152, rem = idx - ct * 49152;
        int ch = rem >> 12, rr = rem & 4095;
        int k = rr >> 6, n = rr & 63;
        int np = ct * 64 + n, h = np >> 2, g = np & 3, orow = g * 256 + h;
        int kk = ch * 64 + k;
        float w = (kk < 512) ? Wih0[orow * 512 + kk] : Whh0[orow * 256 + (kk - 512)];
        __nv_bfloat16 hi = __float2bfloat16(w);
        __nv_bfloat16 lo = __float2bfloat16(w - __bfloat162float(hi));
        unsigned char* base = g_W0sw + (size_t)(ct * 12 + ch) * 16384;
        uint32_t off = SWZ((uint32_t)(k * 128 + n * 2));
        *(__nv_bfloat16*)(base + off) = hi;
        *(__nv_bfloat16*)(base + 8192 + off) = lo;
    }
    for (int idx = bid * NTHR + tid; idx < 16 * 8 * 4096; idx += NBLK * NTHR) {
        int ct = idx / 32768, rem = idx - ct * 32768;
        int ch = rem >> 12, rr = rem & 4095;
        int k = rr >> 6, n = rr & 63;
        int np = ct * 64 + n, h = np >> 2, g = np & 3, orow = g * 256 + h;
        int kk = ch * 64 + k;
        float w = (kk < 256) ? Wih1[orow * 256 + kk] : Whh1[orow * 256 + (kk - 256)];
        __nv_bfloat16 hi = __float2bfloat16(w);
        __nv_bfloat16 lo = __float2bfloat16(w - __bfloat162float(hi));
        unsigned char* base = g_W1sw + (size_t)(ct * 8 + ch) * 16384;
        uint32_t off = SWZ((uint32_t)(k * 128 + n * 2));
        *(__nv_bfloat16*)(base + off) = hi;
        *(__nv_bfloat16*)(base + 8192 + off) = lo;
    }
    for (int idx = bid * NTHR + tid; idx < 4 * 4 * 4096; idx += NBLK * NTHR) {
        int ct = idx / 16384, rem = idx - ct * 16384;
        int ch = rem >> 12, rr = rem & 4095;
        int k = rr >> 6, n = rr & 63;
        int np = ct * 64 + n, kk = ch * 64 + k;
        float w = Wa[kk * 256 + np];
        __nv_bfloat16 hi = __float2bfloat16(w);
        __nv_bfloat16 lo = __float2bfloat16(w - __bfloat162float(hi));
        unsigned char* base = g_Waw + (size_t)(ct * 4 + ch) * 16384;
        uint32_t off = SWZ((uint32_t)(k * 128 + n * 2));
        *(__nv_bfloat16*)(base + off) = hi;
        *(__nv_bfloat16*)(base + 8192 + off) = lo;
    }
    for (int idx = bid * NTHR + tid; idx < 4 * 8 * 4096; idx += NBLK * NTHR) {
        int ct = idx / 32768, rem = idx - ct * 32768;
        int ch = rem >> 12, rr = rem & 4095;
        int k = rr >> 6, n = rr & 63;
        int np = ct * 64 + n, kk = ch * 64 + k;
        float w = Wconcat[np * 512 + kk];
        __nv_bfloat16 hi = __float2bfloat16(w);
        __nv_bfloat16 lo = __float2bfloat16(w - __bfloat162float(hi));
        unsigned char* base = g_Wccw + (size_t)(ct * 8 + ch) * 16384;
        uint32_t off = SWZ((uint32_t)(k * 128 + n * 2));
        *(__nv_bfloat16*)(base + off) = hi;
        *(__nv_bfloat16*)(base + 8192 + off) = lo;
    }
    {
        int g = bid * NTHR + tid;
        int i = g >> 8, j = g & 255;
        float acc = 0.f;
        const float* wc = Wcrit + i * 256;
#pragma unroll 4
        for (int k = 0; k < 256; k++) acc += wc[k] * Wout[k * 256 + j];
        g_Wco[i * 256 + j] = acc;
    }
    for (int idx = bid * NTHR + tid; idx < 1024; idx += NBLK * NTHR) {
        int h = idx >> 2, g = idx & 3, orow = g * 256 + h;
        g_b0p[idx] = bih0[orow] + bhh0[orow];
        g_b1p[idx] = bih1[orow] + bhh1[orow];
    }
    for (int idx = bid * NTHR + tid; idx < Bq * 256; idx += NBLK * NTHR) {
        g_h0a[idx] = enc_h[idx]; g_h1a[idx] = enc_h[Bq * 256 + idx];
        g_c0[idx] = enc_c[idx];  g_c1[idx] = enc_c[Bq * 256 + idx];
        int b = idx >> 8, hh = idx & 255;
        const float* p = enc_out + (size_t)b * Lq * 256 + hh;
        float s = 0.f;
        for (int l = 0; l < Lq; l++) s += p[(size_t)l * 256];
        g_ctx[idx] = s * (1.0f / Lq);
    }
    bt += NBLK; gsync(bt);
    for (int idx = bid * NTHR + tid; idx < 8 * 4 * 4096; idx += NBLK * NTHR) {
        int ct = idx / 16384, rem = idx - ct * 16384;
        int ch = rem >> 12, rr = rem & 4095;
        int k = rr >> 6, n = rr & 63;
        int np = ct * 64 + n, kk = ch * 64 + k;
        float w = (np < 256) ? Wout[np * 256 + kk] : g_Wco[(np - 256) * 256 + kk];
        __nv_bfloat16 hi = __float2bfloat16(w);
        __nv_bfloat16 lo = __float2bfloat16(w - __bfloat162float(hi));
        unsigned char* base = g_Wskw + (size_t)(ct * 4 + ch) * 16384;
        uint32_t off = SWZ((uint32_t)(k * 128 + n * 2));
        *(__nv_bfloat16*)(base + off) = hi;
        *(__nv_bfloat16*)(base + 8192 + off) = lo;
    }
    bt += NBLK; gsync(bt);

    float *h0c = g_h0a, *h0n = g_h0b, *h1c = g_h1a, *h1n = g_h1b;
    const int bmL = (bid >> 4) * 128, ctL = bid & 15;

    for (int t = 0; t < Lq; t++) {
        // P1: LSTM0
        if (tid < 128)
            gidx[tid] = (t == 0) ? 0 : actions[(bmL + tid) * Lq + (t - 1)];
        __syncthreads();
        lstm_mma(dynsm, smb, gidx, bmL, ctL, emb, g_ctx, h0c, 12, true,
                 g_W0sw + (size_t)ctL * (12 * 16384), g_b0p, g_c0, h0n);
        bt += NBLK; gsync(bt);
        // P2: LSTM1
        lstm_mma(dynsm, smb, gidx, bmL, ctL, h0n, h1c, nullptr, 8, false,
                 g_W1sw + (size_t)ctL * (8 * 16384), g_b1p, g_c1, h1n);
        bt += NBLK; gsync(bt);
        // P3: blocks 0-31: q = h1@Wa; blocks 32-63: pre = h1@Wcc1 (K=256)
        if (bid < 32) {
            mma_out(dynsm, smb, (bid >> 2) * 128, bid & 3, h1n, nullptr, 4,
                    g_Waw + (size_t)(bid & 3) * (4 * 16384), nullptr, 0, g_q, nullptr);
        } else if (bid < 64) {
            int b2 = bid - 32;
            mma_out(dynsm, smb, (b2 >> 2) * 128, b2 & 3, h1n, nullptr, 4,
                    g_Wccw + (size_t)(b2 & 3) * (8 * 16384), nullptr, 0, g_pre, nullptr);
        }
        bt += NBLK; gsync(bt);
        // P4: attention, 8 rows concurrent, single pass
        attention8(sp, bid, enc_out, g_ctx_att);
        bt += NBLK; gsync(bt);
        // P5: ctx = tanh(pre + ctx_att@Wcc2) (K=256, 32 tiles)
        if (bid < 32)
            mma_out(dynsm, smb, (bid >> 2) * 128, bid & 3, g_ctx_att, nullptr, 4,
                    g_Wccw + (size_t)(bid & 3) * (8 * 16384) + 4 * 16384,
                    nullptr, 4, g_ctx, g_pre);
        bt += NBLK; gsync(bt);
        // P6: [logit|Q] = ctx @ [Wout;Wco]^T + [0|bcrit] (64 tiles)
        if (bid < 64)
            mma_out(dynsm, smb, (bid >> 3) * 128, bid & 7, g_ctx, nullptr, 4,
                    g_Wskw + (size_t)(bid & 7) * (4 * 16384), bcrit, 3, g_logit, g_Q);
        bt += NBLK; gsync(bt);
        // P7: finalize (no trailing barrier)
        for (int pr = bid; pr < 512; pr += NBLK)
            finalize_pair(sp, pr, t, g_logit, g_Q, actions, out);
        float* tmp = h0c; h0c = h0n; h0n = tmp;
        tmp = h1c; h1c = h1n; h1n = tmp;
    }
}

__global__ void reset_k() { g_count = 0; }

// ---------------- host ----------------
extern "C" void kernel_launch(void* const* d_in, const int* in_sizes, int n_in,
                              void* d_out, int out_size) {
    const float* enc_out = (const float*)d_in[0];
    const float* enc_h   = (const float*)d_in[1];
    const float* enc_c   = (const float*)d_in[2];
    const float* emb     = (const float*)d_in[3];
    const float* Wih0    = (const float*)d_in[4];
    const float* Whh0    = (const float*)d_in[5];
    const float* bih0    = (const float*)d_in[6];
    const float* bhh0    = (const float*)d_in[7];
    const float* Wih1    = (const float*)d_in[8];
    const float* Whh1    = (const float*)d_in[9];
    const float* bih1    = (const float*)d_in[10];
    const float* bhh1    = (const float*)d_in[11];
    const float* Wa      = (const float*)d_in[12];
    const float* Wconcat = (const float*)d_in[13];
    const float* Wout    = (const float*)d_in[14];
    const float* Wcrit   = (const float*)d_in[15];
    const float* bcrit   = (const float*)d_in[16];
    const int*   actions = (const int*)d_in[17];
    float* out = (float*)d_out;

    cudaFuncSetAttribute(mega, cudaFuncAttributeMaxDynamicSharedMemorySize, SMEM_TOTAL);
    reset_k<<<1, 1>>>();
    mega<<<NBLK, NTHR, SMEM_TOTAL>>>(enc_out, enc_h, enc_c, emb,
                                     Wih0, Whh0, bih0, bhh0,
                                     Wih1, Whh1, bih1, bhh1,
                                     Wa, Wconcat, Wout, Wcrit, bcrit, actions, out);
}

// round 13
// speedup vs baseline: 2.5818x; 1.2585x over previous
#include <cuda_runtime.h>
#include <cuda_bf16.h>
#include <cstdint>

#define Bq 1024
#define Lq 100
#define NBLK 128
#define NTHR 512

typedef unsigned long long u64;

// ---------------- static scratch ----------------
__device__ __align__(16) unsigned char g_W0sw[16 * 12 * 16384];  // 3 MB
__device__ __align__(16) unsigned char g_W1sw[16 * 8 * 16384];   // 2 MB
__device__ __align__(16) unsigned char g_Waw[4 * 4 * 16384];     // 256 KB
__device__ __align__(16) unsigned char g_Wccw[4 * 8 * 16384];    // 512 KB
__device__ __align__(16) unsigned char g_Wskw[8 * 4 * 16384];    // 512 KB
__device__ float g_Wco[256 * 256];
__device__ float g_b0p[1024], g_b1p[1024];
__device__ float g_h0a[Bq * 256], g_h0b[Bq * 256];
__device__ float g_h1a[Bq * 256], g_h1b[Bq * 256];
__device__ float g_c0[Bq * 256], g_c1[Bq * 256];
__device__ float g_ctx[Bq * 256], g_ctx_att[Bq * 256];
__device__ float g_q[Bq * 256], g_pre[Bq * 256];
__device__ float g_logit[Bq * 256], g_Q[Bq * 256];
__device__ unsigned g_count;

// ---------------- smem layout ----------------
#define AHI_OFF(b) ((b) * 32768)
#define ALO_OFF(b) (AHI_OFF(b) + 16384)
#define WHI_OFF(b) (65536 + (b) * 16384)
#define WLO_OFF(b) (WHI_OFF(b) + 8192)
#define SMEM_TOTAL 106496

#define SWZ(x) ((x) ^ (((x) >> 3) & 0x70))

__device__ __forceinline__ float sigm(float x) { return 1.f / (1.f + __expf(-x)); }

// ---------------- tensor-core primitives ----------------
__device__ __forceinline__ uint32_t smem_u32(const void* p) {
    uint32_t a;
    asm("{ .reg .u64 t; cvta.to.shared.u64 t, %1; cvt.u32.u64 %0, t; }"
        : "=r"(a) : "l"(p));
    return a;
}
#define LDSM4(r, a) asm volatile( \
    "ldmatrix.sync.aligned.m8n8.x4.shared.b16 {%0,%1,%2,%3}, [%4];" \
    : "=r"((r)[0]), "=r"((r)[1]), "=r"((r)[2]), "=r"((r)[3]) : "r"(a))
#define LDSM4T(r, a) asm volatile( \
    "ldmatrix.sync.aligned.m8n8.x4.trans.shared.b16 {%0,%1,%2,%3}, [%4];" \
    : "=r"((r)[0]), "=r"((r)[1]), "=r"((r)[2]), "=r"((r)[3]) : "r"(a))
__device__ __forceinline__ void mma16816(float* d, const uint32_t* a,
                                         uint32_t b0, uint32_t b1) {
    asm volatile("mma.sync.aligned.m16n8k16.row.col.f32.bf16.bf16.f32 "
                 "{%0,%1,%2,%3}, {%4,%5,%6,%7}, {%8,%9}, {%0,%1,%2,%3};"
                 : "+f"(d[0]), "+f"(d[1]), "+f"(d[2]), "+f"(d[3])
                 : "r"(a[0]), "r"(a[1]), "r"(a[2]), "r"(a[3]), "r"(b0), "r"(b1));
}
__device__ __forceinline__ uint32_t pkbf(float a, float b) {
    uint16_t ua = __bfloat16_as_ushort(__float2bfloat16(a));
    uint16_t ub = __bfloat16_as_ushort(__float2bfloat16(b));
    return (uint32_t)ua | ((uint32_t)ub << 16);
}

// ---------------- grid barrier ----------------
__device__ __forceinline__ void gsync(unsigned target) {
    __syncthreads();
    if (threadIdx.x == 0) {
        unsigned o;
        asm volatile("atom.add.release.gpu.u32 %0, [%1], 1;"
                     : "=r"(o) : "l"(&g_count) : "memory");
        unsigned cur;
        do {
            asm volatile("ld.acquire.gpu.u32 %0, [%1];"
                         : "=r"(cur) : "l"(&g_count) : "memory");
        } while ((int)(cur - target) < 0);
    }
    __syncthreads();
}

// ---------------- tail pool ----------------
struct TailPool {
    struct { float acc[8][256]; float m1[8], e1[8]; } att;
};

// =============== staging helpers =============================================
__device__ __forceinline__ void stage_A(char* sm, int buf, int row, int q,
                                        const float* f) {
    uint32_t hw[8], lw[8];
#pragma unroll
    for (int i = 0; i < 8; i++) {
        float a = f[2 * i], b = f[2 * i + 1];
        __nv_bfloat16 ha = __float2bfloat16(a), hb = __float2bfloat16(b);
        hw[i] = (uint32_t)__bfloat16_as_ushort(ha)
              | ((uint32_t)__bfloat16_as_ushort(hb) << 16);
        lw[i] = pkbf(a - __bfloat162float(ha), b - __bfloat162float(hb));
    }
    uint32_t b0 = row * 128 + q * 32;
    uint32_t s0 = SWZ(b0), s1 = SWZ(b0 + 16);
    *(uint4*)(sm + AHI_OFF(buf) + s0) = make_uint4(hw[0], hw[1], hw[2], hw[3]);
    *(uint4*)(sm + AHI_OFF(buf) + s1) = make_uint4(hw[4], hw[5], hw[6], hw[7]);
    *(uint4*)(sm + ALO_OFF(buf) + s0) = make_uint4(lw[0], lw[1], lw[2], lw[3]);
    *(uint4*)(sm + ALO_OFF(buf) + s1) = make_uint4(lw[4], lw[5], lw[6], lw[7]);
}
// M=64 variant: row = tid>>3, qq = tid&7, 8 floats per thread
__device__ __forceinline__ void stage_A64(char* sm, int buf, int row, int qq,
                                          const float* f) {
    uint32_t hw[4], lw[4];
#pragma unroll
    for (int i = 0; i < 4; i++) {
        float a = f[2 * i], b = f[2 * i + 1];
        __nv_bfloat16 ha = __float2bfloat16(a), hb = __float2bfloat16(b);
        hw[i] = (uint32_t)__bfloat16_as_ushort(ha)
              | ((uint32_t)__bfloat16_as_ushort(hb) << 16);
        lw[i] = pkbf(a - __bfloat162float(ha), b - __bfloat162float(hb));
    }
    uint32_t s0 = SWZ((uint32_t)(row * 128 + qq * 16));
    *(uint4*)(sm + AHI_OFF(buf) + s0) = make_uint4(hw[0], hw[1], hw[2], hw[3]);
    *(uint4*)(sm + ALO_OFF(buf) + s0) = make_uint4(lw[0], lw[1], lw[2], lw[3]);
}

// =============== LSTM via mma.sync bf16-split (verbatim R10/R12) =============
__device__ void lstm_mma(char* sm, uint32_t smb, const int* gidx, int bm, int ct,
                         const float* A0, const float* A1, const float* A2, int nch,
                         bool gather, const unsigned char* __restrict__ Wsw,
                         const float* __restrict__ bias,
                         float* __restrict__ cst, float* __restrict__ hout) {
    const int tid = threadIdx.x;
    const int warp = tid >> 5, lane = tid & 31;
    const int mw = warp & 3, nw = warp >> 2;
    const int row = tid >> 2, q = tid & 3;

    float d[2][2][4];
#pragma unroll
    for (int mt = 0; mt < 2; mt++)
#pragma unroll
        for (int nt = 0; nt < 2; nt++)
#pragma unroll
            for (int e = 0; e < 4; e++) d[mt][nt][e] = 0.f;

    const int lrowA = mw * 32 + (lane & 15);
    const int lkselA = (lane >> 4);
    const int lrowB = (lane & 15);
    const int ljB = nw * 2 + (lane >> 4);

    float f[16];
    uint4 w0, w1;
    {
        int kc = q * 16;
        const float* p = gather ? (A0 + (size_t)gidx[row] * 256 + kc)
                                : (A0 + (size_t)(bm + row) * 256 + kc);
        const float4* p4 = (const float4*)p;
        *(float4*)(f + 0) = p4[0]; *(float4*)(f + 4) = p4[1];
        *(float4*)(f + 8) = p4[2]; *(float4*)(f + 12) = p4[3];
        const uint4* wsrc = (const uint4*)Wsw;
        w0 = wsrc[tid]; w1 = wsrc[512 + tid];
    }

    for (int c = 0; c < nch; c++) {
        const int buf = c & 1;
        stage_A(sm, buf, row, q, f);
        *(uint4*)(sm + WHI_OFF(buf) + tid * 16) = w0;
        *(uint4*)(sm + WLO_OFF(buf) + tid * 16) = w1;
        __syncthreads();
        if (c + 1 < nch) {
            int cn = c + 1;
            int seg = cn >> 2;
            int kc = ((cn & 3) * 64) + q * 16;
            const float* Ab = (seg == 0) ? A0 : (seg == 1 ? A1 : A2);
            const float* p = (gather && seg == 0)
                             ? (Ab + (size_t)gidx[row] * 256 + kc)
                             : (Ab + (size_t)(bm + row) * 256 + kc);
            const float4* p4 = (const float4*)p;
            *(float4*)(f + 0) = p4[0]; *(float4*)(f + 4) = p4[1];
            *(float4*)(f + 8) = p4[2]; *(float4*)(f + 12) = p4[3];
            const uint4* wsrc = (const uint4*)(Wsw + (size_t)cn * 16384);
            w0 = wsrc[tid]; w1 = wsrc[512 + tid];
        }
        const uint32_t ah_base = smb + AHI_OFF(buf);
        const uint32_t al_base = smb + ALO_OFF(buf);
        const uint32_t wh_base = smb + WHI_OFF(buf);
        const uint32_t wl_base = smb + WLO_OFF(buf);
#pragma unroll
        for (int ks = 0; ks < 4; ks++) {
            uint32_t ah[2][4], al[2][4], bh[4], bl[4];
#pragma unroll
            for (int mt = 0; mt < 2; mt++) {
                uint32_t off = SWZ((uint32_t)((lrowA + mt * 16) * 128
                                              + (ks * 2 + lkselA) * 16));
                LDSM4(ah[mt], ah_base + off);
                LDSM4(al[mt], al_base + off);
            }
            {
                uint32_t off = SWZ((uint32_t)((ks * 16 + lrowB) * 128 + ljB * 16));
                LDSM4T(bh, wh_base + off);
                LDSM4T(bl, wl_base + off);
            }
#pragma unroll
            for (int mt = 0; mt < 2; mt++)
#pragma unroll
                for (int nt = 0; nt < 2; nt++) {
                    mma16816(d[mt][nt], ah[mt], bh[2 * nt], bh[2 * nt + 1]);
                    mma16816(d[mt][nt], ah[mt], bl[2 * nt], bl[2 * nt + 1]);
                    mma16816(d[mt][nt], al[mt], bh[2 * nt], bh[2 * nt + 1]);
                }
        }
    }
    {
        float* Dsm = (float*)sm;
#pragma unroll
        for (int mt = 0; mt < 2; mt++) {
            int r = mw * 32 + mt * 16 + (lane >> 2);
#pragma unroll
            for (int nt = 0; nt < 2; nt++) {
                int cc = nw * 16 + nt * 8 + 2 * (lane & 3);
                *(float2*)(Dsm + r * 64 + cc) = make_float2(d[mt][nt][0], d[mt][nt][1]);
                *(float2*)(Dsm + (r + 8) * 64 + cc) = make_float2(d[mt][nt][2], d[mt][nt][3]);
            }
        }
    }
    __syncthreads();
    {
        const float* Dsm = (const float*)sm;
#pragma unroll
        for (int i = 0; i < 4; i++) {
            int e = tid + i * 512;
            int r = e >> 4, hl = e & 15;
            float4 g4 = *(const float4*)(Dsm + r * 64 + hl * 4);
            int nb = ct * 64 + hl * 4;
            float gi = g4.x + bias[nb + 0];
            float gf = g4.y + bias[nb + 1];
            float gg = g4.z + bias[nb + 2];
            float go = g4.w + bias[nb + 3];
            float I = sigm(gi), F = sigm(gf);
            float G = tanhf(gg), Og = sigm(go);
            int idx = (bm + r) * 256 + ct * 16 + hl;
            float cn = F * cst[idx] + I * G;
            cst[idx] = cn;
            hout[idx] = Og * tanhf(cn);
        }
    }
    __syncthreads();
}

// =============== mma GEMM tile M=64 x N=64, direct-frag epilogue =============
// mode 0: store C0; 3: stacked (col<256 -> C0, else C1+bias); 4: tanh(D+C1)->C0
__device__ void mma_out64(char* sm, uint32_t smb, int bm, int ct,
                          const float* A0, int nch,
                          const unsigned char* __restrict__ Wsw,
                          const float* __restrict__ bias, int mode,
                          float* __restrict__ C0, float* __restrict__ C1) {
    const int tid = threadIdx.x;
    const int warp = tid >> 5, lane = tid & 31;
    const int mw = warp & 3, nw = warp >> 2;
    const int row = tid >> 3, qq = tid & 7;

    float d[2][4];
#pragma unroll
    for (int nt = 0; nt < 2; nt++)
#pragma unroll
        for (int e = 0; e < 4; e++) d[nt][e] = 0.f;

    const int lrowA = mw * 16 + (lane & 15);
    const int lkselA = (lane >> 4);
    const int lrowB = (lane & 15);
    const int ljB = nw * 2 + (lane >> 4);

    float f[8];
    uint4 w0, w1;
    {
        const float4* p4 = (const float4*)(A0 + (size_t)(bm + row) * 256 + qq * 8);
        *(float4*)(f + 0) = p4[0]; *(float4*)(f + 4) = p4[1];
        const uint4* wsrc = (const uint4*)Wsw;
        w0 = wsrc[tid]; w1 = wsrc[512 + tid];
    }

    for (int c = 0; c < nch; c++) {
        const int buf = c & 1;
        stage_A64(sm, buf, row, qq, f);
        *(uint4*)(sm + WHI_OFF(buf) + tid * 16) = w0;
        *(uint4*)(sm + WLO_OFF(buf) + tid * 16) = w1;
        __syncthreads();
        if (c + 1 < nch) {
            int cn = c + 1;
            const float4* p4 = (const float4*)(A0 + (size_t)(bm + row) * 256
                                               + cn * 64 + qq * 8);
            *(float4*)(f + 0) = p4[0]; *(float4*)(f + 4) = p4[1];
            const uint4* wsrc = (const uint4*)(Wsw + (size_t)cn * 16384);
            w0 = wsrc[tid]; w1 = wsrc[512 + tid];
        }
        const uint32_t ah_base = smb + AHI_OFF(buf);
        const uint32_t al_base = smb + ALO_OFF(buf);
        const uint32_t wh_base = smb + WHI_OFF(buf);
        const uint32_t wl_base = smb + WLO_OFF(buf);
#pragma unroll
        for (int ks = 0; ks < 4; ks++) {
            uint32_t ah[4], al[4], bh[4], bl[4];
            {
                uint32_t off = SWZ((uint32_t)(lrowA * 128 + (ks * 2 + lkselA) * 16));
                LDSM4(ah, ah_base + off);
                LDSM4(al, al_base + off);
            }
            {
                uint32_t off = SWZ((uint32_t)((ks * 16 + lrowB) * 128 + ljB * 16));
                LDSM4T(bh, wh_base + off);
                LDSM4T(bl, wl_base + off);
            }
#pragma unroll
            for (int nt = 0; nt < 2; nt++) {
                mma16816(d[nt], ah, bh[2 * nt], bh[2 * nt + 1]);
                mma16816(d[nt], ah, bl[2 * nt], bl[2 * nt + 1]);
                mma16816(d[nt], al, bh[2 * nt], bh[2 * nt + 1]);
            }
        }
    }
#pragma unroll
    for (int nt = 0; nt < 2; nt++) {
        int r = bm + mw * 16 + (lane >> 2);
        int cc = nw * 16 + nt * 8 + 2 * (lane & 3);
        int colg = ct * 64 + cc;
        float2 v0 = make_float2(d[nt][0], d[nt][1]);
        float2 v1 = make_float2(d[nt][2], d[nt][3]);
        if (mode == 4) {
            float2 p0 = *(const float2*)(C1 + (size_t)r * 256 + colg);
            float2 p1 = *(const float2*)(C1 + (size_t)(r + 8) * 256 + colg);
            v0.x = tanhf(v0.x + p0.x); v0.y = tanhf(v0.y + p0.y);
            v1.x = tanhf(v1.x + p1.x); v1.y = tanhf(v1.y + p1.y);
            *(float2*)(C0 + (size_t)r * 256 + colg) = v0;
            *(float2*)(C0 + (size_t)(r + 8) * 256 + colg) = v1;
        } else if (mode == 3 && colg >= 256) {
            float b0 = bias[colg - 256], b1 = bias[colg - 255];
            v0.x += b0; v0.y += b1; v1.x += b0; v1.y += b1;
            *(float2*)(C1 + (size_t)r * 256 + colg - 256) = v0;
            *(float2*)(C1 + (size_t)(r + 8) * 256 + colg - 256) = v1;
        } else {
            *(float2*)(C0 + (size_t)r * 256 + colg) = v0;
            *(float2*)(C0 + (size_t)(r + 8) * 256 + colg) = v1;
        }
    }
    __syncthreads();
}

// =============== attention: single-pass online softmax, 2-deep pipeline ======
__device__ void attention8(TailPool* sp, int bid, const float* __restrict__ eo,
                           float* __restrict__ ctx_att) {
    const int tid = threadIdx.x, w = tid >> 5, lane = tid & 31;
    const int r8 = w >> 1, half = w & 1, b = bid * 8 + r8;
    const float* qb = g_q + b * 256;
    float4 q0 = *(const float4*)(qb + lane * 4);
    float4 q1 = *(const float4*)(qb + 128 + lane * 4);
    const float* eb = eo + (size_t)b * Lq * 256;
    float m = -1e30f, esum = 0.f;
    float4 a0 = make_float4(0, 0, 0, 0), a1 = make_float4(0, 0, 0, 0);
    const int l0 = half * 50;
    float4 c00, c01, c10, c11;
    {
        const float* p0 = eb + (size_t)l0 * 256;
        const float* p1 = eb + (size_t)(l0 + 1) * 256;
        c00 = *(const float4*)(p0 + lane * 4);
        c01 = *(const float4*)(p0 + 128 + lane * 4);
        c10 = *(const float4*)(p1 + lane * 4);
        c11 = *(const float4*)(p1 + 128 + lane * 4);
    }
#pragma unroll 5
    for (int l = l0; l < l0 + 50; l += 2) {
        float4 n00, n01, n10, n11;
        if (l + 2 < l0 + 50) {
            const float* p0 = eb + (size_t)(l + 2) * 256;
            const float* p1 = eb + (size_t)(l + 3) * 256;
            n00 = *(const float4*)(p0 + lane * 4);
            n01 = *(const float4*)(p0 + 128 + lane * 4);
            n10 = *(const float4*)(p1 + lane * 4);
            n11 = *(const float4*)(p1 + 128 + lane * 4);
        }
#pragma unroll
        for (int jj = 0; jj < 2; jj++) {
            float4 v0 = jj ? c10 : c00;
            float4 v1 = jj ? c11 : c01;
            float s = v0.x * q0.x + v0.y * q0.y + v0.z * q0.z + v0.w * q0.w
                    + v1.x * q1.x + v1.y * q1.y + v1.z * q1.z + v1.w * q1.w;
#pragma unroll
            for (int o = 16; o; o >>= 1) s += __shfl_xor_sync(0xFFFFFFFFu, s, o);
            if (s <= m) {
                float wg = __expf(s - m);
                esum += wg;
                a0.x += wg * v0.x; a0.y += wg * v0.y; a0.z += wg * v0.z; a0.w += wg * v0.w;
                a1.x += wg * v1.x; a1.y += wg * v1.y; a1.z += wg * v1.z; a1.w += wg * v1.w;
            } else {
                float r = __expf(m - s);
                esum = esum * r + 1.f;
                a0.x = a0.x * r + v0.x; a0.y = a0.y * r + v0.y;
                a0.z = a0.z * r + v0.z; a0.w = a0.w * r + v0.w;
                a1.x = a1.x * r + v1.x; a1.y = a1.y * r + v1.y;
                a1.z = a1.z * r + v1.z; a1.w = a1.w * r + v1.w;
                m = s;
            }
        }
        c00 = n00; c01 = n01; c10 = n10; c11 = n11;
    }
    if (half) {
        sp->att.m1[r8] = m; sp->att.e1[r8] = esum;
        *(float4*)&sp->att.acc[r8][lane * 4] = a0;
        *(float4*)&sp->att.acc[r8][128 + lane * 4] = a1;
    }
    __syncthreads();
    if (!half) {
        float m1 = sp->att.m1[r8], e1 = sp->att.e1[r8];
        float M = fmaxf(m, m1);
        float s0 = __expf(m - M), s1 = __expf(m1 - M);
        float inv = 1.f / (esum * s0 + e1 * s1);
        float4 p0 = *(const float4*)&sp->att.acc[r8][lane * 4];
        float4 p1 = *(const float4*)&sp->att.acc[r8][128 + lane * 4];
        float4 o0, o1;
        o0.x = (a0.x * s0 + p0.x * s1) * inv; o0.y = (a0.y * s0 + p0.y * s1) * inv;
        o0.z = (a0.z * s0 + p0.z * s1) * inv; o0.w = (a0.w * s0 + p0.w * s1) * inv;
        o1.x = (a1.x * s0 + p1.x * s1) * inv; o1.y = (a1.y * s0 + p1.y * s1) * inv;
        o1.z = (a1.z * s0 + p1.z * s1) * inv; o1.w = (a1.w * s0 + p1.w * s1) * inv;
        *(float4*)(ctx_att + b * 256 + lane * 4) = o0;
        *(float4*)(ctx_att + b * 256 + 128 + lane * 4) = o1;
    }
    __syncthreads();
}

// =============== finalize: warp-per-row (proven R5/R7) =======================
__device__ void finalize8(int bid, int t, const int* __restrict__ actions,
                          float* __restrict__ out) {
    const int w = threadIdx.x >> 5, lane = threadIdx.x & 31;
    if (w >= 8) return;
    const int b = bid * 8 + w;
    const float* lr = g_logit + b * 256;
    float4 l0 = *(const float4*)(lr + lane * 4);
    float4 l1 = *(const float4*)(lr + 128 + lane * 4);
    float m = fmaxf(fmaxf(fmaxf(l0.x, l0.y), fmaxf(l0.z, l0.w)),
                    fmaxf(fmaxf(l1.x, l1.y), fmaxf(l1.z, l1.w)));
#pragma unroll
    for (int o = 16; o; o >>= 1) m = fmaxf(m, __shfl_xor_sync(0xFFFFFFFFu, m, o));
    float4 e0 = make_float4(__expf(l0.x - m), __expf(l0.y - m), __expf(l0.z - m), __expf(l0.w - m));
    float4 e1 = make_float4(__expf(l1.x - m), __expf(l1.y - m), __expf(l1.z - m), __expf(l1.w - m));
    float s = e0.x + e0.y + e0.z + e0.w + e1.x + e1.y + e1.z + e1.w;
#pragma unroll
    for (int o = 16; o; o >>= 1) s += __shfl_xor_sync(0xFFFFFFFFu, s, o);
    float inv = 1.f / s;
    e0.x *= inv; e0.y *= inv; e0.z *= inv; e0.w *= inv;
    e1.x *= inv; e1.y *= inv; e1.z *= inv; e1.w *= inv;
    float* outl = out + (size_t)Bq * Lq + ((size_t)b * Lq + t) * 256;
    *(float4*)(outl + lane * 4) = e0;
    *(float4*)(outl + 128 + lane * 4) = e1;
    const float* Qr = g_Q + b * 256;
    float4 Q0 = *(const float4*)(Qr + lane * 4);
    float4 Q1 = *(const float4*)(Qr + 128 + lane * 4);
    float v = e0.x * Q0.x + e0.y * Q0.y + e0.z * Q0.z + e0.w * Q0.w
            + e1.x * Q1.x + e1.y * Q1.y + e1.z * Q1.z + e1.w * Q1.w;
#pragma unroll
    for (int o = 16; o; o >>= 1) v += __shfl_xor_sync(0xFFFFFFFFu, v, o);
    if (!lane) {
        out[(size_t)Bq * Lq + (size_t)Bq * Lq * 256 + b * Lq + t] = v;
        out[b * Lq + t] = (float)actions[b * Lq + t];
    }
}

// =============== persistent mega-kernel ======================================
__global__ void __launch_bounds__(NTHR, 1)
mega(const float* __restrict__ enc_out, const float* __restrict__ enc_h,
     const float* __restrict__ enc_c, const float* __restrict__ emb,
     const float* __restrict__ Wih0, const float* __restrict__ Whh0,
     const float* __restrict__ bih0, const float* __restrict__ bhh0,
     const float* __restrict__ Wih1, const float* __restrict__ Whh1,
     const float* __restrict__ bih1, const float* __restrict__ bhh1,
     const float* __restrict__ Wa, const float* __restrict__ Wconcat,
     const float* __restrict__ Wout, const float* __restrict__ Wcrit,
     const float* __restrict__ bcrit, const int* __restrict__ actions,
     float* __restrict__ out) {
    extern __shared__ char dynsm[];
    TailPool* sp = (TailPool*)dynsm;
    __shared__ int gidx[128];
    const int bid = blockIdx.x, tid = threadIdx.x;
    const uint32_t smb = smem_u32(dynsm);
    unsigned bt = 0;

    // ---- init phase 0 (identical to R12) ----
    for (int idx = bid * NTHR + tid; idx < 16 * 12 * 4096; idx += NBLK * NTHR) {
        int ct = idx / 49152, rem = idx - ct * 49152;
        int ch = rem >> 12, rr = rem & 4095;
        int k = rr >> 6, n = rr & 63;
        int np = ct * 64 + n, h = np >> 2, g = np & 3, orow = g * 256 + h;
        int kk = ch * 64 + k;
        float w = (kk < 512) ? Wih0[orow * 512 + kk] : Whh0[orow * 256 + (kk - 512)];
        __nv_bfloat16 hi = __float2bfloat16(w);
        __nv_bfloat16 lo = __float2bfloat16(w - __bfloat162float(hi));
        unsigned char* base = g_W0sw + (size_t)(ct * 12 + ch) * 16384;
        uint32_t off = SWZ((uint32_t)(k * 128 + n * 2));
        *(__nv_bfloat16*)(base + off) = hi;
        *(__nv_bfloat16*)(base + 8192 + off) = lo;
    }
    for (int idx = bid * NTHR + tid; idx < 16 * 8 * 4096; idx += NBLK * NTHR) {
        int ct = idx / 32768, rem = idx - ct * 32768;
        int ch = rem >> 12, rr = rem & 4095;
        int k = rr >> 6, n = rr & 63;
        int np = ct * 64 + n, h = np >> 2, g = np & 3, orow = g * 256 + h;
        int kk = ch * 64 + k;
        float w = (kk < 256) ? Wih1[orow * 256 + kk] : Whh1[orow * 256 + (kk - 256)];
        __nv_bfloat16 hi = __float2bfloat16(w);
        __nv_bfloat16 lo = __float2bfloat16(w - __bfloat162float(hi));
        unsigned char* base = g_W1sw + (size_t)(ct * 8 + ch) * 16384;
        uint32_t off = SWZ((uint32_t)(k * 128 + n * 2));
        *(__nv_bfloat16*)(base + off) = hi;
        *(__nv_bfloat16*)(base + 8192 + off) = lo;
    }
    for (int idx = bid * NTHR + tid; idx < 4 * 4 * 4096; idx += NBLK * NTHR) {
        int ct = idx / 16384, rem = idx - ct * 16384;
        int ch = rem >> 12, rr = rem & 4095;
        int k = rr >> 6, n = rr & 63;
        int np = ct * 64 + n, kk = ch * 64 + k;
        float w = Wa[kk * 256 + np];
        __nv_bfloat16 hi = __float2bfloat16(w);
        __nv_bfloat16 lo = __float2bfloat16(w - __bfloat162float(hi));
        unsigned char* base = g_Waw + (size_t)(ct * 4 + ch) * 16384;
        uint32_t off = SWZ((uint32_t)(k * 128 + n * 2));
        *(__nv_bfloat16*)(base + off) = hi;
        *(__nv_bfloat16*)(base + 8192 + off) = lo;
    }
    for (int idx = bid * NTHR + tid; idx < 4 * 8 * 4096; idx += NBLK * NTHR) {
        int ct = idx / 32768, rem = idx - ct * 32768;
        int ch = rem >> 12, rr = rem & 4095;
        int k = rr >> 6, n = rr & 63;
        int np = ct * 64 + n, kk = ch * 64 + k;
        float w = Wconcat[np * 512 + kk];
        __nv_bfloat16 hi = __float2bfloat16(w);
        __nv_bfloat16 lo = __float2bfloat16(w - __bfloat162float(hi));
        unsigned char* base = g_Wccw + (size_t)(ct * 8 + ch) * 16384;
        uint32_t off = SWZ((uint32_t)(k * 128 + n * 2));
        *(__nv_bfloat16*)(base + off) = hi;
        *(__nv_bfloat16*)(base + 8192 + off) = lo;
    }
    {
        int g = bid * NTHR + tid;
        int i = g >> 8, j = g & 255;
        float acc = 0.f;
        const float* wc = Wcrit + i * 256;
#pragma unroll 4
        for (int k = 0; k < 256; k++) acc += wc[k] * Wout[k * 256 + j];
        g_Wco[i * 256 + j] = acc;
    }
    for (int idx = bid * NTHR + tid; idx < 1024; idx += NBLK * NTHR) {
        int h = idx >> 2, g = idx & 3, orow = g * 256 + h;
        g_b0p[idx] = bih0[orow] + bhh0[orow];
        g_b1p[idx] = bih1[orow] + bhh1[orow];
    }
    for (int idx = bid * NTHR + tid; idx < Bq * 256; idx += NBLK * NTHR) {
        g_h0a[idx] = enc_h[idx]; g_h1a[idx] = enc_h[Bq * 256 + idx];
        g_c0[idx] = enc_c[idx];  g_c1[idx] = enc_c[Bq * 256 + idx];
        int b = idx >> 8, hh = idx & 255;
        const float* p = enc_out + (size_t)b * Lq * 256 + hh;
        float s = 0.f;
        for (int l = 0; l < Lq; l++) s += p[(size_t)l * 256];
        g_ctx[idx] = s * (1.0f / Lq);
    }
    bt += NBLK; gsync(bt);
    for (int idx = bid * NTHR + tid; idx < 8 * 4 * 4096; idx += NBLK * NTHR) {
        int ct = idx / 16384, rem = idx - ct * 16384;
        int ch = rem >> 12, rr = rem & 4095;
        int k = rr >> 6, n = rr & 63;
        int np = ct * 64 + n, kk = ch * 64 + k;
        float w = (np < 256) ? Wout[np * 256 + kk] : g_Wco[(np - 256) * 256 + kk];
        __nv_bfloat16 hi = __float2bfloat16(w);
        __nv_bfloat16 lo = __float2bfloat16(w - __bfloat162float(hi));
        unsigned char* base = g_Wskw + (size_t)(ct * 4 + ch) * 16384;
        uint32_t off = SWZ((uint32_t)(k * 128 + n * 2));
        *(__nv_bfloat16*)(base + off) = hi;
        *(__nv_bfloat16*)(base + 8192 + off) = lo;
    }
    bt += NBLK; gsync(bt);

    float *h0c = g_h0a, *h0n = g_h0b, *h1c = g_h1a, *h1n = g_h1b;
    const int bmL = (bid >> 4) * 128, ctL = bid & 15;

    for (int t = 0; t < Lq; t++) {
        // P1: LSTM0
        if (tid < 128)
            gidx[tid] = (t == 0) ? 0 : actions[(bmL + tid) * Lq + (t - 1)];
        __syncthreads();
        lstm_mma(dynsm, smb, gidx, bmL, ctL, emb, g_ctx, h0c, 12, true,
                 g_W0sw + (size_t)ctL * (12 * 16384), g_b0p, g_c0, h0n);
        bt += NBLK; gsync(bt);
        // P2: LSTM1
        lstm_mma(dynsm, smb, gidx, bmL, ctL, h0n, h1c, nullptr, 8, false,
                 g_W1sw + (size_t)ctL * (8 * 16384), g_b1p, g_c1, h1n);
        bt += NBLK; gsync(bt);
        // P3 (all 128 blocks): 0-63 q = h1@Wa; 64-127 pre = h1@Wcc1 (M=64 tiles)
        if (bid < 64) {
            mma_out64(dynsm, smb, (bid >> 2) * 64, bid & 3, h1n, 4,
                      g_Waw + (size_t)(bid & 3) * (4 * 16384), nullptr, 0, g_q, nullptr);
        } else {
            int b2 = bid - 64;
            mma_out64(dynsm, smb, (b2 >> 2) * 64, b2 & 3, h1n, 4,
                      g_Wccw + (size_t)(b2 & 3) * (8 * 16384), nullptr, 0, g_pre, nullptr);
        }
        bt += NBLK; gsync(bt);
        // P4: attention (8 rows concurrent, pipelined single pass)
        attention8(sp, bid, enc_out, g_ctx_att);
        bt += NBLK; gsync(bt);
        // P5: ctx = tanh(pre + ctx_att@Wcc2) (M=64 tiles, 64 blocks)
        if (bid < 64)
            mma_out64(dynsm, smb, (bid >> 2) * 64, bid & 3, g_ctx_att, 4,
                      g_Wccw + (size_t)(bid & 3) * (8 * 16384) + 4 * 16384,
                      nullptr, 4, g_ctx, g_pre);
        bt += NBLK; gsync(bt);
        // P6: [logit|Q] = ctx @ [Wout;Wco]^T + [0|bcrit] (M=64, all 128 blocks)
        mma_out64(dynsm, smb, (bid >> 3) * 64, bid & 7, g_ctx, 4,
                  g_Wskw + (size_t)(bid & 7) * (4 * 16384), bcrit, 3, g_logit, g_Q);
        bt += NBLK; gsync(bt);
        // P7: finalize (warp-per-row, no barriers)
        finalize8(bid, t, actions, out);
        float* tmp = h0c; h0c = h0n; h0n = tmp;
        tmp = h1c; h1c = h1n; h1n = tmp;
    }
}

__global__ void reset_k() { g_count = 0; }

// ---------------- host ----------------
extern "C" void kernel_launch(void* const* d_in, const int* in_sizes, int n_in,
                              void* d_out, int out_size) {
    const float* enc_out = (const float*)d_in[0];
    const float* enc_h   = (const float*)d_in[1];
    const float* enc_c   = (const float*)d_in[2];
    const float* emb     = (const float*)d_in[3];
    const float* Wih0    = (const float*)d_in[4];
    const float* Whh0    = (const float*)d_in[5];
    const float* bih0    = (const float*)d_in[6];
    const float* bhh0    = (const float*)d_in[7];
    const float* Wih1    = (const float*)d_in[8];
    const float* Whh1    = (const float*)d_in[9];
    const float* bih1    = (const float*)d_in[10];
    const float* bhh1    = (const float*)d_in[11];
    const float* Wa      = (const float*)d_in[12];
    const float* Wconcat = (const float*)d_in[13];
    const float* Wout    = (const float*)d_in[14];
    const float* Wcrit   = (const float*)d_in[15];
    const float* bcrit   = (const float*)d_in[16];
    const int*   actions = (const int*)d_in[17];
    float* out = (float*)d_out;

    cudaFuncSetAttribute(mega, cudaFuncAttributeMaxDynamicSharedMemorySize, SMEM_TOTAL);
    reset_k<<<1, 1>>>();
    mega<<<NBLK, NTHR, SMEM_TOTAL>>>(enc_out, enc_h, enc_c, emb,
                                     Wih0, Whh0, bih0, bhh0,
                                     Wih1, Whh1, bih1, bhh1,
                                     Wa, Wconcat, Wout, Wcrit, bcrit, actions, out);
}

// round 14
// speedup vs baseline: 2.8680x; 1.1109x over previous
#include <cuda_runtime.h>
#include <cuda_bf16.h>
#include <cstdint>

#define Bq 1024
#define Lq 100
#define NBLK 128
#define NTHR 512

typedef unsigned long long u64;
typedef __nv_bfloat16 bf16;

// ---------------- static scratch ----------------
__device__ __align__(16) unsigned char g_W0sw[16 * 12 * 16384];  // 3 MB
__device__ __align__(16) unsigned char g_W1sw[16 * 8 * 16384];   // 2 MB
__device__ __align__(16) unsigned char g_Waw[4 * 4 * 16384];
__device__ __align__(16) unsigned char g_Wccw[4 * 8 * 16384];
__device__ __align__(16) unsigned char g_Wskw[8 * 4 * 16384];
__device__ float g_Wco[256 * 256];
__device__ float g_b0p[1024], g_b1p[1024];
// bf16 hi/lo activation images
__device__ __align__(16) bf16 g_embh[256 * 256], g_embl[256 * 256];
__device__ __align__(16) bf16 g_ctxh[Bq * 256], g_ctxl[Bq * 256];
__device__ __align__(16) bf16 g_h0ah[Bq * 256], g_h0al[Bq * 256];
__device__ __align__(16) bf16 g_h0bh[Bq * 256], g_h0bl[Bq * 256];
__device__ __align__(16) bf16 g_h1ah[Bq * 256], g_h1al[Bq * 256];
__device__ __align__(16) bf16 g_h1bh[Bq * 256], g_h1bl[Bq * 256];
__device__ __align__(16) bf16 g_cah[Bq * 256], g_cal[Bq * 256];
__device__ float g_c0[Bq * 256], g_c1[Bq * 256];
__device__ float g_q[Bq * 256], g_pre[Bq * 256];
__device__ float g_logit[Bq * 256], g_Q[Bq * 256];
__device__ unsigned g_count;

// ---------------- smem layout ----------------
#define AHI_OFF(b) ((b) * 32768)
#define ALO_OFF(b) (AHI_OFF(b) + 16384)
#define WHI_OFF(b) (65536 + (b) * 16384)
#define WLO_OFF(b) (WHI_OFF(b) + 8192)
#define SMEM_TOTAL 106496

#define SWZ(x) ((x) ^ (((x) >> 3) & 0x70))

__device__ __forceinline__ float sigm(float x) { return 1.f / (1.f + __expf(-x)); }

// ---------------- primitives ----------------
__device__ __forceinline__ uint32_t smem_u32(const void* p) {
    uint32_t a;
    asm("{ .reg .u64 t; cvta.to.shared.u64 t, %1; cvt.u32.u64 %0, t; }"
        : "=r"(a) : "l"(p));
    return a;
}
#define LDSM4(r, a) asm volatile( \
    "ldmatrix.sync.aligned.m8n8.x4.shared.b16 {%0,%1,%2,%3}, [%4];" \
    : "=r"((r)[0]), "=r"((r)[1]), "=r"((r)[2]), "=r"((r)[3]) : "r"(a))
#define LDSM4T(r, a) asm volatile( \
    "ldmatrix.sync.aligned.m8n8.x4.trans.shared.b16 {%0,%1,%2,%3}, [%4];" \
    : "=r"((r)[0]), "=r"((r)[1]), "=r"((r)[2]), "=r"((r)[3]) : "r"(a))
__device__ __forceinline__ void mma16816(float* d, const uint32_t* a,
                                         uint32_t b0, uint32_t b1) {
    asm volatile("mma.sync.aligned.m16n8k16.row.col.f32.bf16.bf16.f32 "
                 "{%0,%1,%2,%3}, {%4,%5,%6,%7}, {%8,%9}, {%0,%1,%2,%3};"
                 : "+f"(d[0]), "+f"(d[1]), "+f"(d[2]), "+f"(d[3])
                 : "r"(a[0]), "r"(a[1]), "r"(a[2]), "r"(a[3]), "r"(b0), "r"(b1));
}
__device__ __forceinline__ uint32_t pkbf(float a, float b) {
    uint16_t ua = __bfloat16_as_ushort(__float2bfloat16(a));
    uint16_t ub = __bfloat16_as_ushort(__float2bfloat16(b));
    return (uint32_t)ua | ((uint32_t)ub << 16);
}
// split two floats into packed-hi u32 and packed-lo u32
__device__ __forceinline__ void split2(float a, float b, uint32_t& h, uint32_t& l) {
    bf16 ha = __float2bfloat16(a), hb = __float2bfloat16(b);
    h = (uint32_t)__bfloat16_as_ushort(ha) | ((uint32_t)__bfloat16_as_ushort(hb) << 16);
    l = pkbf(a - __bfloat162float(ha), b - __bfloat162float(hb));
}
__device__ __forceinline__ void split1(float a, bf16* ph, bf16* pl) {
    bf16 h = __float2bfloat16(a);
    *ph = h;
    *pl = __float2bfloat16(a - __bfloat162float(h));
}

// ---------------- grid barrier ----------------
__device__ __forceinline__ void gsync(unsigned target) {
    __syncthreads();
    if (threadIdx.x == 0) {
        unsigned o;
        asm volatile("atom.add.release.gpu.u32 %0, [%1], 1;"
                     : "=r"(o) : "l"(&g_count) : "memory");
        unsigned cur;
        do {
            asm volatile("ld.acquire.gpu.u32 %0, [%1];"
                         : "=r"(cur) : "l"(&g_count) : "memory");
        } while ((int)(cur - target) < 0);
    }
    __syncthreads();
}

// ---------------- tail pool ----------------
struct TailPool {
    struct { float acc[8][256]; float m1[8], e1[8]; } att;
};

// =============== LSTM via mma.sync bf16-split, image A-operands ==============
__device__ void lstm_mma(char* sm, uint32_t smb, const int* gidx, int bm, int ct,
                         const bf16* A0h, const bf16* A0l,
                         const bf16* A1h, const bf16* A1l,
                         const bf16* A2h, const bf16* A2l,
                         int nch, bool gather,
                         const unsigned char* __restrict__ Wsw,
                         const float* __restrict__ bias,
                         float* __restrict__ cst,
                         bf16* __restrict__ houth, bf16* __restrict__ houtl) {
    const int tid = threadIdx.x;
    const int warp = tid >> 5, lane = tid & 31;
    const int mw = warp & 3, nw = warp >> 2;
    const int row = tid >> 2, q = tid & 3;

    float d[2][2][4];
#pragma unroll
    for (int mt = 0; mt < 2; mt++)
#pragma unroll
        for (int nt = 0; nt < 2; nt++)
#pragma unroll
            for (int e = 0; e < 4; e++) d[mt][nt][e] = 0.f;

    const int lrowA = mw * 32 + (lane & 15);
    const int lkselA = (lane >> 4);
    const int lrowB = (lane & 15);
    const int ljB = nw * 2 + (lane >> 4);

    uint4 vh0, vh1, vl0, vl1, w0, w1;
    {   // prefetch chunk 0
        const bf16* Ah = A0h; const bf16* Al = A0l;
        int ri = gather ? gidx[row] : (bm + row);
        const uint4* ph = (const uint4*)(Ah + (size_t)ri * 256 + q * 16);
        const uint4* pl = (const uint4*)(Al + (size_t)ri * 256 + q * 16);
        vh0 = ph[0]; vh1 = ph[1]; vl0 = pl[0]; vl1 = pl[1];
        const uint4* wsrc = (const uint4*)Wsw;
        w0 = wsrc[tid]; w1 = wsrc[512 + tid];
    }

    for (int c = 0; c < nch; c++) {
        const int buf = c & 1;
        {
            uint32_t b0 = row * 128 + q * 32;
            uint32_t s0 = SWZ(b0), s1 = SWZ(b0 + 16);
            *(uint4*)(sm + AHI_OFF(buf) + s0) = vh0;
            *(uint4*)(sm + AHI_OFF(buf) + s1) = vh1;
            *(uint4*)(sm + ALO_OFF(buf) + s0) = vl0;
            *(uint4*)(sm + ALO_OFF(buf) + s1) = vl1;
            *(uint4*)(sm + WHI_OFF(buf) + tid * 16) = w0;
            *(uint4*)(sm + WLO_OFF(buf) + tid * 16) = w1;
        }
        __syncthreads();
        if (c + 1 < nch) {
            int cn = c + 1;
            int seg = cn >> 2;
            int kc = ((cn & 3) * 64) + q * 16;
            const bf16* Ah = (seg == 0) ? A0h : (seg == 1 ? A1h : A2h);
            const bf16* Al = (seg == 0) ? A0l : (seg == 1 ? A1l : A2l);
            int ri = (gather && seg == 0) ? gidx[row] : (bm + row);
            const uint4* ph = (const uint4*)(Ah + (size_t)ri * 256 + kc);
            const uint4* pl = (const uint4*)(Al + (size_t)ri * 256 + kc);
            vh0 = ph[0]; vh1 = ph[1]; vl0 = pl[0]; vl1 = pl[1];
            const uint4* wsrc = (const uint4*)(Wsw + (size_t)cn * 16384);
            w0 = wsrc[tid]; w1 = wsrc[512 + tid];
        }
        const uint32_t ah_base = smb + AHI_OFF(buf);
        const uint32_t al_base = smb + ALO_OFF(buf);
        const uint32_t wh_base = smb + WHI_OFF(buf);
        const uint32_t wl_base = smb + WLO_OFF(buf);
#pragma unroll
        for (int ks = 0; ks < 4; ks++) {
            uint32_t ah[2][4], al[2][4], bh[4], bl[4];
#pragma unroll
            for (int mt = 0; mt < 2; mt++) {
                uint32_t off = SWZ((uint32_t)((lrowA + mt * 16) * 128
                                              + (ks * 2 + lkselA) * 16));
                LDSM4(ah[mt], ah_base + off);
                LDSM4(al[mt], al_base + off);
            }
            {
                uint32_t off = SWZ((uint32_t)((ks * 16 + lrowB) * 128 + ljB * 16));
                LDSM4T(bh, wh_base + off);
                LDSM4T(bl, wl_base + off);
            }
#pragma unroll
            for (int mt = 0; mt < 2; mt++)
#pragma unroll
                for (int nt = 0; nt < 2; nt++) {
                    mma16816(d[mt][nt], ah[mt], bh[2 * nt], bh[2 * nt + 1]);
                    mma16816(d[mt][nt], ah[mt], bl[2 * nt], bl[2 * nt + 1]);
                    mma16816(d[mt][nt], al[mt], bh[2 * nt], bh[2 * nt + 1]);
                }
        }
    }
    {
        float* Dsm = (float*)sm;
#pragma unroll
        for (int mt = 0; mt < 2; mt++) {
            int r = mw * 32 + mt * 16 + (lane >> 2);
#pragma unroll
            for (int nt = 0; nt < 2; nt++) {
                int cc = nw * 16 + nt * 8 + 2 * (lane & 3);
                *(float2*)(Dsm + r * 64 + cc) = make_float2(d[mt][nt][0], d[mt][nt][1]);
                *(float2*)(Dsm + (r + 8) * 64 + cc) = make_float2(d[mt][nt][2], d[mt][nt][3]);
            }
        }
    }
    __syncthreads();
    {
        const float* Dsm = (const float*)sm;
#pragma unroll
        for (int i = 0; i < 4; i++) {
            int e = tid + i * 512;
            int r = e >> 4, hl = e & 15;
            float4 g4 = *(const float4*)(Dsm + r * 64 + hl * 4);
            int nb = ct * 64 + hl * 4;
            float gi = g4.x + bias[nb + 0];
            float gf = g4.y + bias[nb + 1];
            float gg = g4.z + bias[nb + 2];
            float go = g4.w + bias[nb + 3];
            float I = sigm(gi), F = sigm(gf);
            float G = tanhf(gg), Og = sigm(go);
            int idx = (bm + r) * 256 + ct * 16 + hl;
            float cn = F * cst[idx] + I * G;
            cst[idx] = cn;
            split1(Og * tanhf(cn), houth + idx, houtl + idx);
        }
    }
    __syncthreads();
}

// =============== mma GEMM tile M=64 x N=64, image A-operands =================
// mode 0: store C0 fp32; 3: stacked (col<256->C0, else C1+bias);
// mode 4: tanh(D + C1) -> Ch/Cl bf16 images
__device__ void mma_out64(char* sm, uint32_t smb, int bm, int ct,
                          const bf16* Ah, const bf16* Al, int nch,
                          const unsigned char* __restrict__ Wsw,
                          const float* __restrict__ bias, int mode,
                          float* __restrict__ C0, float* __restrict__ C1,
                          bf16* __restrict__ Ch, bf16* __restrict__ Cl) {
    const int tid = threadIdx.x;
    const int warp = tid >> 5, lane = tid & 31;
    const int mw = warp & 3, nw = warp >> 2;
    const int row = tid >> 3, qq = tid & 7;

    float d[2][4];
#pragma unroll
    for (int nt = 0; nt < 2; nt++)
#pragma unroll
        for (int e = 0; e < 4; e++) d[nt][e] = 0.f;

    const int lrowA = mw * 16 + (lane & 15);
    const int lkselA = (lane >> 4);
    const int lrowB = (lane & 15);
    const int ljB = nw * 2 + (lane >> 4);

    uint4 vh, vl, w0, w1;
    {
        const uint4* ph = (const uint4*)(Ah + (size_t)(bm + row) * 256 + qq * 8);
        const uint4* pl = (const uint4*)(Al + (size_t)(bm + row) * 256 + qq * 8);
        vh = ph[0]; vl = pl[0];
        const uint4* wsrc = (const uint4*)Wsw;
        w0 = wsrc[tid]; w1 = wsrc[512 + tid];
    }

    for (int c = 0; c < nch; c++) {
        const int buf = c & 1;
        {
            uint32_t s0 = SWZ((uint32_t)(row * 128 + qq * 16));
            *(uint4*)(sm + AHI_OFF(buf) + s0) = vh;
            *(uint4*)(sm + ALO_OFF(buf) + s0) = vl;
            *(uint4*)(sm + WHI_OFF(buf) + tid * 16) = w0;
            *(uint4*)(sm + WLO_OFF(buf) + tid * 16) = w1;
        }
        __syncthreads();
        if (c + 1 < nch) {
            int cn = c + 1;
            int kc = cn * 64 + qq * 8;
            const uint4* ph = (const uint4*)(Ah + (size_t)(bm + row) * 256 + kc);
            const uint4* pl = (const uint4*)(Al + (size_t)(bm + row) * 256 + kc);
            vh = ph[0]; vl = pl[0];
            const uint4* wsrc = (const uint4*)(Wsw + (size_t)cn * 16384);
            w0 = wsrc[tid]; w1 = wsrc[512 + tid];
        }
        const uint32_t ah_base = smb + AHI_OFF(buf);
        const uint32_t al_base = smb + ALO_OFF(buf);
        const uint32_t wh_base = smb + WHI_OFF(buf);
        const uint32_t wl_base = smb + WLO_OFF(buf);
#pragma unroll
        for (int ks = 0; ks < 4; ks++) {
            uint32_t ah[4], al[4], bh[4], bl[4];
            {
                uint32_t off = SWZ((uint32_t)(lrowA * 128 + (ks * 2 + lkselA) * 16));
                LDSM4(ah, ah_base + off);
                LDSM4(al, al_base + off);
            }
            {
                uint32_t off = SWZ((uint32_t)((ks * 16 + lrowB) * 128 + ljB * 16));
                LDSM4T(bh, wh_base + off);
                LDSM4T(bl, wl_base + off);
            }
#pragma unroll
            for (int nt = 0; nt < 2; nt++) {
                mma16816(d[nt], ah, bh[2 * nt], bh[2 * nt + 1]);
                mma16816(d[nt], ah, bl[2 * nt], bl[2 * nt + 1]);
                mma16816(d[nt], al, bh[2 * nt], bh[2 * nt + 1]);
            }
        }
    }
#pragma unroll
    for (int nt = 0; nt < 2; nt++) {
        int r = bm + mw * 16 + (lane >> 2);
        int cc = nw * 16 + nt * 8 + 2 * (lane & 3);
        int colg = ct * 64 + cc;
        float2 v0 = make_float2(d[nt][0], d[nt][1]);
        float2 v1 = make_float2(d[nt][2], d[nt][3]);
        if (mode == 4) {
            float2 p0 = *(const float2*)(C1 + (size_t)r * 256 + colg);
            float2 p1 = *(const float2*)(C1 + (size_t)(r + 8) * 256 + colg);
            float t0 = tanhf(v0.x + p0.x), t1 = tanhf(v0.y + p0.y);
            float t2 = tanhf(v1.x + p1.x), t3 = tanhf(v1.y + p1.y);
            uint32_t h, l;
            split2(t0, t1, h, l);
            *(uint32_t*)(Ch + (size_t)r * 256 + colg) = h;
            *(uint32_t*)(Cl + (size_t)r * 256 + colg) = l;
            split2(t2, t3, h, l);
            *(uint32_t*)(Ch + (size_t)(r + 8) * 256 + colg) = h;
            *(uint32_t*)(Cl + (size_t)(r + 8) * 256 + colg) = l;
        } else if (mode == 3 && colg >= 256) {
            float b0 = bias[colg - 256], b1 = bias[colg - 255];
            v0.x += b0; v0.y += b1; v1.x += b0; v1.y += b1;
            *(float2*)(C1 + (size_t)r * 256 + colg - 256) = v0;
            *(float2*)(C1 + (size_t)(r + 8) * 256 + colg - 256) = v1;
        } else {
            *(float2*)(C0 + (size_t)r * 256 + colg) = v0;
            *(float2*)(C0 + (size_t)(r + 8) * 256 + colg) = v1;
        }
    }
    __syncthreads();
}

// =============== attention: single-pass online softmax, pipelined ============
__device__ void attention8(TailPool* sp, int bid, const float* __restrict__ eo) {
    const int tid = threadIdx.x, w = tid >> 5, lane = tid & 31;
    const int r8 = w >> 1, half = w & 1, b = bid * 8 + r8;
    const float* qb = g_q + b * 256;
    float4 q0 = *(const float4*)(qb + lane * 4);
    float4 q1 = *(const float4*)(qb + 128 + lane * 4);
    const float* eb = eo + (size_t)b * Lq * 256;
    float m = -1e30f, esum = 0.f;
    float4 a0 = make_float4(0, 0, 0, 0), a1 = make_float4(0, 0, 0, 0);
    const int l0 = half * 50;
    float4 c00, c01, c10, c11;
    {
        const float* p0 = eb + (size_t)l0 * 256;
        const float* p1 = eb + (size_t)(l0 + 1) * 256;
        c00 = *(const float4*)(p0 + lane * 4);
        c01 = *(const float4*)(p0 + 128 + lane * 4);
        c10 = *(const float4*)(p1 + lane * 4);
        c11 = *(const float4*)(p1 + 128 + lane * 4);
    }
#pragma unroll 5
    for (int l = l0; l < l0 + 50; l += 2) {
        float4 n00, n01, n10, n11;
        if (l + 2 < l0 + 50) {
            const float* p0 = eb + (size_t)(l + 2) * 256;
            const float* p1 = eb + (size_t)(l + 3) * 256;
            n00 = *(const float4*)(p0 + lane * 4);
            n01 = *(const float4*)(p0 + 128 + lane * 4);
            n10 = *(const float4*)(p1 + lane * 4);
            n11 = *(const float4*)(p1 + 128 + lane * 4);
        }
#pragma unroll
        for (int jj = 0; jj < 2; jj++) {
            float4 v0 = jj ? c10 : c00;
            float4 v1 = jj ? c11 : c01;
            float s = v0.x * q0.x + v0.y * q0.y + v0.z * q0.z + v0.w * q0.w
                    + v1.x * q1.x + v1.y * q1.y + v1.z * q1.z + v1.w * q1.w;
#pragma unroll
            for (int o = 16; o; o >>= 1) s += __shfl_xor_sync(0xFFFFFFFFu, s, o);
            if (s <= m) {
                float wg = __expf(s - m);
                esum += wg;
                a0.x += wg * v0.x; a0.y += wg * v0.y; a0.z += wg * v0.z; a0.w += wg * v0.w;
                a1.x += wg * v1.x; a1.y += wg * v1.y; a1.z += wg * v1.z; a1.w += wg * v1.w;
            } else {
                float r = __expf(m - s);
                esum = esum * r + 1.f;
                a0.x = a0.x * r + v0.x; a0.y = a0.y * r + v0.y;
                a0.z = a0.z * r + v0.z; a0.w = a0.w * r + v0.w;
                a1.x = a1.x * r + v1.x; a1.y = a1.y * r + v1.y;
                a1.z = a1.z * r + v1.z; a1.w = a1.w * r + v1.w;
                m = s;
            }
        }
        c00 = n00; c01 = n01; c10 = n10; c11 = n11;
    }
    if (half) {
        sp->att.m1[r8] = m; sp->att.e1[r8] = esum;
        *(float4*)&sp->att.acc[r8][lane * 4] = a0;
        *(float4*)&sp->att.acc[r8][128 + lane * 4] = a1;
    }
    __syncthreads();
    if (!half) {
        float m1 = sp->att.m1[r8], e1 = sp->att.e1[r8];
        float M = fmaxf(m, m1);
        float s0 = __expf(m - M), s1 = __expf(m1 - M);
        float inv = 1.f / (esum * s0 + e1 * s1);
        float o[8];
        float4 p0 = *(const float4*)&sp->att.acc[r8][lane * 4];
        float4 p1 = *(const float4*)&sp->att.acc[r8][128 + lane * 4];
        o[0] = (a0.x * s0 + p0.x * s1) * inv; o[1] = (a0.y * s0 + p0.y * s1) * inv;
        o[2] = (a0.z * s0 + p0.z * s1) * inv; o[3] = (a0.w * s0 + p0.w * s1) * inv;
        o[4] = (a1.x * s0 + p1.x * s1) * inv; o[5] = (a1.y * s0 + p1.y * s1) * inv;
        o[6] = (a1.z * s0 + p1.z * s1) * inv; o[7] = (a1.w * s0 + p1.w * s1) * inv;
        uint32_t h0, l0p, h1, l1;
        split2(o[0], o[1], h0, l0p); split2(o[2], o[3], h1, l1);
        *(uint2*)(g_cah + b * 256 + lane * 4) = make_uint2(h0, h1);
        *(uint2*)(g_cal + b * 256 + lane * 4) = make_uint2(l0p, l1);
        split2(o[4], o[5], h0, l0p); split2(o[6], o[7], h1, l1);
        *(uint2*)(g_cah + b * 256 + 128 + lane * 4) = make_uint2(h0, h1);
        *(uint2*)(g_cal + b * 256 + 128 + lane * 4) = make_uint2(l0p, l1);
    }
    __syncthreads();
}

// =============== finalize: warp-per-row ======================================
__device__ void finalize8(int bid, int t, const int* __restrict__ actions,
                          float* __restrict__ out) {
    const int w = threadIdx.x >> 5, lane = threadIdx.x & 31;
    if (w >= 8) return;
    const int b = bid * 8 + w;
    const float* lr = g_logit + b * 256;
    float4 l0 = *(const float4*)(lr + lane * 4);
    float4 l1 = *(const float4*)(lr + 128 + lane * 4);
    float m = fmaxf(fmaxf(fmaxf(l0.x, l0.y), fmaxf(l0.z, l0.w)),
                    fmaxf(fmaxf(l1.x, l1.y), fmaxf(l1.z, l1.w)));
#pragma unroll
    for (int o = 16; o; o >>= 1) m = fmaxf(m, __shfl_xor_sync(0xFFFFFFFFu, m, o));
    float4 e0 = make_float4(__expf(l0.x - m), __expf(l0.y - m), __expf(l0.z - m), __expf(l0.w - m));
    float4 e1 = make_float4(__expf(l1.x - m), __expf(l1.y - m), __expf(l1.z - m), __expf(l1.w - m));
    float s = e0.x + e0.y + e0.z + e0.w + e1.x + e1.y + e1.z + e1.w;
#pragma unroll
    for (int o = 16; o; o >>= 1) s += __shfl_xor_sync(0xFFFFFFFFu, s, o);
    float inv = 1.f / s;
    e0.x *= inv; e0.y *= inv; e0.z *= inv; e0.w *= inv;
    e1.x *= inv; e1.y *= inv; e1.z *= inv; e1.w *= inv;
    float* outl = out + (size_t)Bq * Lq + ((size_t)b * Lq + t) * 256;
    *(float4*)(outl + lane * 4) = e0;
    *(float4*)(outl + 128 + lane * 4) = e1;
    const float* Qr = g_Q + b * 256;
    float4 Q0 = *(const float4*)(Qr + lane * 4);
    float4 Q1 = *(const float4*)(Qr + 128 + lane * 4);
    float v = e0.x * Q0.x + e0.y * Q0.y + e0.z * Q0.z + e0.w * Q0.w
            + e1.x * Q1.x + e1.y * Q1.y + e1.z * Q1.z + e1.w * Q1.w;
#pragma unroll
    for (int o = 16; o; o >>= 1) v += __shfl_xor_sync(0xFFFFFFFFu, v, o);
    if (!lane) {
        out[(size_t)Bq * Lq + (size_t)Bq * Lq * 256 + b * Lq + t] = v;
        out[b * Lq + t] = (float)actions[b * Lq + t];
    }
}

// =============== persistent mega-kernel ======================================
__global__ void __launch_bounds__(NTHR, 1)
mega(const float* __restrict__ enc_out, const float* __restrict__ enc_h,
     const float* __restrict__ enc_c, const float* __restrict__ emb,
     const float* __restrict__ Wih0, const float* __restrict__ Whh0,
     const float* __restrict__ bih0, const float* __restrict__ bhh0,
     const float* __restrict__ Wih1, const float* __restrict__ Whh1,
     const float* __restrict__ bih1, const float* __restrict__ bhh1,
     const float* __restrict__ Wa, const float* __restrict__ Wconcat,
     const float* __restrict__ Wout, const float* __restrict__ Wcrit,
     const float* __restrict__ bcrit, const int* __restrict__ actions,
     float* __restrict__ out) {
    extern __shared__ char dynsm[];
    TailPool* sp = (TailPool*)dynsm;
    __shared__ int gidx[128];
    const int bid = blockIdx.x, tid = threadIdx.x;
    const uint32_t smb = smem_u32(dynsm);
    unsigned bt = 0;

    // ---- init: weight images (as R13) + activation images ----
    for (int idx = bid * NTHR + tid; idx < 16 * 12 * 4096; idx += NBLK * NTHR) {
        int ct = idx / 49152, rem = idx - ct * 49152;
        int ch = rem >> 12, rr = rem & 4095;
        int k = rr >> 6, n = rr & 63;
        int np = ct * 64 + n, h = np >> 2, g = np & 3, orow = g * 256 + h;
        int kk = ch * 64 + k;
        float w = (kk < 512) ? Wih0[orow * 512 + kk] : Whh0[orow * 256 + (kk - 512)];
        bf16 hi = __float2bfloat16(w);
        bf16 lo = __float2bfloat16(w - __bfloat162float(hi));
        unsigned char* base = g_W0sw + (size_t)(ct * 12 + ch) * 16384;
        uint32_t off = SWZ((uint32_t)(k * 128 + n * 2));
        *(bf16*)(base + off) = hi;
        *(bf16*)(base + 8192 + off) = lo;
    }
    for (int idx = bid * NTHR + tid; idx < 16 * 8 * 4096; idx += NBLK * NTHR) {
        int ct = idx / 32768, rem = idx - ct * 32768;
        int ch = rem >> 12, rr = rem & 4095;
        int k = rr >> 6, n = rr & 63;
        int np = ct * 64 + n, h = np >> 2, g = np & 3, orow = g * 256 + h;
        int kk = ch * 64 + k;
        float w = (kk < 256) ? Wih1[orow * 256 + kk] : Whh1[orow * 256 + (kk - 256)];
        bf16 hi = __float2bfloat16(w);
        bf16 lo = __float2bfloat16(w - __bfloat162float(hi));
        unsigned char* base = g_W1sw + (size_t)(ct * 8 + ch) * 16384;
        uint32_t off = SWZ((uint32_t)(k * 128 + n * 2));
        *(bf16*)(base + off) = hi;
        *(bf16*)(base + 8192 + off) = lo;
    }
    for (int idx = bid * NTHR + tid; idx < 4 * 4 * 4096; idx += NBLK * NTHR) {
        int ct = idx / 16384, rem = idx - ct * 16384;
        int ch = rem >> 12, rr = rem & 4095;
        int k = rr >> 6, n = rr & 63;
        int np = ct * 64 + n, kk = ch * 64 + k;
        float w = Wa[kk * 256 + np];
        bf16 hi = __float2bfloat16(w);
        bf16 lo = __float2bfloat16(w - __bfloat162float(hi));
        unsigned char* base = g_Waw + (size_t)(ct * 4 + ch) * 16384;
        uint32_t off = SWZ((uint32_t)(k * 128 + n * 2));
        *(bf16*)(base + off) = hi;
        *(bf16*)(base + 8192 + off) = lo;
    }
    for (int idx = bid * NTHR + tid; idx < 4 * 8 * 4096; idx += NBLK * NTHR) {
        int ct = idx / 32768, rem = idx - ct * 32768;
        int ch = rem >> 12, rr = rem & 4095;
        int k = rr >> 6, n = rr & 63;
        int np = ct * 64 + n, kk = ch * 64 + k;
        float w = Wconcat[np * 512 + kk];
        bf16 hi = __float2bfloat16(w);
        bf16 lo = __float2bfloat16(w - __bfloat162float(hi));
        unsigned char* base = g_Wccw + (size_t)(ct * 8 + ch) * 16384;
        uint32_t off = SWZ((uint32_t)(k * 128 + n * 2));
        *(bf16*)(base + off) = hi;
        *(bf16*)(base + 8192 + off) = lo;
    }
    {
        int g = bid * NTHR + tid;
        int i = g >> 8, j = g & 255;
        float acc = 0.f;
        const float* wc = Wcrit + i * 256;
#pragma unroll 4
        for (int k = 0; k < 256; k++) acc += wc[k] * Wout[k * 256 + j];
        g_Wco[i * 256 + j] = acc;
    }
    for (int idx = bid * NTHR + tid; idx < 1024; idx += NBLK * NTHR) {
        int h = idx >> 2, g = idx & 3, orow = g * 256 + h;
        g_b0p[idx] = bih0[orow] + bhh0[orow];
        g_b1p[idx] = bih1[orow] + bhh1[orow];
    }
    for (int idx = bid * NTHR + tid; idx < 65536; idx += NBLK * NTHR)
        split1(emb[idx], g_embh + idx, g_embl + idx);
    for (int idx = bid * NTHR + tid; idx < Bq * 256; idx += NBLK * NTHR) {
        split1(enc_h[idx], g_h0ah + idx, g_h0al + idx);
        split1(enc_h[Bq * 256 + idx], g_h1ah + idx, g_h1al + idx);
        g_c0[idx] = enc_c[idx];
        g_c1[idx] = enc_c[Bq * 256 + idx];
        int b = idx >> 8, hh = idx & 255;
        const float* p = enc_out + (size_t)b * Lq * 256 + hh;
        float s = 0.f;
        for (int l = 0; l < Lq; l++) s += p[(size_t)l * 256];
        split1(s * (1.0f / Lq), g_ctxh + idx, g_ctxl + idx);
    }
    bt += NBLK; gsync(bt);
    for (int idx = bid * NTHR + tid; idx < 8 * 4 * 4096; idx += NBLK * NTHR) {
        int ct = idx / 16384, rem = idx - ct * 16384;
        int ch = rem >> 12, rr = rem & 4095;
        int k = rr >> 6, n = rr & 63;
        int np = ct * 64 + n, kk = ch * 64 + k;
        float w = (np < 256) ? Wout[np * 256 + kk] : g_Wco[(np - 256) * 256 + kk];
        bf16 hi = __float2bfloat16(w);
        bf16 lo = __float2bfloat16(w - __bfloat162float(hi));
        unsigned char* base = g_Wskw + (size_t)(ct * 4 + ch) * 16384;
        uint32_t off = SWZ((uint32_t)(k * 128 + n * 2));
        *(bf16*)(base + off) = hi;
        *(bf16*)(base + 8192 + off) = lo;
    }
    bt += NBLK; gsync(bt);

    bf16 *h0ch = g_h0ah, *h0cl = g_h0al, *h0nh = g_h0bh, *h0nl = g_h0bl;
    bf16 *h1ch = g_h1ah, *h1cl = g_h1al, *h1nh = g_h1bh, *h1nl = g_h1bl;
    const int bmL = (bid >> 4) * 128, ctL = bid & 15;

    for (int t = 0; t < Lq; t++) {
        // P1: LSTM0 [emb(gather) | ctx | h0]
        if (tid < 128)
            gidx[tid] = (t == 0) ? 0 : actions[(bmL + tid) * Lq + (t - 1)];
        __syncthreads();
        lstm_mma(dynsm, smb, gidx, bmL, ctL,
                 g_embh, g_embl, g_ctxh, g_ctxl, h0ch, h0cl, 12, true,
                 g_W0sw + (size_t)ctL * (12 * 16384), g_b0p, g_c0, h0nh, h0nl);
        bt += NBLK; gsync(bt);
        // P2: LSTM1 [h0n | h1c]
        lstm_mma(dynsm, smb, gidx, bmL, ctL,
                 h0nh, h0nl, h1ch, h1cl, nullptr, nullptr, 8, false,
                 g_W1sw + (size_t)ctL * (8 * 16384), g_b1p, g_c1, h1nh, h1nl);
        bt += NBLK; gsync(bt);
        // P3: 0-63 q = h1@Wa; 64-127 pre = h1@Wcc1
        if (bid < 64) {
            mma_out64(dynsm, smb, (bid >> 2) * 64, bid & 3, h1nh, h1nl, 4,
                      g_Waw + (size_t)(bid & 3) * (4 * 16384), nullptr, 0,
                      g_q, nullptr, nullptr, nullptr);
        } else {
            int b2 = bid - 64;
            mma_out64(dynsm, smb, (b2 >> 2) * 64, b2 & 3, h1nh, h1nl, 4,
                      g_Wccw + (size_t)(b2 & 3) * (8 * 16384), nullptr, 0,
                      g_pre, nullptr, nullptr, nullptr);
        }
        bt += NBLK; gsync(bt);
        // P4: attention -> ctx_att images
        attention8(sp, bid, enc_out);
        bt += NBLK; gsync(bt);
        // P5: ctx = tanh(pre + ctx_att@Wcc2) -> ctx images
        if (bid < 64)
            mma_out64(dynsm, smb, (bid >> 2) * 64, bid & 3, g_cah, g_cal, 4,
                      g_Wccw + (size_t)(bid & 3) * (8 * 16384) + 4 * 16384,
                      nullptr, 4, nullptr, g_pre, g_ctxh, g_ctxl);
        bt += NBLK; gsync(bt);
        // P6: [logit|Q] = ctx @ [Wout;Wco]^T + [0|bcrit]
        mma_out64(dynsm, smb, (bid >> 3) * 64, bid & 7, g_ctxh, g_ctxl, 4,
                  g_Wskw + (size_t)(bid & 7) * (4 * 16384), bcrit, 3,
                  g_logit, g_Q, nullptr, nullptr);
        bt += NBLK; gsync(bt);
        // P7: finalize
        finalize8(bid, t, actions, out);
        bf16* tp;
        tp = h0ch; h0ch = h0nh; h0nh = tp;
        tp = h0cl; h0cl = h0nl; h0nl = tp;
        tp = h1ch; h1ch = h1nh; h1nh = tp;
        tp = h1cl; h1cl = h1nl; h1nl = tp;
    }
}

__global__ void reset_k() { g_count = 0; }

// ---------------- host ----------------
extern "C" void kernel_launch(void* const* d_in, const int* in_sizes, int n_in,
                              void* d_out, int out_size) {
    const float* enc_out = (const float*)d_in[0];
    const float* enc_h   = (const float*)d_in[1];
    const float* enc_c   = (const float*)d_in[2];
    const float* emb     = (const float*)d_in[3];
    const float* Wih0    = (const float*)d_in[4];
    const float* Whh0    = (const float*)d_in[5];
    const float* bih0    = (const float*)d_in[6];
    const float* bhh0    = (const float*)d_in[7];
    const float* Wih1    = (const float*)d_in[8];
    const float* Whh1    = (const float*)d_in[9];
    const float* bih1    = (const float*)d_in[10];
    const float* bhh1    = (const float*)d_in[11];
    const float* Wa      = (const float*)d_in[12];
    const float* Wconcat = (const float*)d_in[13];
    const float* Wout    = (const float*)d_in[14];
    const float* Wcrit   = (const float*)d_in[15];
    const float* bcrit   = (const float*)d_in[16];
    const int*   actions = (const int*)d_in[17];
    float* out = (float*)d_out;

    cudaFuncSetAttribute(mega, cudaFuncAttributeMaxDynamicSharedMemorySize, SMEM_TOTAL);
    reset_k<<<1, 1>>>();
    mega<<<NBLK, NTHR, SMEM_TOTAL>>>(enc_out, enc_h, enc_c, emb,
                                     Wih0, Whh0, bih0, bhh0,
                                     Wih1, Whh1, bih1, bhh1,
                                     Wa, Wconcat, Wout, Wcrit, bcrit, actions, out);
}

// round 16
// speedup vs baseline: 3.1508x; 1.0986x over previous
#include <cuda_runtime.h>
#include <cuda_bf16.h>
#include <cstdint>

#define Bq 1024
#define Lq 100
#define NBLK 128
#define NTHR 512

typedef unsigned long long u64;
typedef __nv_bfloat16 bf16;

// ---------------- static scratch ----------------
__device__ __align__(16) unsigned char g_W0sw[16 * 12 * 16384];  // 3 MB
__device__ __align__(16) unsigned char g_W1sw[16 * 8 * 16384];   // 2 MB
__device__ __align__(16) unsigned char g_Waw[4 * 4 * 16384];
__device__ __align__(16) unsigned char g_Wccw[4 * 8 * 16384];
__device__ __align__(16) unsigned char g_Wskw[8 * 4 * 16384];
__device__ float g_Wco[256 * 256];
__device__ float g_b0p[1024], g_b1p[1024];
// bf16 hi/lo activation images
__device__ __align__(16) bf16 g_embh[256 * 256], g_embl[256 * 256];
__device__ __align__(16) bf16 g_ctxh[Bq * 256], g_ctxl[Bq * 256];
__device__ __align__(16) bf16 g_h0ah[Bq * 256], g_h0al[Bq * 256];
__device__ __align__(16) bf16 g_h0bh[Bq * 256], g_h0bl[Bq * 256];
__device__ __align__(16) bf16 g_h1ah[Bq * 256], g_h1al[Bq * 256];
__device__ __align__(16) bf16 g_h1bh[Bq * 256], g_h1bl[Bq * 256];
__device__ __align__(16) bf16 g_cah[Bq * 256], g_cal[Bq * 256];
__device__ float g_c0[Bq * 256], g_c1[Bq * 256];
__device__ float g_q[Bq * 256], g_pre[Bq * 256];
__device__ float g_logit[Bq * 256], g_Q[Bq * 256];
__device__ unsigned g_count;

// ---------------- smem layout ----------------
#define AHI_OFF(b) ((b) * 32768)
#define ALO_OFF(b) (AHI_OFF(b) + 16384)
#define WHI_OFF(b) (65536 + (b) * 16384)
#define WLO_OFF(b) (WHI_OFF(b) + 8192)
#define SMEM_TOTAL 106496

#define SWZ(x) ((x) ^ (((x) >> 3) & 0x70))

__device__ __forceinline__ float sigm(float x) { return 1.f / (1.f + __expf(-x)); }

// ---------------- primitives ----------------
__device__ __forceinline__ uint32_t smem_u32(const void* p) {
    uint32_t a;
    asm("{ .reg .u64 t; cvta.to.shared.u64 t, %1; cvt.u32.u64 %0, t; }"
        : "=r"(a) : "l"(p));
    return a;
}
// 256-bit evict-last load (enc_out: keep resident in L2); p must be 32B aligned
__device__ __forceinline__ void ldg_el8(const float* p, float4& a, float4& b) {
    uint32_t r0, r1, r2, r3, r4, r5, r6, r7;
    asm volatile("ld.global.nc.L2::evict_last.v8.b32 "
                 "{%0,%1,%2,%3,%4,%5,%6,%7}, [%8];"
                 : "=r"(r0), "=r"(r1), "=r"(r2), "=r"(r3),
                   "=r"(r4), "=r"(r5), "=r"(r6), "=r"(r7) : "l"(p));
    a.x = __uint_as_float(r0); a.y = __uint_as_float(r1);
    a.z = __uint_as_float(r2); a.w = __uint_as_float(r3);
    b.x = __uint_as_float(r4); b.y = __uint_as_float(r5);
    b.z = __uint_as_float(r6); b.w = __uint_as_float(r7);
}
#define LDSM4(r, a) asm volatile( \
    "ldmatrix.sync.aligned.m8n8.x4.shared.b16 {%0,%1,%2,%3}, [%4];" \
    : "=r"((r)[0]), "=r"((r)[1]), "=r"((r)[2]), "=r"((r)[3]) : "r"(a))
#define LDSM4T(r, a) asm volatile( \
    "ldmatrix.sync.aligned.m8n8.x4.trans.shared.b16 {%0,%1,%2,%3}, [%4];" \
    : "=r"((r)[0]), "=r"((r)[1]), "=r"((r)[2]), "=r"((r)[3]) : "r"(a))
__device__ __forceinline__ void mma16816(float* d, const uint32_t* a,
                                         uint32_t b0, uint32_t b1) {
    asm volatile("mma.sync.aligned.m16n8k16.row.col.f32.bf16.bf16.f32 "
                 "{%0,%1,%2,%3}, {%4,%5,%6,%7}, {%8,%9}, {%0,%1,%2,%3};"
                 : "+f"(d[0]), "+f"(d[1]), "+f"(d[2]), "+f"(d[3])
                 : "r"(a[0]), "r"(a[1]), "r"(a[2]), "r"(a[3]), "r"(b0), "r"(b1));
}
__device__ __forceinline__ uint32_t pkbf(float a, float b) {
    uint16_t ua = __bfloat16_as_ushort(__float2bfloat16(a));
    uint16_t ub = __bfloat16_as_ushort(__float2bfloat16(b));
    return (uint32_t)ua | ((uint32_t)ub << 16);
}
__device__ __forceinline__ void split2(float a, float b, uint32_t& h, uint32_t& l) {
    bf16 ha = __float2bfloat16(a), hb = __float2bfloat16(b);
    h = (uint32_t)__bfloat16_as_ushort(ha) | ((uint32_t)__bfloat16_as_ushort(hb) << 16);
    l = pkbf(a - __bfloat162float(ha), b - __bfloat162float(hb));
}
__device__ __forceinline__ void split1(float a, bf16* ph, bf16* pl) {
    bf16 h = __float2bfloat16(a);
    *ph = h;
    *pl = __float2bfloat16(a - __bfloat162float(h));
}

// ---------------- grid barrier ----------------
__device__ __forceinline__ void gsync(unsigned target) {
    __syncthreads();
    if (threadIdx.x == 0) {
        asm volatile("red.add.release.gpu.u32 [%0], 1;"
                     :: "l"(&g_count) : "memory");
        unsigned cur;
        do {
            asm volatile("ld.acquire.gpu.u32 %0, [%1];"
                         : "=r"(cur) : "l"(&g_count) : "memory");
        } while ((int)(cur - target) < 0);
    }
    __syncthreads();
}

// ---------------- tail pool ----------------
struct TailPool {
    struct { float acc[8][256]; float m1[8], e1[8]; } att;
};

// =============== LSTM via mma.sync bf16-split, image A-operands ==============
__device__ void lstm_mma(char* sm, uint32_t smb, const int* gidx, int bm, int ct,
                         const bf16* A0h, const bf16* A0l,
                         const bf16* A1h, const bf16* A1l,
                         const bf16* A2h, const bf16* A2l,
                         int nch, bool gather,
                         const unsigned char* __restrict__ Wsw,
                         const float* __restrict__ bias,
                         float* __restrict__ cst,
                         bf16* __restrict__ houth, bf16* __restrict__ houtl) {
    const int tid = threadIdx.x;
    const int warp = tid >> 5, lane = tid & 31;
    const int mw = warp & 3, nw = warp >> 2;
    const int row = tid >> 2, q = tid & 3;

    float d[2][2][4];
#pragma unroll
    for (int mt = 0; mt < 2; mt++)
#pragma unroll
        for (int nt = 0; nt < 2; nt++)
#pragma unroll
            for (int e = 0; e < 4; e++) d[mt][nt][e] = 0.f;

    const int lrowA = mw * 32 + (lane & 15);
    const int lkselA = (lane >> 4);
    const int lrowB = (lane & 15);
    const int ljB = nw * 2 + (lane >> 4);

    uint4 vh0, vh1, vl0, vl1, w0, w1;
    {
        int ri = gather ? gidx[row] : (bm + row);
        const uint4* ph = (const uint4*)(A0h + (size_t)ri * 256 + q * 16);
        const uint4* pl = (const uint4*)(A0l + (size_t)ri * 256 + q * 16);
        vh0 = ph[0]; vh1 = ph[1]; vl0 = pl[0]; vl1 = pl[1];
        w0 = __ldcs((const uint4*)(Wsw + tid * 16));
        w1 = __ldcs((const uint4*)(Wsw + 8192 + tid * 16));
    }

    for (int c = 0; c < nch; c++) {
        const int buf = c & 1;
        {
            uint32_t b0 = row * 128 + q * 32;
            uint32_t s0 = SWZ(b0), s1 = SWZ(b0 + 16);
            *(uint4*)(sm + AHI_OFF(buf) + s0) = vh0;
            *(uint4*)(sm + AHI_OFF(buf) + s1) = vh1;
            *(uint4*)(sm + ALO_OFF(buf) + s0) = vl0;
            *(uint4*)(sm + ALO_OFF(buf) + s1) = vl1;
            *(uint4*)(sm + WHI_OFF(buf) + tid * 16) = w0;
            *(uint4*)(sm + WLO_OFF(buf) + tid * 16) = w1;
        }
        __syncthreads();
        if (c + 1 < nch) {
            int cn = c + 1;
            int seg = cn >> 2;
            int kc = ((cn & 3) * 64) + q * 16;
            const bf16* Ah = (seg == 0) ? A0h : (seg == 1 ? A1h : A2h);
            const bf16* Al = (seg == 0) ? A0l : (seg == 1 ? A1l : A2l);
            int ri = (gather && seg == 0) ? gidx[row] : (bm + row);
            const uint4* ph = (const uint4*)(Ah + (size_t)ri * 256 + kc);
            const uint4* pl = (const uint4*)(Al + (size_t)ri * 256 + kc);
            vh0 = ph[0]; vh1 = ph[1]; vl0 = pl[0]; vl1 = pl[1];
            w0 = __ldcs((const uint4*)(Wsw + (size_t)cn * 16384 + tid * 16));
            w1 = __ldcs((const uint4*)(Wsw + (size_t)cn * 16384 + 8192 + tid * 16));
        }
        const uint32_t ah_base = smb + AHI_OFF(buf);
        const uint32_t al_base = smb + ALO_OFF(buf);
        const uint32_t wh_base = smb + WHI_OFF(buf);
        const uint32_t wl_base = smb + WLO_OFF(buf);
#pragma unroll
        for (int ks = 0; ks < 4; ks++) {
            uint32_t ah[2][4], al[2][4], bh[4], bl[4];
#pragma unroll
            for (int mt = 0; mt < 2; mt++) {
                uint32_t off = SWZ((uint32_t)((lrowA + mt * 16) * 128
                                              + (ks * 2 + lkselA) * 16));
                LDSM4(ah[mt], ah_base + off);
                LDSM4(al[mt], al_base + off);
            }
            {
                uint32_t off = SWZ((uint32_t)((ks * 16 + lrowB) * 128 + ljB * 16));
                LDSM4T(bh, wh_base + off);
                LDSM4T(bl, wl_base + off);
            }
#pragma unroll
            for (int mt = 0; mt < 2; mt++)
#pragma unroll
                for (int nt = 0; nt < 2; nt++) {
                    mma16816(d[mt][nt], ah[mt], bh[2 * nt], bh[2 * nt + 1]);
                    mma16816(d[mt][nt], ah[mt], bl[2 * nt], bl[2 * nt + 1]);
                    mma16816(d[mt][nt], al[mt], bh[2 * nt], bh[2 * nt + 1]);
                }
        }
    }
    {
        float* Dsm = (float*)sm;
#pragma unroll
        for (int mt = 0; mt < 2; mt++) {
            int r = mw * 32 + mt * 16 + (lane >> 2);
#pragma unroll
            for (int nt = 0; nt < 2; nt++) {
                int cc = nw * 16 + nt * 8 + 2 * (lane & 3);
                *(float2*)(Dsm + r * 64 + cc) = make_float2(d[mt][nt][0], d[mt][nt][1]);
                *(float2*)(Dsm + (r + 8) * 64 + cc) = make_float2(d[mt][nt][2], d[mt][nt][3]);
            }
        }
    }
    __syncthreads();
    {
        const float* Dsm = (const float*)sm;
#pragma unroll
        for (int i = 0; i < 4; i++) {
            int e = tid + i * 512;
            int r = e >> 4, hl = e & 15;
            float4 g4 = *(const float4*)(Dsm + r * 64 + hl * 4);
            int nb = ct * 64 + hl * 4;
            float gi = g4.x + bias[nb + 0];
            float gf = g4.y + bias[nb + 1];
            float gg = g4.z + bias[nb + 2];
            float go = g4.w + bias[nb + 3];
            float I = sigm(gi), F = sigm(gf);
            float G = tanhf(gg), Og = sigm(go);
            int idx = (bm + r) * 256 + ct * 16 + hl;
            float cn = F * cst[idx] + I * G;
            cst[idx] = cn;
            split1(Og * tanhf(cn), houth + idx, houtl + idx);
        }
    }
    __syncthreads();
}

// =============== mma GEMM tile M=64 x N=64, image A-operands =================
__device__ void mma_out64(char* sm, uint32_t smb, int bm, int ct,
                          const bf16* Ah, const bf16* Al, int nch,
                          const unsigned char* __restrict__ Wsw,
                          const float* __restrict__ bias, int mode,
                          float* __restrict__ C0, float* __restrict__ C1,
                          bf16* __restrict__ Ch, bf16* __restrict__ Cl) {
    const int tid = threadIdx.x;
    const int warp = tid >> 5, lane = tid & 31;
    const int mw = warp & 3, nw = warp >> 2;
    const int row = tid >> 3, qq = tid & 7;

    float d[2][4];
#pragma unroll
    for (int nt = 0; nt < 2; nt++)
#pragma unroll
        for (int e = 0; e < 4; e++) d[nt][e] = 0.f;

    const int lrowA = mw * 16 + (lane & 15);
    const int lkselA = (lane >> 4);
    const int lrowB = (lane & 15);
    const int ljB = nw * 2 + (lane >> 4);

    uint4 vh, vl, w0, w1;
    {
        const uint4* ph = (const uint4*)(Ah + (size_t)(bm + row) * 256 + qq * 8);
        const uint4* pl = (const uint4*)(Al + (size_t)(bm + row) * 256 + qq * 8);
        vh = ph[0]; vl = pl[0];
        w0 = __ldcs((const uint4*)(Wsw + tid * 16));
        w1 = __ldcs((const uint4*)(Wsw + 8192 + tid * 16));
    }

    for (int c = 0; c < nch; c++) {
        const int buf = c & 1;
        {
            uint32_t s0 = SWZ((uint32_t)(row * 128 + qq * 16));
            *(uint4*)(sm + AHI_OFF(buf) + s0) = vh;
            *(uint4*)(sm + ALO_OFF(buf) + s0) = vl;
            *(uint4*)(sm + WHI_OFF(buf) + tid * 16) = w0;
            *(uint4*)(sm + WLO_OFF(buf) + tid * 16) = w1;
        }
        __syncthreads();
        if (c + 1 < nch) {
            int cn = c + 1;
            int kc = cn * 64 + qq * 8;
            const uint4* ph = (const uint4*)(Ah + (size_t)(bm + row) * 256 + kc);
            const uint4* pl = (const uint4*)(Al + (size_t)(bm + row) * 256 + kc);
            vh = ph[0]; vl = pl[0];
            w0 = __ldcs((const uint4*)(Wsw + (size_t)cn * 16384 + tid * 16));
            w1 = __ldcs((const uint4*)(Wsw + (size_t)cn * 16384 + 8192 + tid * 16));
        }
        const uint32_t ah_base = smb + AHI_OFF(buf);
        const uint32_t al_base = smb + ALO_OFF(buf);
        const uint32_t wh_base = smb + WHI_OFF(buf);
        const uint32_t wl_base = smb + WLO_OFF(buf);
#pragma unroll
        for (int ks = 0; ks < 4; ks++) {
            uint32_t ah[4], al[4], bh[4], bl[4];
            {
                uint32_t off = SWZ((uint32_t)(lrowA * 128 + (ks * 2 + lkselA) * 16));
                LDSM4(ah, ah_base + off);
                LDSM4(al, al_base + off);
            }
            {
                uint32_t off = SWZ((uint32_t)((ks * 16 + lrowB) * 128 + ljB * 16));
                LDSM4T(bh, wh_base + off);
                LDSM4T(bl, wl_base + off);
            }
#pragma unroll
            for (int nt = 0; nt < 2; nt++) {
                mma16816(d[nt], ah, bh[2 * nt], bh[2 * nt + 1]);
                mma16816(d[nt], ah, bl[2 * nt], bl[2 * nt + 1]);
                mma16816(d[nt], al, bh[2 * nt], bh[2 * nt + 1]);
            }
        }
    }
#pragma unroll
    for (int nt = 0; nt < 2; nt++) {
        int r = bm + mw * 16 + (lane >> 2);
        int cc = nw * 16 + nt * 8 + 2 * (lane & 3);
        int colg = ct * 64 + cc;
        float2 v0 = make_float2(d[nt][0], d[nt][1]);
        float2 v1 = make_float2(d[nt][2], d[nt][3]);
        if (mode == 4) {
            float2 p0 = *(const float2*)(C1 + (size_t)r * 256 + colg);
            float2 p1 = *(const float2*)(C1 + (size_t)(r + 8) * 256 + colg);
            float t0 = tanhf(v0.x + p0.x), t1 = tanhf(v0.y + p0.y);
            float t2 = tanhf(v1.x + p1.x), t3 = tanhf(v1.y + p1.y);
            uint32_t h, l;
            split2(t0, t1, h, l);
            *(uint32_t*)(Ch + (size_t)r * 256 + colg) = h;
            *(uint32_t*)(Cl + (size_t)r * 256 + colg) = l;
            split2(t2, t3, h, l);
            *(uint32_t*)(Ch + (size_t)(r + 8) * 256 + colg) = h;
            *(uint32_t*)(Cl + (size_t)(r + 8) * 256 + colg) = l;
        } else if (mode == 3 && colg >= 256) {
            float b0 = bias[colg - 256], b1 = bias[colg - 255];
            v0.x += b0; v0.y += b1; v1.x += b0; v1.y += b1;
            *(float2*)(C1 + (size_t)r * 256 + colg - 256) = v0;
            *(float2*)(C1 + (size_t)(r + 8) * 256 + colg - 256) = v1;
        } else {
            *(float2*)(C0 + (size_t)r * 256 + colg) = v0;
            *(float2*)(C0 + (size_t)(r + 8) * 256 + colg) = v1;
        }
    }
    __syncthreads();
}

// =============== attention: online softmax, 32B-lane layout, evict_last ======
__device__ void attention8(TailPool* sp, int bid, const float* __restrict__ eo) {
    const int tid = threadIdx.x, w = tid >> 5, lane = tid & 31;
    const int r8 = w >> 1, half = w & 1, b = bid * 8 + r8;
    const float* qb = g_q + b * 256;
    // lane owns columns lane*8 .. lane*8+7
    float4 q0 = *(const float4*)(qb + lane * 8);
    float4 q1 = *(const float4*)(qb + lane * 8 + 4);
    const float* eb = eo + (size_t)b * Lq * 256;
    float m = -1e30f, esum = 0.f;
    float4 a0 = make_float4(0, 0, 0, 0), a1 = make_float4(0, 0, 0, 0);
    const int l0 = half * 50;
    float4 c00, c01, c10, c11;
    ldg_el8(eb + (size_t)l0 * 256 + lane * 8, c00, c01);
    ldg_el8(eb + (size_t)(l0 + 1) * 256 + lane * 8, c10, c11);
#pragma unroll 5
    for (int l = l0; l < l0 + 50; l += 2) {
        float4 n00, n01, n10, n11;
        if (l + 2 < l0 + 50) {
            ldg_el8(eb + (size_t)(l + 2) * 256 + lane * 8, n00, n01);
            ldg_el8(eb + (size_t)(l + 3) * 256 + lane * 8, n10, n11);
        }
#pragma unroll
        for (int jj = 0; jj < 2; jj++) {
            float4 v0 = jj ? c10 : c00;
            float4 v1 = jj ? c11 : c01;
            float s = v0.x * q0.x + v0.y * q0.y + v0.z * q0.z + v0.w * q0.w
                    + v1.x * q1.x + v1.y * q1.y + v1.z * q1.z + v1.w * q1.w;
#pragma unroll
            for (int o = 16; o; o >>= 1) s += __shfl_xor_sync(0xFFFFFFFFu, s, o);
            if (s <= m) {
                float wg = __expf(s - m);
                esum += wg;
                a0.x += wg * v0.x; a0.y += wg * v0.y; a0.z += wg * v0.z; a0.w += wg * v0.w;
                a1.x += wg * v1.x; a1.y += wg * v1.y; a1.z += wg * v1.z; a1.w += wg * v1.w;
            } else {
                float r = __expf(m - s);
                esum = esum * r + 1.f;
                a0.x = a0.x * r + v0.x; a0.y = a0.y * r + v0.y;
                a0.z = a0.z * r + v0.z; a0.w = a0.w * r + v0.w;
                a1.x = a1.x * r + v1.x; a1.y = a1.y * r + v1.y;
                a1.z = a1.z * r + v1.z; a1.w = a1.w * r + v1.w;
                m = s;
            }
        }
        c00 = n00; c01 = n01; c10 = n10; c11 = n11;
    }
    if (half) {
        sp->att.m1[r8] = m; sp->att.e1[r8] = esum;
        *(float4*)&sp->att.acc[r8][lane * 8] = a0;
        *(float4*)&sp->att.acc[r8][lane * 8 + 4] = a1;
    }
    __syncthreads();
    if (!half) {
        float m1 = sp->att.m1[r8], e1 = sp->att.e1[r8];
        float M = fmaxf(m, m1);
        float s0 = __expf(m - M), s1 = __expf(m1 - M);
        float inv = 1.f / (esum * s0 + e1 * s1);
        float4 p0 = *(const float4*)&sp->att.acc[r8][lane * 8];
        float4 p1 = *(const float4*)&sp->att.acc[r8][lane * 8 + 4];
        float o[8];
        o[0] = (a0.x * s0 + p0.x * s1) * inv; o[1] = (a0.y * s0 + p0.y * s1) * inv;
        o[2] = (a0.z * s0 + p0.z * s1) * inv; o[3] = (a0.w * s0 + p0.w * s1) * inv;
        o[4] = (a1.x * s0 + p1.x * s1) * inv; o[5] = (a1.y * s0 + p1.y * s1) * inv;
        o[6] = (a1.z * s0 + p1.z * s1) * inv; o[7] = (a1.w * s0 + p1.w * s1) * inv;
        uint32_t h0, l0p, h1, l1, h2, l2, h3, l3;
        split2(o[0], o[1], h0, l0p); split2(o[2], o[3], h1, l1);
        split2(o[4], o[5], h2, l2);  split2(o[6], o[7], h3, l3);
        *(uint4*)(g_cah + b * 256 + lane * 8) = make_uint4(h0, h1, h2, h3);
        *(uint4*)(g_cal + b * 256 + lane * 8) = make_uint4(l0p, l1, l2, l3);
    }
    __syncthreads();
}

// =============== finalize: warp-per-row ======================================
__device__ void finalize8(int bid, int t, const int* __restrict__ actions,
                          float* __restrict__ out) {
    const int w = threadIdx.x >> 5, lane = threadIdx.x & 31;
    if (w >= 8) return;
    const int b = bid * 8 + w;
    const float* lr = g_logit + b * 256;
    float4 l0 = *(const float4*)(lr + lane * 4);
    float4 l1 = *(const float4*)(lr + 128 + lane * 4);
    float m = fmaxf(fmaxf(fmaxf(l0.x, l0.y), fmaxf(l0.z, l0.w)),
                    fmaxf(fmaxf(l1.x, l1.y), fmaxf(l1.z, l1.w)));
#pragma unroll
    for (int o = 16; o; o >>= 1) m = fmaxf(m, __shfl_xor_sync(0xFFFFFFFFu, m, o));
    float4 e0 = make_float4(__expf(l0.x - m), __expf(l0.y - m), __expf(l0.z - m), __expf(l0.w - m));
    float4 e1 = make_float4(__expf(l1.x - m), __expf(l1.y - m), __expf(l1.z - m), __expf(l1.w - m));
    float s = e0.x + e0.y + e0.z + e0.w + e1.x + e1.y + e1.z + e1.w;
#pragma unroll
    for (int o = 16; o; o >>= 1) s += __shfl_xor_sync(0xFFFFFFFFu, s, o);
    float inv = 1.f / s;
    e0.x *= inv; e0.y *= inv; e0.z *= inv; e0.w *= inv;
    e1.x *= inv; e1.y *= inv; e1.z *= inv; e1.w *= inv;
    float* outl = out + (size_t)Bq * Lq + ((size_t)b * Lq + t) * 256;
    *(float4*)(outl + lane * 4) = e0;
    *(float4*)(outl + 128 + lane * 4) = e1;
    const float* Qr = g_Q + b * 256;
    float4 Q0 = *(const float4*)(Qr + lane * 4);
    float4 Q1 = *(const float4*)(Qr + 128 + lane * 4);
    float v = e0.x * Q0.x + e0.y * Q0.y + e0.z * Q0.z + e0.w * Q0.w
            + e1.x * Q1.x + e1.y * Q1.y + e1.z * Q1.z + e1.w * Q1.w;
#pragma unroll
    for (int o = 16; o; o >>= 1) v += __shfl_xor_sync(0xFFFFFFFFu, v, o);
    if (!lane) {
        out[(size_t)Bq * Lq + (size_t)Bq * Lq * 256 + b * Lq + t] = v;
        out[b * Lq + t] = (float)actions[b * Lq + t];
    }
}

// =============== persistent mega-kernel ======================================
__global__ void __launch_bounds__(NTHR, 1)
mega(const float* __restrict__ enc_out, const float* __restrict__ enc_h,
     const float* __restrict__ enc_c, const float* __restrict__ emb,
     const float* __restrict__ Wih0, const float* __restrict__ Whh0,
     const float* __restrict__ bih0, const float* __restrict__ bhh0,
     const float* __restrict__ Wih1, const float* __restrict__ Whh1,
     const float* __restrict__ bih1, const float* __restrict__ bhh1,
     const float* __restrict__ Wa, const float* __restrict__ Wconcat,
     const float* __restrict__ Wout, const float* __restrict__ Wcrit,
     const float* __restrict__ bcrit, const int* __restrict__ actions,
     float* __restrict__ out) {
    extern __shared__ char dynsm[];
    TailPool* sp = (TailPool*)dynsm;
    __shared__ int gidx[128];
    const int bid = blockIdx.x, tid = threadIdx.x;
    const uint32_t smb = smem_u32(dynsm);
    unsigned bt = 0;

    // ---- init: weight images + activation images ----
    for (int idx = bid * NTHR + tid; idx < 16 * 12 * 4096; idx += NBLK * NTHR) {
        int ct = idx / 49152, rem = idx - ct * 49152;
        int ch = rem >> 12, rr = rem & 4095;
        int k = rr >> 6, n = rr & 63;
        int np = ct * 64 + n, h = np >> 2, g = np & 3, orow = g * 256 + h;
        int kk = ch * 64 + k;
        float w = (kk < 512) ? Wih0[orow * 512 + kk] : Whh0[orow * 256 + (kk - 512)];
        bf16 hi = __float2bfloat16(w);
        bf16 lo = __float2bfloat16(w - __bfloat162float(hi));
        unsigned char* base = g_W0sw + (size_t)(ct * 12 + ch) * 16384;
        uint32_t off = SWZ((uint32_t)(k * 128 + n * 2));
        *(bf16*)(base + off) = hi;
        *(bf16*)(base + 8192 + off) = lo;
    }
    for (int idx = bid * NTHR + tid; idx < 16 * 8 * 4096; idx += NBLK * NTHR) {
        int ct = idx / 32768, rem = idx - ct * 32768;
        int ch = rem >> 12, rr = rem & 4095;
        int k = rr >> 6, n = rr & 63;
        int np = ct * 64 + n, h = np >> 2, g = np & 3, orow = g * 256 + h;
        int kk = ch * 64 + k;
        float w = (kk < 256) ? Wih1[orow * 256 + kk] : Whh1[orow * 256 + (kk - 256)];
        bf16 hi = __float2bfloat16(w);
        bf16 lo = __float2bfloat16(w - __bfloat162float(hi));
        unsigned char* base = g_W1sw + (size_t)(ct * 8 + ch) * 16384;
        uint32_t off = SWZ((uint32_t)(k * 128 + n * 2));
        *(bf16*)(base + off) = hi;
        *(bf16*)(base + 8192 + off) = lo;
    }
    for (int idx = bid * NTHR + tid; idx < 4 * 4 * 4096; idx += NBLK * NTHR) {
        int ct = idx / 16384, rem = idx - ct * 16384;
        int ch = rem >> 12, rr = rem & 4095;
        int k = rr >> 6, n = rr & 63;
        int np = ct * 64 + n, kk = ch * 64 + k;
        float w = Wa[kk * 256 + np];
        bf16 hi = __float2bfloat16(w);
        bf16 lo = __float2bfloat16(w - __bfloat162float(hi));
        unsigned char* base = g_Waw + (size_t)(ct * 4 + ch) * 16384;
        uint32_t off = SWZ((uint32_t)(k * 128 + n * 2));
        *(bf16*)(base + off) = hi;
        *(bf16*)(base + 8192 + off) = lo;
    }
    for (int idx = bid * NTHR + tid; idx < 4 * 8 * 4096; idx += NBLK * NTHR) {
        int ct = idx / 32768, rem = idx - ct * 32768;
        int ch = rem >> 12, rr = rem & 4095;
        int k = rr >> 6, n = rr & 63;
        int np = ct * 64 + n, kk = ch * 64 + k;
        float w = Wconcat[np * 512 + kk];
        bf16 hi = __float2bfloat16(w);
        bf16 lo = __float2bfloat16(w - __bfloat162float(hi));
        unsigned char* base = g_Wccw + (size_t)(ct * 8 + ch) * 16384;
        uint32_t off = SWZ((uint32_t)(k * 128 + n * 2));
        *(bf16*)(base + off) = hi;
        *(bf16*)(base + 8192 + off) = lo;
    }
    {
        int g = bid * NTHR + tid;
        int i = g >> 8, j = g & 255;
        float acc = 0.f;
        const float* wc = Wcrit + i * 256;
#pragma unroll 4
        for (int k = 0; k < 256; k++) acc += wc[k] * Wout[k * 256 + j];
        g_Wco[i * 256 + j] = acc;
    }
    for (int idx = bid * NTHR + tid; idx < 1024; idx += NBLK * NTHR) {
        int h = idx >> 2, g = idx & 3, orow = g * 256 + h;
        g_b0p[idx] = bih0[orow] + bhh0[orow];
        g_b1p[idx] = bih1[orow] + bhh1[orow];
    }
    for (int idx = bid * NTHR + tid; idx < 65536; idx += NBLK * NTHR)
        split1(emb[idx], g_embh + idx, g_embl + idx);
    for (int idx = bid * NTHR + tid; idx < Bq * 256; idx += NBLK * NTHR) {
        split1(enc_h[idx], g_h0ah + idx, g_h0al + idx);
        split1(enc_h[Bq * 256 + idx], g_h1ah + idx, g_h1al + idx);
        g_c0[idx] = enc_c[idx];
        g_c1[idx] = enc_c[Bq * 256 + idx];
        int b = idx >> 8, hh = idx & 255;
        const float* p = enc_out + (size_t)b * Lq * 256 + hh;
        float s = 0.f;
        for (int l = 0; l < Lq; l++) s += p[(size_t)l * 256];
        split1(s * (1.0f / Lq), g_ctxh + idx, g_ctxl + idx);
    }
    bt += NBLK; gsync(bt);
    for (int idx = bid * NTHR + tid; idx < 8 * 4 * 4096; idx += NBLK * NTHR) {
        int ct = idx / 16384, rem = idx - ct * 16384;
        int ch = rem >> 12, rr = rem & 4095;
        int k = rr >> 6, n = rr & 63;
        int np = ct * 64 + n, kk = ch * 64 + k;
        float w = (np < 256) ? Wout[np * 256 + kk] : g_Wco[(np - 256) * 256 + kk];
        bf16 hi = __float2bfloat16(w);
        bf16 lo = __float2bfloat16(w - __bfloat162float(hi));
        unsigned char* base = g_Wskw + (size_t)(ct * 4 + ch) * 16384;
        uint32_t off = SWZ((uint32_t)(k * 128 + n * 2));
        *(bf16*)(base + off) = hi;
        *(bf16*)(base + 8192 + off) = lo;
    }
    bt += NBLK; gsync(bt);

    bf16 *h0ch = g_h0ah, *h0cl = g_h0al, *h0nh = g_h0bh, *h0nl = g_h0bl;
    bf16 *h1ch = g_h1ah, *h1cl = g_h1al, *h1nh = g_h1bh, *h1nl = g_h1bl;
    const int bmL = (bid >> 4) * 128, ctL = bid & 15;

    for (int t = 0; t < Lq; t++) {
        // P1: LSTM0 [emb(gather) | ctx | h0]
        if (tid < 128)
            gidx[tid] = (t == 0) ? 0 : actions[(bmL + tid) * Lq + (t - 1)];
        __syncthreads();
        lstm_mma(dynsm, smb, gidx, bmL, ctL,
                 g_embh, g_embl, g_ctxh, g_ctxl, h0ch, h0cl, 12, true,
                 g_W0sw + (size_t)ctL * (12 * 16384), g_b0p, g_c0, h0nh, h0nl);
        bt += NBLK; gsync(bt);
        // P2: LSTM1 [h0n | h1c]
        lstm_mma(dynsm, smb, gidx, bmL, ctL,
                 h0nh, h0nl, h1ch, h1cl, nullptr, nullptr, 8, false,
                 g_W1sw + (size_t)ctL * (8 * 16384), g_b1p, g_c1, h1nh, h1nl);
        bt += NBLK; gsync(bt);
        // P3: 0-63 q = h1@Wa; 64-127 pre = h1@Wcc1
        if (bid < 64) {
            mma_out64(dynsm, smb, (bid >> 2) * 64, bid & 3, h1nh, h1nl, 4,
                      g_Waw + (size_t)(bid & 3) * (4 * 16384), nullptr, 0,
                      g_q, nullptr, nullptr, nullptr);
        } else {
            int b2 = bid - 64;
            mma_out64(dynsm, smb, (b2 >> 2) * 64, b2 & 3, h1nh, h1nl, 4,
                      g_Wccw + (size_t)(b2 & 3) * (8 * 16384), nullptr, 0,
                      g_pre, nullptr, nullptr, nullptr);
        }
        bt += NBLK; gsync(bt);
        // P4: attention -> ctx_att images
        attention8(sp, bid, enc_out);
        bt += NBLK; gsync(bt);
        // P5: ctx = tanh(pre + ctx_att@Wcc2) -> ctx images
        if (bid < 64)
            mma_out64(dynsm, smb, (bid >> 2) * 64, bid & 3, g_cah, g_cal, 4,
                      g_Wccw + (size_t)(bid & 3) * (8 * 16384) + 4 * 16384,
                      nullptr, 4, nullptr, g_pre, g_ctxh, g_ctxl);
        bt += NBLK; gsync(bt);
        // P6: [logit|Q] = ctx @ [Wout;Wco]^T + [0|bcrit]
        mma_out64(dynsm, smb, (bid >> 3) * 64, bid & 7, g_ctxh, g_ctxl, 4,
                  g_Wskw + (size_t)(bid & 7) * (4 * 16384), bcrit, 3,
                  g_logit, g_Q, nullptr, nullptr);
        bt += NBLK; gsync(bt);
        // P7: finalize
        finalize8(bid, t, actions, out);
        bf16* tp;
        tp = h0ch; h0ch = h0nh; h0nh = tp;
        tp = h0cl; h0cl = h0nl; h0nl = tp;
        tp = h1ch; h1ch = h1nh; h1nh = tp;
        tp = h1cl; h1cl = h1nl; h1nl = tp;
    }
}

__global__ void reset_k() { g_count = 0; }

// ---------------- host ----------------
extern "C" void kernel_launch(void* const* d_in, const int* in_sizes, int n_in,
                              void* d_out, int out_size) {
    const float* enc_out = (const float*)d_in[0];
    const float* enc_h   = (const float*)d_in[1];
    const float* enc_c   = (const float*)d_in[2];
    const float* emb     = (const float*)d_in[3];
    const float* Wih0    = (const float*)d_in[4];
    const float* Whh0    = (const float*)d_in[5];
    const float* bih0    = (const float*)d_in[6];
    const float* bhh0    = (const float*)d_in[7];
    const float* Wih1    = (const float*)d_in[8];
    const float* Whh1    = (const float*)d_in[9];
    const float* bih1    = (const float*)d_in[10];
    const float* bhh1    = (const float*)d_in[11];
    const float* Wa      = (const float*)d_in[12];
    const float* Wconcat = (const float*)d_in[13];
    const float* Wout    = (const float*)d_in[14];
    const float* Wcrit   = (const float*)d_in[15];
    const float* bcrit   = (const float*)d_in[16];
    const int*   actions = (const int*)d_in[17];
    float* out = (float*)d_out;

    cudaFuncSetAttribute(mega, cudaFuncAttributeMaxDynamicSharedMemorySize, SMEM_TOTAL);
    reset_k<<<1, 1>>>();
    mega<<<NBLK, NTHR, SMEM_TOTAL>>>(enc_out, enc_h, enc_c, emb,
                                     Wih0, Whh0, bih0, bhh0,
                                     Wih1, Whh1, bih1, bhh1,
                                     Wa, Wconcat, Wout, Wcrit, bcrit, actions, out);
}